// round 10
// baseline (speedup 1.0000x reference)
#include <cuda_runtime.h>
#include <cuda_fp16.h>
#include <cstdint>
#include <math.h>

#define NTOK   4096
#define DMODEL 1024
#define DHID   256
#define NHEADS 4
#define HDIM   256

// ---------------- scratch (__device__ globals; no allocation allowed) -------
__device__ float  g_h  [NTOK * DHID];
__device__ int    g_mask[NTOK];
__device__ float  g_qp [NTOK * DMODEL];
__device__ float  g_kp [NTOK * DMODEL];
__device__ float  g_vp [NTOK * DMODEL];
__device__ float  g_ctx[NTOK * DMODEL];
__device__ float  g_w1t[DHID * DMODEL];
__device__ float  g_wqt[DMODEL * DMODEL];
__device__ float  g_wkt[DMODEL * DMODEL];
__device__ float  g_wvt[DMODEL * DMODEL];
__device__ float  g_wot[DMODEL * DMODEL];
__device__ float  g_vpt[DMODEL * NTOK];
__device__ float  g_S  [(size_t)NHEADS * NTOK * NTOK];    // 268MB
__device__ __half g_P  [(size_t)NHEADS * NTOK * NTOK];    // 134MB

// ---------------- fp16 helpers ----------------------------------------------
__device__ __forceinline__ void split2h(float x0, float x1,
                                        uint32_t& h, uint32_t& l) {
    __half2 hv = __floats2half2_rn(x0, x1);
    float f0 = __low2float(hv), f1 = __high2float(hv);
    __half2 lv = __floats2half2_rn(x0 - f0, x1 - f1);
    h = *(uint32_t*)&hv;
    l = *(uint32_t*)&lv;
}
__device__ __forceinline__ uint32_t pack2h(float x0, float x1) {
    __half2 hv = __floats2half2_rn(x0, x1);
    return *(uint32_t*)&hv;
}
__device__ __forceinline__ void mma16816(float* c, const uint32_t* a,
                                         const uint32_t* b) {
    asm volatile(
        "mma.sync.aligned.m16n8k16.row.col.f32.f16.f16.f32 "
        "{%0,%1,%2,%3}, {%4,%5,%6,%7}, {%8,%9}, {%0,%1,%2,%3};"
        : "+f"(c[0]), "+f"(c[1]), "+f"(c[2]), "+f"(c[3])
        : "r"(a[0]), "r"(a[1]), "r"(a[2]), "r"(a[3]), "r"(b[0]), "r"(b[1]));
}
__device__ __forceinline__ uint32_t smem_u32(const void* p) {
    uint32_t a;
    asm("{ .reg .u64 t; cvta.to.shared.u64 t, %1; cvt.u32.u64 %0, t; }"
        : "=r"(a) : "l"(p));
    return a;
}
__device__ __forceinline__ void ldsm4(uint32_t& r0, uint32_t& r1,
                                      uint32_t& r2, uint32_t& r3,
                                      uint32_t addr) {
    asm volatile("ldmatrix.sync.aligned.m8n8.x4.shared.b16 {%0,%1,%2,%3}, [%4];"
                 : "=r"(r0), "=r"(r1), "=r"(r2), "=r"(r3) : "r"(addr));
}

// ---------------- unified tensor-core GEMM ----------------------------------
// D[M,N] = A[M,K] @ B[N,K]^T (+ epilogue). CTA 128x128, K-chunk 32,
// 256 threads, 8 warps (4x2), warp tile 32x64.
// AHALF=0: A fp32 -> fp16 hi+lo split, B fp32 -> fp16 hi; 2 MMAs/frag.
// AHALF=1: A already fp16 in gmem, B fp32 -> fp16 hi; 1 MMA/frag.
enum { EPI_RAW = 0, EPI_BIAS, EPI_RELU, EPI_QSCALE, EPI_KEYMASK, EPI_ROWMASK };

#define SROW   20                      // u32 per smem row (16 data + 4 pad)
#define STG_U  (128 * SROW)
#define STG_B  (3 * STG_U * 4)         // Ah|Al|Bh (AHALF=0)
#define STG_B2 (2 * STG_U * 4)         // Ah|Bh    (AHALF=1)
#define SMEM_BYTES (2 * STG_B)         // 61440 (max of both)

template <int AHALF>
__device__ __forceinline__ void ldg_sts_chunk(
    const void* __restrict__ Arow, int lda,
    const float* __restrict__ Brow, int ldb,
    int k0, uint32_t* st, int tid)
{
    uint32_t* Ah = st;
    uint32_t* Al = st + STG_U;                       // unused when AHALF
    uint32_t* Bh = st + (AHALF ? 1 : 2) * STG_U;
#pragma unroll
    for (int i = 0; i < 4; i++) {
        int idx = tid + i * 256;
        int r = idx >> 3, c4 = idx & 7;
        int o = r * SROW + c4 * 2;
        if (AHALF) {
            uint2 a = *(const uint2*)((const __half*)Arow +
                                      (long)r * lda + k0 + c4 * 4);
            Ah[o] = a.x; Ah[o + 1] = a.y;
        } else {
            float4 a = *(const float4*)((const float*)Arow +
                                        (long)r * lda + k0 + c4 * 4);
            uint32_t h01, l01, h23, l23;
            split2h(a.x, a.y, h01, l01);
            split2h(a.z, a.w, h23, l23);
            Ah[o] = h01; Ah[o + 1] = h23;
            Al[o] = l01; Al[o + 1] = l23;
        }
        float4 b = *(const float4*)(Brow + (long)r * ldb + k0 + c4 * 4);
        Bh[o] = pack2h(b.x, b.y);
        Bh[o + 1] = pack2h(b.z, b.w);
    }
}

template <int EPI, int AHALF>
__global__ __launch_bounds__(256, 1) void gemm_bf(
    const void* __restrict__ A, int lda, long aZ,
    const float* __restrict__ B, int ldb, long bZ,
    float* __restrict__ C, int ldc, long cZ,
    int K, const float* __restrict__ bias,
    const int* __restrict__ mask, float scale)
{
    extern __shared__ __align__(16) char smem[];
    const int tid = threadIdx.x;
    const int wid = tid >> 5, lane = tid & 31;
    const int wm = wid & 3, wn = wid >> 2;      // 4x2 warp grid
    const int qr = lane >> 2, qc = lane & 3;
    const int bm = blockIdx.y * 128, bn = blockIdx.x * 128;
    const int stgb = AHALF ? STG_B2 : STG_B;

    const void* Arow = AHALF
        ? (const void*)((const __half*)A + blockIdx.z * aZ + (long)bm * lda)
        : (const void*)((const float*)A + blockIdx.z * aZ + (long)bm * lda);
    const float* Brow = B + blockIdx.z * bZ + (long)bn * ldb;
    C += blockIdx.z * cZ;

    // ldmatrix per-lane offsets (u32 units within one plane sub-array)
    const int a_off = (wm * 32 + ((lane >> 3) & 1) * 8 + (lane & 7)) * SROW +
                      (lane >> 4) * 4;            // + mf*16*SROW
    const int b_off = (wn * 64 + (lane >> 4) * 8 + (lane & 7)) * SROW +
                      ((lane >> 3) & 1) * 4;      // + p*16*SROW

    float acc[2][8][4];
#pragma unroll
    for (int mf = 0; mf < 2; mf++)
#pragma unroll
        for (int nf = 0; nf < 8; nf++)
#pragma unroll
            for (int j = 0; j < 4; j++) acc[mf][nf][j] = 0.f;

    const int nc = K / 32;
    ldg_sts_chunk<AHALF>(Arow, lda, Brow, ldb, 0, (uint32_t*)smem, tid);
    __syncthreads();

    for (int c = 0; c < nc; c++) {
        const uint32_t sb = smem_u32(smem + (c & 1) * stgb);
#pragma unroll
        for (int kk = 0; kk < 2; kk++) {
            uint32_t ah[2][4], al[2][4], bh[8][2];
#pragma unroll
            for (int mf = 0; mf < 2; mf++) {
                uint32_t ao = sb + (uint32_t)(a_off + mf * 16 * SROW + kk * 8) * 4;
                ldsm4(ah[mf][0], ah[mf][1], ah[mf][2], ah[mf][3], ao);
                if (!AHALF)
                    ldsm4(al[mf][0], al[mf][1], al[mf][2], al[mf][3],
                          ao + STG_U * 4);
            }
#pragma unroll
            for (int p = 0; p < 4; p++) {
                uint32_t bo = sb + (AHALF ? 1 : 2) * STG_U * 4 +
                              (uint32_t)(b_off + p * 16 * SROW + kk * 8) * 4;
                ldsm4(bh[2 * p][0], bh[2 * p][1],
                      bh[2 * p + 1][0], bh[2 * p + 1][1], bo);
            }
#pragma unroll
            for (int mf = 0; mf < 2; mf++)
#pragma unroll
                for (int nf = 0; nf < 8; nf++) {
                    mma16816(acc[mf][nf], ah[mf], bh[nf]);
                    if (!AHALF) mma16816(acc[mf][nf], al[mf], bh[nf]);
                }
        }
        if (c + 1 < nc)
            ldg_sts_chunk<AHALF>(Arow, lda, Brow, ldb, (c + 1) * 32,
                                 (uint32_t*)(smem + ((c + 1) & 1) * stgb), tid);
        __syncthreads();
    }

#pragma unroll
    for (int mf = 0; mf < 2; mf++) {
        const int r0 = bm + wm * 32 + mf * 16 + qr;
        const int r1 = r0 + 8;
        int keep0 = 1, keep1 = 1;
        if (EPI == EPI_ROWMASK) { keep0 = mask[r0]; keep1 = mask[r1]; }
#pragma unroll
        for (int nf = 0; nf < 8; nf++) {
            const int cc = bn + wn * 64 + nf * 8 + qc * 2;
            float v0 = acc[mf][nf][0], v1 = acc[mf][nf][1];
            float v2 = acc[mf][nf][2], v3 = acc[mf][nf][3];
            if (EPI == EPI_BIAS || EPI == EPI_RELU || EPI == EPI_QSCALE ||
                EPI == EPI_ROWMASK) {
                float b0 = bias[cc], b1 = bias[cc + 1];
                v0 += b0; v1 += b1; v2 += b0; v3 += b1;
            }
            if (EPI == EPI_RELU) {
                v0 = fmaxf(v0, 0.f); v1 = fmaxf(v1, 0.f);
                v2 = fmaxf(v2, 0.f); v3 = fmaxf(v3, 0.f);
            }
            if (EPI == EPI_QSCALE) {
                v0 *= scale; v1 *= scale; v2 *= scale; v3 *= scale;
            }
            if (EPI == EPI_KEYMASK) {
                if (!mask[cc])     { v0 = -1e9f; v2 = -1e9f; }
                if (!mask[cc + 1]) { v1 = -1e9f; v3 = -1e9f; }
            }
            if (EPI == EPI_ROWMASK) {
                if (!keep0) { v0 = 0.f; v1 = 0.f; }
                if (!keep1) { v2 = 0.f; v3 = 0.f; }
            }
            float2 o0 = {v0, v1}, o1 = {v2, v3};
            *(float2*)&C[(long)r0 * ldc + cc] = o0;
            *(float2*)&C[(long)r1 * ldc + cc] = o1;
        }
    }
}

// ---------------- transpose: out[C][R] = in[R][C]^T --------------------------
__global__ void transpose_k(const float* __restrict__ in, float* __restrict__ out,
                            int R, int C)
{
    __shared__ float t[32][33];
    const int bx = blockIdx.x * 32, by = blockIdx.y * 32;
#pragma unroll
    for (int j = 0; j < 32; j += 8)
        t[threadIdx.y + j][threadIdx.x] =
            in[(long)(by + threadIdx.y + j) * C + bx + threadIdx.x];
    __syncthreads();
#pragma unroll
    for (int j = 0; j < 32; j += 8)
        out[(long)(bx + threadIdx.y + j) * R + by + threadIdx.x] =
            t[threadIdx.x][threadIdx.y + j];
}

// ---------------- mask: sigmoid(h @ w2 + b2) > 0.15 --------------------------
__global__ void score_k(const float* __restrict__ h, const float* __restrict__ w2,
                        const float* __restrict__ b2, int* __restrict__ mask)
{
    const int warp = (blockIdx.x * blockDim.x + threadIdx.x) >> 5;
    const int lane = threadIdx.x & 31;
    if (warp >= NTOK) return;
    const float* hr = h + warp * DHID;
    float s = 0.f;
#pragma unroll
    for (int i = 0; i < DHID / 32; i++)
        s += hr[lane + i * 32] * w2[lane + i * 32];
#pragma unroll
    for (int o = 16; o; o >>= 1) s += __shfl_xor_sync(0xffffffffu, s, o);
    if (lane == 0) {
        float sig = 1.0f / (1.0f + expf(-(s + b2[0])));
        mask[warp] = (sig > 0.15f) ? 1 : 0;
    }
}

// ---------------- row softmax: S fp32 -> P fp16 ------------------------------
__global__ __launch_bounds__(256) void softmax_k(const float* __restrict__ S,
                                                 __half* __restrict__ P)
{
    __shared__ float cache[NTOK];
    __shared__ float red[256];
    const size_t row = (size_t)blockIdx.y * NTOK + blockIdx.x;
    const float* Sr = S + row * NTOK;
    const int tid = threadIdx.x;

    float m = -3.4e38f;
#pragma unroll
    for (int i = 0; i < 4; i++) {
        float4 v = *(const float4*)&Sr[(tid + i * 256) * 4];
        m = fmaxf(m, fmaxf(fmaxf(v.x, v.y), fmaxf(v.z, v.w)));
    }
    red[tid] = m;
    __syncthreads();
    for (int s = 128; s; s >>= 1) {
        if (tid < s) red[tid] = fmaxf(red[tid], red[tid + s]);
        __syncthreads();
    }
    m = red[0];
    __syncthreads();

    float sum = 0.f;
#pragma unroll
    for (int i = 0; i < 4; i++) {
        int f4 = tid + i * 256;
        float4 v = *(const float4*)&Sr[f4 * 4];
        float4 p;
        p.x = __expf(v.x - m); p.y = __expf(v.y - m);
        p.z = __expf(v.z - m); p.w = __expf(v.w - m);
        *(float4*)&cache[f4 * 4] = p;
        sum += p.x + p.y + p.z + p.w;
    }
    red[tid] = sum;
    __syncthreads();
    for (int s = 128; s; s >>= 1) {
        if (tid < s) red[tid] += red[tid + s];
        __syncthreads();
    }
    const float inv = 1.0f / red[0];
    uint2* Pr = (uint2*)(P + row * NTOK);
#pragma unroll
    for (int i = 0; i < 4; i++) {
        int f4 = tid + i * 256;
        float4 p = *(const float4*)&cache[f4 * 4];
        uint2 o;
        o.x = pack2h(p.x * inv, p.y * inv);
        o.y = pack2h(p.z * inv, p.w * inv);
        Pr[f4] = o;
    }
}

// ---------------------------------------------------------------------------
extern "C" void kernel_launch(void* const* d_in, const int* in_sizes, int n_in,
                              void* d_out, int out_size)
{
    const float* q  = (const float*)d_in[0];
    const float* k  = (const float*)d_in[1];
    const float* v  = (const float*)d_in[2];
    const float* w1 = (const float*)d_in[3];
    const float* b1 = (const float*)d_in[4];
    const float* w2 = (const float*)d_in[5];
    const float* b2 = (const float*)d_in[6];
    const float* wq = (const float*)d_in[7];
    const float* bq = (const float*)d_in[8];
    const float* wk = (const float*)d_in[9];
    const float* bk = (const float*)d_in[10];
    const float* wv = (const float*)d_in[11];
    const float* bv = (const float*)d_in[12];
    const float* wo = (const float*)d_in[13];
    const float* bo = (const float*)d_in[14];
    float* out = (float*)d_out;

    float *hh, *qp, *kp, *vp, *ctx, *w1t, *wqt, *wkt, *wvt, *wot, *vpt, *S;
    __half* P;
    int* msk;
    cudaGetSymbolAddress((void**)&hh,  g_h);
    cudaGetSymbolAddress((void**)&msk, g_mask);
    cudaGetSymbolAddress((void**)&qp,  g_qp);
    cudaGetSymbolAddress((void**)&kp,  g_kp);
    cudaGetSymbolAddress((void**)&vp,  g_vp);
    cudaGetSymbolAddress((void**)&ctx, g_ctx);
    cudaGetSymbolAddress((void**)&w1t, g_w1t);
    cudaGetSymbolAddress((void**)&wqt, g_wqt);
    cudaGetSymbolAddress((void**)&wkt, g_wkt);
    cudaGetSymbolAddress((void**)&wvt, g_wvt);
    cudaGetSymbolAddress((void**)&wot, g_wot);
    cudaGetSymbolAddress((void**)&vpt, g_vpt);
    cudaGetSymbolAddress((void**)&S,   g_S);
    cudaGetSymbolAddress((void**)&P,   g_P);

    cudaFuncSetAttribute(gemm_bf<EPI_RAW, 1>,
        cudaFuncAttributeMaxDynamicSharedMemorySize, SMEM_BYTES);
    cudaFuncSetAttribute(gemm_bf<EPI_BIAS, 0>,
        cudaFuncAttributeMaxDynamicSharedMemorySize, SMEM_BYTES);
    cudaFuncSetAttribute(gemm_bf<EPI_RELU, 0>,
        cudaFuncAttributeMaxDynamicSharedMemorySize, SMEM_BYTES);
    cudaFuncSetAttribute(gemm_bf<EPI_QSCALE, 0>,
        cudaFuncAttributeMaxDynamicSharedMemorySize, SMEM_BYTES);
    cudaFuncSetAttribute(gemm_bf<EPI_KEYMASK, 0>,
        cudaFuncAttributeMaxDynamicSharedMemorySize, SMEM_BYTES);
    cudaFuncSetAttribute(gemm_bf<EPI_ROWMASK, 0>,
        cudaFuncAttributeMaxDynamicSharedMemorySize, SMEM_BYTES);

    dim3 tb(32, 8);
    transpose_k<<<dim3(DHID / 32, DMODEL / 32), tb>>>(w1, w1t, DMODEL, DHID);
    transpose_k<<<dim3(32, 32), tb>>>(wq, wqt, DMODEL, DMODEL);
    transpose_k<<<dim3(32, 32), tb>>>(wk, wkt, DMODEL, DMODEL);
    transpose_k<<<dim3(32, 32), tb>>>(wv, wvt, DMODEL, DMODEL);
    transpose_k<<<dim3(32, 32), tb>>>(wo, wot, DMODEL, DMODEL);

    // 1) predictor hidden: h = relu(q @ w1 + b1)
    gemm_bf<EPI_RELU, 0><<<dim3(DHID / 128, NTOK / 128), 256, SMEM_BYTES>>>(
        q, DMODEL, 0, w1t, DMODEL, 0, hh, DHID, 0, DMODEL, b1, nullptr, 0.f);
    // 2) token mask
    score_k<<<NTOK / 8, 256>>>(hh, w2, b2, msk);
    // 3) projections (softmax scale folded into qp)
    gemm_bf<EPI_QSCALE, 0><<<dim3(8, 32), 256, SMEM_BYTES>>>(
        q, DMODEL, 0, wqt, DMODEL, 0, qp, DMODEL, 0, DMODEL, bq, nullptr,
        0.0625f);
    gemm_bf<EPI_BIAS, 0><<<dim3(8, 32), 256, SMEM_BYTES>>>(
        k, DMODEL, 0, wkt, DMODEL, 0, kp, DMODEL, 0, DMODEL, bk, nullptr, 0.f);
    gemm_bf<EPI_BIAS, 0><<<dim3(8, 32), 256, SMEM_BYTES>>>(
        v, DMODEL, 0, wvt, DMODEL, 0, vp, DMODEL, 0, DMODEL, bv, nullptr, 0.f);
    // 4) transpose V projection -> [1024][4096]
    transpose_k<<<dim3(DMODEL / 32, NTOK / 32), tb>>>(vp, vpt, NTOK, DMODEL);
    // 5) S[h] = qp @ kp^T, masked keys -> -1e9
    gemm_bf<EPI_KEYMASK, 0><<<dim3(32, 32, NHEADS), 256, SMEM_BYTES>>>(
        qp, DMODEL, HDIM, kp, DMODEL, HDIM, S, NTOK, (long)NTOK * NTOK,
        HDIM, nullptr, msk, 0.f);
    // 6) softmax rows -> fp16 P
    softmax_k<<<dim3(NTOK, NHEADS), 256>>>(S, P);
    // 7) ctx[h] = P @ V  (plain fp16 A, hi-only B)
    gemm_bf<EPI_RAW, 1><<<dim3(HDIM / 128, 32, NHEADS), 256, SMEM_BYTES>>>(
        P, NTOK, (long)NTOK * NTOK, vpt, NTOK, (long)HDIM * NTOK,
        ctx, DMODEL, HDIM, NTOK, nullptr, nullptr, 0.f);
    // 8) out = rowmask(ctx @ wo + bo)
    gemm_bf<EPI_ROWMASK, 0><<<dim3(8, 32), 256, SMEM_BYTES>>>(
        ctx, DMODEL, 0, wot, DMODEL, 0, out, DMODEL, 0, DMODEL, bo, msk, 0.f);
}

// round 11
// speedup vs baseline: 1.2210x; 1.2210x over previous
#include <cuda_runtime.h>
#include <cuda_fp16.h>
#include <cstdint>
#include <math.h>

#define NTOK   4096
#define DMODEL 1024
#define DHID   256
#define NHEADS 4
#define HDIM   256

// ---------------- scratch (__device__ globals; no allocation allowed) -------
__device__ float  g_h  [NTOK * DHID];
__device__ int    g_mask[NTOK];
__device__ float  g_qp [NTOK * DMODEL];
__device__ float  g_kp [NTOK * DMODEL];
__device__ float  g_vp [NTOK * DMODEL];
__device__ float  g_ctx[NTOK * DMODEL];
__device__ float  g_w1t[DHID * DMODEL];
__device__ float  g_wqt[DMODEL * DMODEL];
__device__ float  g_wkt[DMODEL * DMODEL];
__device__ float  g_wvt[DMODEL * DMODEL];
__device__ float  g_wot[DMODEL * DMODEL];
__device__ float  g_vpt[DMODEL * NTOK];
__device__ float  g_S  [(size_t)NHEADS * NTOK * NTOK];    // 268MB
__device__ __half g_P  [(size_t)NHEADS * NTOK * NTOK];    // 134MB

// ---------------- fp16 helpers ----------------------------------------------
__device__ __forceinline__ void split2h(float x0, float x1,
                                        uint32_t& h, uint32_t& l) {
    __half2 hv = __floats2half2_rn(x0, x1);
    float f0 = __low2float(hv), f1 = __high2float(hv);
    __half2 lv = __floats2half2_rn(x0 - f0, x1 - f1);
    h = *(uint32_t*)&hv;
    l = *(uint32_t*)&lv;
}
__device__ __forceinline__ uint32_t pack2h(float x0, float x1) {
    __half2 hv = __floats2half2_rn(x0, x1);
    return *(uint32_t*)&hv;
}
__device__ __forceinline__ void mma16816(float* c, const uint32_t* a,
                                         const uint32_t* b) {
    asm volatile(
        "mma.sync.aligned.m16n8k16.row.col.f32.f16.f16.f32 "
        "{%0,%1,%2,%3}, {%4,%5,%6,%7}, {%8,%9}, {%0,%1,%2,%3};"
        : "+f"(c[0]), "+f"(c[1]), "+f"(c[2]), "+f"(c[3])
        : "r"(a[0]), "r"(a[1]), "r"(a[2]), "r"(a[3]), "r"(b[0]), "r"(b[1]));
}
__device__ __forceinline__ uint32_t smem_u32(const void* p) {
    uint32_t a;
    asm("{ .reg .u64 t; cvta.to.shared.u64 t, %1; cvt.u32.u64 %0, t; }"
        : "=r"(a) : "l"(p));
    return a;
}
__device__ __forceinline__ void ldsm4(uint32_t& r0, uint32_t& r1,
                                      uint32_t& r2, uint32_t& r3,
                                      uint32_t addr) {
    asm volatile("ldmatrix.sync.aligned.m8n8.x4.shared.b16 {%0,%1,%2,%3}, [%4];"
                 : "=r"(r0), "=r"(r1), "=r"(r2), "=r"(r3) : "r"(addr));
}

// ---------------- unified tensor-core GEMM ----------------------------------
// D[M,N] = A[M,K] @ B[N,K]^T (+ epilogue). CTA 128x128, K-chunk 32,
// 256 threads, 8 warps (4x2), warp tile 32x64.
// AHALF=0: A fp32 -> fp16 hi+lo split (2 MMAs/frag); AHALF=1: A fp16 (1 MMA).
// B always fp32 -> fp16 hi.  Loop: early LDG -> MMA -> sync -> STS -> sync.
enum { EPI_RAW = 0, EPI_BIAS, EPI_RELU, EPI_QSCALE, EPI_KEYMASK, EPI_ROWMASK };

#define SROW   20                      // u32 per smem row (16 data + 4 pad)
#define STG_U  (128 * SROW)
#define STG_B  (3 * STG_U * 4)         // Ah|Al|Bh (AHALF=0)
#define STG_B2 (2 * STG_U * 4)         // Ah|Bh    (AHALF=1)
#define SMEM_BYTES (2 * STG_B)         // 61440 (max)

template <int AHALF>
__device__ __forceinline__ void ldg_chunk(const void* __restrict__ Arow,
                                          int lda,
                                          const float* __restrict__ Brow,
                                          int ldb, int k0, int tid,
                                          float4* av, uint2* av2, float4* bv) {
#pragma unroll
    for (int i = 0; i < 4; i++) {
        int idx = tid + i * 256;
        int r = idx >> 3, c4 = idx & 7;
        if (AHALF)
            av2[i] = *(const uint2*)((const __half*)Arow +
                                     (long)r * lda + k0 + c4 * 4);
        else
            av[i] = *(const float4*)((const float*)Arow +
                                     (long)r * lda + k0 + c4 * 4);
        bv[i] = *(const float4*)(Brow + (long)r * ldb + k0 + c4 * 4);
    }
}
template <int AHALF>
__device__ __forceinline__ void sts_chunk(uint32_t* st, int tid,
                                          const float4* av, const uint2* av2,
                                          const float4* bv) {
    uint32_t* Ah = st;
    uint32_t* Al = st + STG_U;
    uint32_t* Bh = st + (AHALF ? 1 : 2) * STG_U;
#pragma unroll
    for (int i = 0; i < 4; i++) {
        int idx = tid + i * 256;
        int r = idx >> 3, c4 = idx & 7;
        int o = r * SROW + c4 * 2;
        if (AHALF) {
            Ah[o] = av2[i].x; Ah[o + 1] = av2[i].y;
        } else {
            uint32_t h01, l01, h23, l23;
            split2h(av[i].x, av[i].y, h01, l01);
            split2h(av[i].z, av[i].w, h23, l23);
            Ah[o] = h01; Ah[o + 1] = h23;
            Al[o] = l01; Al[o + 1] = l23;
        }
        Bh[o] = pack2h(bv[i].x, bv[i].y);
        Bh[o + 1] = pack2h(bv[i].z, bv[i].w);
    }
}

template <int EPI, int AHALF>
__global__ __launch_bounds__(256, 1) void gemm_bf(
    const void* __restrict__ A, int lda, long aZ,
    const float* __restrict__ B, int ldb, long bZ,
    float* __restrict__ C, int ldc, long cZ,
    int K, const float* __restrict__ bias,
    const int* __restrict__ mask, float scale)
{
    extern __shared__ __align__(16) char smem[];
    const int tid = threadIdx.x;
    const int wid = tid >> 5, lane = tid & 31;
    const int wm = wid & 3, wn = wid >> 2;      // 4x2 warp grid
    const int qr = lane >> 2, qc = lane & 3;
    const int bm = blockIdx.y * 128, bn = blockIdx.x * 128;
    const int stgb = AHALF ? STG_B2 : STG_B;

    const void* Arow = AHALF
        ? (const void*)((const __half*)A + blockIdx.z * aZ + (long)bm * lda)
        : (const void*)((const float*)A + blockIdx.z * aZ + (long)bm * lda);
    const float* Brow = B + blockIdx.z * bZ + (long)bn * ldb;
    C += blockIdx.z * cZ;

    const int a_off = (wm * 32 + ((lane >> 3) & 1) * 8 + (lane & 7)) * SROW +
                      (lane >> 4) * 4;
    const int b_off = (wn * 64 + (lane >> 4) * 8 + (lane & 7)) * SROW +
                      ((lane >> 3) & 1) * 4;

    float acc[2][8][4];
#pragma unroll
    for (int mf = 0; mf < 2; mf++)
#pragma unroll
        for (int nf = 0; nf < 8; nf++)
#pragma unroll
            for (int j = 0; j < 4; j++) acc[mf][nf][j] = 0.f;

    const int nc = K / 32;
    float4 av[4], bv[4];
    uint2 av2[4];
    ldg_chunk<AHALF>(Arow, lda, Brow, ldb, 0, tid, av, av2, bv);
    sts_chunk<AHALF>((uint32_t*)smem, tid, av, av2, bv);
    __syncthreads();

    for (int c = 0; c < nc; c++) {
        if (c + 1 < nc)
            ldg_chunk<AHALF>(Arow, lda, Brow, ldb, (c + 1) * 32, tid,
                             av, av2, bv);
        const uint32_t sb = smem_u32(smem + (c & 1) * stgb);
#pragma unroll
        for (int kk = 0; kk < 2; kk++) {
            uint32_t ah[2][4], al[2][4], bh[8][2];
#pragma unroll
            for (int mf = 0; mf < 2; mf++) {
                uint32_t ao = sb + (uint32_t)(a_off + mf * 16 * SROW + kk * 8) * 4;
                ldsm4(ah[mf][0], ah[mf][1], ah[mf][2], ah[mf][3], ao);
                if (!AHALF)
                    ldsm4(al[mf][0], al[mf][1], al[mf][2], al[mf][3],
                          ao + STG_U * 4);
            }
#pragma unroll
            for (int p = 0; p < 4; p++) {
                uint32_t bo = sb + (AHALF ? 1 : 2) * STG_U * 4 +
                              (uint32_t)(b_off + p * 16 * SROW + kk * 8) * 4;
                ldsm4(bh[2 * p][0], bh[2 * p][1],
                      bh[2 * p + 1][0], bh[2 * p + 1][1], bo);
            }
#pragma unroll
            for (int mf = 0; mf < 2; mf++)
#pragma unroll
                for (int nf = 0; nf < 8; nf++) {
                    mma16816(acc[mf][nf], ah[mf], bh[nf]);
                    if (!AHALF) mma16816(acc[mf][nf], al[mf], bh[nf]);
                }
        }
        __syncthreads();
        if (c + 1 < nc) {
            sts_chunk<AHALF>((uint32_t*)(smem + ((c + 1) & 1) * stgb), tid,
                             av, av2, bv);
            __syncthreads();
        }
    }

#pragma unroll
    for (int mf = 0; mf < 2; mf++) {
        const int r0 = bm + wm * 32 + mf * 16 + qr;
        const int r1 = r0 + 8;
        int keep0 = 1, keep1 = 1;
        if (EPI == EPI_ROWMASK) { keep0 = mask[r0]; keep1 = mask[r1]; }
#pragma unroll
        for (int nf = 0; nf < 8; nf++) {
            const int cc = bn + wn * 64 + nf * 8 + qc * 2;
            float v0 = acc[mf][nf][0], v1 = acc[mf][nf][1];
            float v2 = acc[mf][nf][2], v3 = acc[mf][nf][3];
            if (EPI == EPI_BIAS || EPI == EPI_RELU || EPI == EPI_QSCALE ||
                EPI == EPI_ROWMASK) {
                float b0 = bias[cc], b1 = bias[cc + 1];
                v0 += b0; v1 += b1; v2 += b0; v3 += b1;
            }
            if (EPI == EPI_RELU) {
                v0 = fmaxf(v0, 0.f); v1 = fmaxf(v1, 0.f);
                v2 = fmaxf(v2, 0.f); v3 = fmaxf(v3, 0.f);
            }
            if (EPI == EPI_QSCALE) {
                v0 *= scale; v1 *= scale; v2 *= scale; v3 *= scale;
            }
            if (EPI == EPI_KEYMASK) {
                if (!mask[cc])     { v0 = -1e9f; v2 = -1e9f; }
                if (!mask[cc + 1]) { v1 = -1e9f; v3 = -1e9f; }
            }
            if (EPI == EPI_ROWMASK) {
                if (!keep0) { v0 = 0.f; v1 = 0.f; }
                if (!keep1) { v2 = 0.f; v3 = 0.f; }
            }
            float2 o0 = {v0, v1}, o1 = {v2, v3};
            *(float2*)&C[(long)r0 * ldc + cc] = o0;
            *(float2*)&C[(long)r1 * ldc + cc] = o1;
        }
    }
}

// ---------------- transpose: out[C][R] = in[R][C]^T --------------------------
__global__ void transpose_k(const float* __restrict__ in, float* __restrict__ out,
                            int R, int C)
{
    __shared__ float t[32][33];
    const int bx = blockIdx.x * 32, by = blockIdx.y * 32;
#pragma unroll
    for (int j = 0; j < 32; j += 8)
        t[threadIdx.y + j][threadIdx.x] =
            in[(long)(by + threadIdx.y + j) * C + bx + threadIdx.x];
    __syncthreads();
#pragma unroll
    for (int j = 0; j < 32; j += 8)
        out[(long)(bx + threadIdx.y + j) * R + by + threadIdx.x] =
            t[threadIdx.x][threadIdx.y + j];
}

// ---------------- mask: sigmoid(h @ w2 + b2) > 0.15 --------------------------
__global__ void score_k(const float* __restrict__ h, const float* __restrict__ w2,
                        const float* __restrict__ b2, int* __restrict__ mask)
{
    const int warp = (blockIdx.x * blockDim.x + threadIdx.x) >> 5;
    const int lane = threadIdx.x & 31;
    if (warp >= NTOK) return;
    const float* hr = h + warp * DHID;
    float s = 0.f;
#pragma unroll
    for (int i = 0; i < DHID / 32; i++)
        s += hr[lane + i * 32] * w2[lane + i * 32];
#pragma unroll
    for (int o = 16; o; o >>= 1) s += __shfl_xor_sync(0xffffffffu, s, o);
    if (lane == 0) {
        float sig = 1.0f / (1.0f + expf(-(s + b2[0])));
        mask[warp] = (sig > 0.15f) ? 1 : 0;
    }
}

// ---------------- row softmax: S fp32 -> P fp16 ------------------------------
__global__ __launch_bounds__(256) void softmax_k(const float* __restrict__ S,
                                                 __half* __restrict__ P)
{
    __shared__ float cache[NTOK];
    __shared__ float red[256];
    const size_t row = (size_t)blockIdx.y * NTOK + blockIdx.x;
    const float* Sr = S + row * NTOK;
    const int tid = threadIdx.x;

    float m = -3.4e38f;
#pragma unroll
    for (int i = 0; i < 4; i++) {
        float4 v = *(const float4*)&Sr[(tid + i * 256) * 4];
        m = fmaxf(m, fmaxf(fmaxf(v.x, v.y), fmaxf(v.z, v.w)));
    }
    red[tid] = m;
    __syncthreads();
    for (int s = 128; s; s >>= 1) {
        if (tid < s) red[tid] = fmaxf(red[tid], red[tid + s]);
        __syncthreads();
    }
    m = red[0];
    __syncthreads();

    float sum = 0.f;
#pragma unroll
    for (int i = 0; i < 4; i++) {
        int f4 = tid + i * 256;
        float4 v = *(const float4*)&Sr[f4 * 4];
        float4 p;
        p.x = __expf(v.x - m); p.y = __expf(v.y - m);
        p.z = __expf(v.z - m); p.w = __expf(v.w - m);
        *(float4*)&cache[f4 * 4] = p;
        sum += p.x + p.y + p.z + p.w;
    }
    red[tid] = sum;
    __syncthreads();
    for (int s = 128; s; s >>= 1) {
        if (tid < s) red[tid] += red[tid + s];
        __syncthreads();
    }
    const float inv = 1.0f / red[0];
    uint2* Pr = (uint2*)(P + row * NTOK);
#pragma unroll
    for (int i = 0; i < 4; i++) {
        int f4 = tid + i * 256;
        float4 p = *(const float4*)&cache[f4 * 4];
        uint2 o;
        o.x = pack2h(p.x * inv, p.y * inv);
        o.y = pack2h(p.z * inv, p.w * inv);
        Pr[f4] = o;
    }
}

// ---------------------------------------------------------------------------
extern "C" void kernel_launch(void* const* d_in, const int* in_sizes, int n_in,
                              void* d_out, int out_size)
{
    const float* q  = (const float*)d_in[0];
    const float* k  = (const float*)d_in[1];
    const float* v  = (const float*)d_in[2];
    const float* w1 = (const float*)d_in[3];
    const float* b1 = (const float*)d_in[4];
    const float* w2 = (const float*)d_in[5];
    const float* b2 = (const float*)d_in[6];
    const float* wq = (const float*)d_in[7];
    const float* bq = (const float*)d_in[8];
    const float* wk = (const float*)d_in[9];
    const float* bk = (const float*)d_in[10];
    const float* wv = (const float*)d_in[11];
    const float* bv = (const float*)d_in[12];
    const float* wo = (const float*)d_in[13];
    const float* bo = (const float*)d_in[14];
    float* out = (float*)d_out;

    float *hh, *qp, *kp, *vp, *ctx, *w1t, *wqt, *wkt, *wvt, *wot, *vpt, *S;
    __half* P;
    int* msk;
    cudaGetSymbolAddress((void**)&hh,  g_h);
    cudaGetSymbolAddress((void**)&msk, g_mask);
    cudaGetSymbolAddress((void**)&qp,  g_qp);
    cudaGetSymbolAddress((void**)&kp,  g_kp);
    cudaGetSymbolAddress((void**)&vp,  g_vp);
    cudaGetSymbolAddress((void**)&ctx, g_ctx);
    cudaGetSymbolAddress((void**)&w1t, g_w1t);
    cudaGetSymbolAddress((void**)&wqt, g_wqt);
    cudaGetSymbolAddress((void**)&wkt, g_wkt);
    cudaGetSymbolAddress((void**)&wvt, g_wvt);
    cudaGetSymbolAddress((void**)&wot, g_wot);
    cudaGetSymbolAddress((void**)&vpt, g_vpt);
    cudaGetSymbolAddress((void**)&S,   g_S);
    cudaGetSymbolAddress((void**)&P,   g_P);

    cudaFuncSetAttribute(gemm_bf<EPI_RAW, 1>,
        cudaFuncAttributeMaxDynamicSharedMemorySize, SMEM_BYTES);
    cudaFuncSetAttribute(gemm_bf<EPI_BIAS, 0>,
        cudaFuncAttributeMaxDynamicSharedMemorySize, SMEM_BYTES);
    cudaFuncSetAttribute(gemm_bf<EPI_RELU, 0>,
        cudaFuncAttributeMaxDynamicSharedMemorySize, SMEM_BYTES);
    cudaFuncSetAttribute(gemm_bf<EPI_QSCALE, 0>,
        cudaFuncAttributeMaxDynamicSharedMemorySize, SMEM_BYTES);
    cudaFuncSetAttribute(gemm_bf<EPI_KEYMASK, 0>,
        cudaFuncAttributeMaxDynamicSharedMemorySize, SMEM_BYTES);
    cudaFuncSetAttribute(gemm_bf<EPI_ROWMASK, 0>,
        cudaFuncAttributeMaxDynamicSharedMemorySize, SMEM_BYTES);

    dim3 tb(32, 8);
    transpose_k<<<dim3(DHID / 32, DMODEL / 32), tb>>>(w1, w1t, DMODEL, DHID);
    transpose_k<<<dim3(32, 32), tb>>>(wq, wqt, DMODEL, DMODEL);
    transpose_k<<<dim3(32, 32), tb>>>(wk, wkt, DMODEL, DMODEL);
    transpose_k<<<dim3(32, 32), tb>>>(wv, wvt, DMODEL, DMODEL);
    transpose_k<<<dim3(32, 32), tb>>>(wo, wot, DMODEL, DMODEL);

    // 1) predictor hidden: h = relu(q @ w1 + b1)
    gemm_bf<EPI_RELU, 0><<<dim3(DHID / 128, NTOK / 128), 256, SMEM_BYTES>>>(
        q, DMODEL, 0, w1t, DMODEL, 0, hh, DHID, 0, DMODEL, b1, nullptr, 0.f);
    // 2) token mask
    score_k<<<NTOK / 8, 256>>>(hh, w2, b2, msk);
    // 3) projections (softmax scale folded into qp)
    gemm_bf<EPI_QSCALE, 0><<<dim3(8, 32), 256, SMEM_BYTES>>>(
        q, DMODEL, 0, wqt, DMODEL, 0, qp, DMODEL, 0, DMODEL, bq, nullptr,
        0.0625f);
    gemm_bf<EPI_BIAS, 0><<<dim3(8, 32), 256, SMEM_BYTES>>>(
        k, DMODEL, 0, wkt, DMODEL, 0, kp, DMODEL, 0, DMODEL, bk, nullptr, 0.f);
    gemm_bf<EPI_BIAS, 0><<<dim3(8, 32), 256, SMEM_BYTES>>>(
        v, DMODEL, 0, wvt, DMODEL, 0, vp, DMODEL, 0, DMODEL, bv, nullptr, 0.f);
    // 4) transpose V projection -> [1024][4096]
    transpose_k<<<dim3(DMODEL / 32, NTOK / 32), tb>>>(vp, vpt, NTOK, DMODEL);
    // 5) S[h] = qp @ kp^T, masked keys -> -1e9
    gemm_bf<EPI_KEYMASK, 0><<<dim3(32, 32, NHEADS), 256, SMEM_BYTES>>>(
        qp, DMODEL, HDIM, kp, DMODEL, HDIM, S, NTOK, (long)NTOK * NTOK,
        HDIM, nullptr, msk, 0.f);
    // 6) softmax rows -> fp16 P
    softmax_k<<<dim3(NTOK, NHEADS), 256>>>(S, P);
    // 7) ctx[h] = P @ V  (plain fp16 A, hi-only B)
    gemm_bf<EPI_RAW, 1><<<dim3(HDIM / 128, 32, NHEADS), 256, SMEM_BYTES>>>(
        P, NTOK, (long)NTOK * NTOK, vpt, NTOK, (long)HDIM * NTOK,
        ctx, DMODEL, HDIM, NTOK, nullptr, nullptr, 0.f);
    // 8) out = rowmask(ctx @ wo + bo)
    gemm_bf<EPI_ROWMASK, 0><<<dim3(8, 32), 256, SMEM_BYTES>>>(
        ctx, DMODEL, 0, wot, DMODEL, 0, out, DMODEL, 0, DMODEL, bo, msk, 0.f);
}

// round 12
// speedup vs baseline: 1.2418x; 1.0170x over previous
#include <cuda_runtime.h>
#include <cuda_fp16.h>
#include <cstdint>
#include <math.h>

#define NTOK   4096
#define DMODEL 1024
#define DHID   256
#define NHEADS 4
#define HDIM   256

// ---------------- scratch (__device__ globals; no allocation allowed) -------
__device__ float  g_h  [NTOK * DHID];
__device__ int    g_mask[NTOK];
__device__ float  g_qp [NTOK * DMODEL];
__device__ float  g_kp [NTOK * DMODEL];
__device__ float  g_vp [NTOK * DMODEL];
__device__ float  g_ctx[NTOK * DMODEL];
__device__ float  g_w1t[DHID * DMODEL];
__device__ float  g_wqt[DMODEL * DMODEL];
__device__ float  g_wkt[DMODEL * DMODEL];
__device__ float  g_wvt[DMODEL * DMODEL];
__device__ float  g_wot[DMODEL * DMODEL];
__device__ float  g_vpt[DMODEL * NTOK];
__device__ float  g_S  [(size_t)NHEADS * NTOK * NTOK];    // 268MB
__device__ __half g_P  [(size_t)NHEADS * NTOK * NTOK];    // 134MB

// ---------------- fp16 helpers ----------------------------------------------
__device__ __forceinline__ void split2h(float x0, float x1,
                                        uint32_t& h, uint32_t& l) {
    __half2 hv = __floats2half2_rn(x0, x1);
    float f0 = __low2float(hv), f1 = __high2float(hv);
    __half2 lv = __floats2half2_rn(x0 - f0, x1 - f1);
    h = *(uint32_t*)&hv;
    l = *(uint32_t*)&lv;
}
__device__ __forceinline__ uint32_t pack2h(float x0, float x1) {
    __half2 hv = __floats2half2_rn(x0, x1);
    return *(uint32_t*)&hv;
}
__device__ __forceinline__ void mma16816(float* c, const uint32_t* a,
                                         const uint32_t* b) {
    asm volatile(
        "mma.sync.aligned.m16n8k16.row.col.f32.f16.f16.f32 "
        "{%0,%1,%2,%3}, {%4,%5,%6,%7}, {%8,%9}, {%0,%1,%2,%3};"
        : "+f"(c[0]), "+f"(c[1]), "+f"(c[2]), "+f"(c[3])
        : "r"(a[0]), "r"(a[1]), "r"(a[2]), "r"(a[3]), "r"(b[0]), "r"(b[1]));
}
__device__ __forceinline__ uint32_t smem_u32(const void* p) {
    uint32_t a;
    asm("{ .reg .u64 t; cvta.to.shared.u64 t, %1; cvt.u32.u64 %0, t; }"
        : "=r"(a) : "l"(p));
    return a;
}
__device__ __forceinline__ void ldsm4(uint32_t& r0, uint32_t& r1,
                                      uint32_t& r2, uint32_t& r3,
                                      uint32_t addr) {
    asm volatile("ldmatrix.sync.aligned.m8n8.x4.shared.b16 {%0,%1,%2,%3}, [%4];"
                 : "=r"(r0), "=r"(r1), "=r"(r2), "=r"(r3) : "r"(addr));
}

// ---------------- unified tensor-core GEMM ----------------------------------
// D[M,N] = A[M,K] @ B[N,K]^T (+ epilogue). CTA 128x128, K-chunk 32,
// 256 threads, 8 warps (4x2), warp tile 32x64. 2 CTAs/SM for phase overlap.
// AHALF=0: A fp32 -> fp16 hi+lo split (2 MMAs/frag); AHALF=1: A fp16 (1 MMA).
// B always fp32 -> fp16 hi.  Loop: early LDG -> MMA -> sync -> STS -> sync.
enum { EPI_RAW = 0, EPI_BIAS, EPI_RELU, EPI_QSCALE, EPI_KEYMASK, EPI_ROWMASK };

#define SROW   20                      // u32 per smem row (16 data + 4 pad)
#define STG_U  (128 * SROW)
#define STG_B  (3 * STG_U * 4)         // Ah|Al|Bh (AHALF=0)
#define STG_B2 (2 * STG_U * 4)         // Ah|Bh    (AHALF=1)
#define SMEM_BYTES (2 * STG_B)         // 61440 (max)

template <int AHALF>
__device__ __forceinline__ void ldg_chunk(const void* __restrict__ Arow,
                                          int lda,
                                          const float* __restrict__ Brow,
                                          int ldb, int k0, int tid,
                                          float4* av, uint2* av2, float4* bv) {
#pragma unroll
    for (int i = 0; i < 4; i++) {
        int idx = tid + i * 256;
        int r = idx >> 3, c4 = idx & 7;
        if (AHALF)
            av2[i] = *(const uint2*)((const __half*)Arow +
                                     (long)r * lda + k0 + c4 * 4);
        else
            av[i] = *(const float4*)((const float*)Arow +
                                     (long)r * lda + k0 + c4 * 4);
        bv[i] = *(const float4*)(Brow + (long)r * ldb + k0 + c4 * 4);
    }
}
template <int AHALF>
__device__ __forceinline__ void sts_chunk(uint32_t* st, int tid,
                                          const float4* av, const uint2* av2,
                                          const float4* bv) {
    uint32_t* Ah = st;
    uint32_t* Al = st + STG_U;
    uint32_t* Bh = st + (AHALF ? 1 : 2) * STG_U;
#pragma unroll
    for (int i = 0; i < 4; i++) {
        int idx = tid + i * 256;
        int r = idx >> 3, c4 = idx & 7;
        int o = r * SROW + c4 * 2;
        if (AHALF) {
            Ah[o] = av2[i].x; Ah[o + 1] = av2[i].y;
        } else {
            uint32_t h01, l01, h23, l23;
            split2h(av[i].x, av[i].y, h01, l01);
            split2h(av[i].z, av[i].w, h23, l23);
            Ah[o] = h01; Ah[o + 1] = h23;
            Al[o] = l01; Al[o + 1] = l23;
        }
        Bh[o] = pack2h(bv[i].x, bv[i].y);
        Bh[o + 1] = pack2h(bv[i].z, bv[i].w);
    }
}

template <int EPI, int AHALF>
__global__ __launch_bounds__(256, 2) void gemm_bf(
    const void* __restrict__ A, int lda, long aZ,
    const float* __restrict__ B, int ldb, long bZ,
    float* __restrict__ C, int ldc, long cZ,
    int K, const float* __restrict__ bias,
    const int* __restrict__ mask, float scale)
{
    extern __shared__ __align__(16) char smem[];
    const int tid = threadIdx.x;
    const int wid = tid >> 5, lane = tid & 31;
    const int wm = wid & 3, wn = wid >> 2;      // 4x2 warp grid
    const int qr = lane >> 2, qc = lane & 3;
    const int bm = blockIdx.y * 128, bn = blockIdx.x * 128;
    const int stgb = AHALF ? STG_B2 : STG_B;

    const void* Arow = AHALF
        ? (const void*)((const __half*)A + blockIdx.z * aZ + (long)bm * lda)
        : (const void*)((const float*)A + blockIdx.z * aZ + (long)bm * lda);
    const float* Brow = B + blockIdx.z * bZ + (long)bn * ldb;
    C += blockIdx.z * cZ;

    const int a_off = (wm * 32 + ((lane >> 3) & 1) * 8 + (lane & 7)) * SROW +
                      (lane >> 4) * 4;
    const int b_off = (wn * 64 + (lane >> 4) * 8 + (lane & 7)) * SROW +
                      ((lane >> 3) & 1) * 4;

    float acc[2][8][4];
#pragma unroll
    for (int mf = 0; mf < 2; mf++)
#pragma unroll
        for (int nf = 0; nf < 8; nf++)
#pragma unroll
            for (int j = 0; j < 4; j++) acc[mf][nf][j] = 0.f;

    const int nc = K / 32;
    float4 av[4], bv[4];
    uint2 av2[4];
    ldg_chunk<AHALF>(Arow, lda, Brow, ldb, 0, tid, av, av2, bv);
    sts_chunk<AHALF>((uint32_t*)smem, tid, av, av2, bv);
    __syncthreads();

    for (int c = 0; c < nc; c++) {
        if (c + 1 < nc)
            ldg_chunk<AHALF>(Arow, lda, Brow, ldb, (c + 1) * 32, tid,
                             av, av2, bv);
        const uint32_t sb = smem_u32(smem + (c & 1) * stgb);
#pragma unroll
        for (int kk = 0; kk < 2; kk++) {
            uint32_t ah[2][4], al[2][4], bh[8][2];
#pragma unroll
            for (int mf = 0; mf < 2; mf++) {
                uint32_t ao = sb + (uint32_t)(a_off + mf * 16 * SROW + kk * 8) * 4;
                ldsm4(ah[mf][0], ah[mf][1], ah[mf][2], ah[mf][3], ao);
                if (!AHALF)
                    ldsm4(al[mf][0], al[mf][1], al[mf][2], al[mf][3],
                          ao + STG_U * 4);
            }
#pragma unroll
            for (int p = 0; p < 4; p++) {
                uint32_t bo = sb + (AHALF ? 1 : 2) * STG_U * 4 +
                              (uint32_t)(b_off + p * 16 * SROW + kk * 8) * 4;
                ldsm4(bh[2 * p][0], bh[2 * p][1],
                      bh[2 * p + 1][0], bh[2 * p + 1][1], bo);
            }
#pragma unroll
            for (int mf = 0; mf < 2; mf++)
#pragma unroll
                for (int nf = 0; nf < 8; nf++) {
                    mma16816(acc[mf][nf], ah[mf], bh[nf]);
                    if (!AHALF) mma16816(acc[mf][nf], al[mf], bh[nf]);
                }
        }
        __syncthreads();
        if (c + 1 < nc) {
            sts_chunk<AHALF>((uint32_t*)(smem + ((c + 1) & 1) * stgb), tid,
                             av, av2, bv);
            __syncthreads();
        }
    }

#pragma unroll
    for (int mf = 0; mf < 2; mf++) {
        const int r0 = bm + wm * 32 + mf * 16 + qr;
        const int r1 = r0 + 8;
        int keep0 = 1, keep1 = 1;
        if (EPI == EPI_ROWMASK) { keep0 = mask[r0]; keep1 = mask[r1]; }
#pragma unroll
        for (int nf = 0; nf < 8; nf++) {
            const int cc = bn + wn * 64 + nf * 8 + qc * 2;
            float v0 = acc[mf][nf][0], v1 = acc[mf][nf][1];
            float v2 = acc[mf][nf][2], v3 = acc[mf][nf][3];
            if (EPI == EPI_BIAS || EPI == EPI_RELU || EPI == EPI_QSCALE ||
                EPI == EPI_ROWMASK) {
                float b0 = bias[cc], b1 = bias[cc + 1];
                v0 += b0; v1 += b1; v2 += b0; v3 += b1;
            }
            if (EPI == EPI_RELU) {
                v0 = fmaxf(v0, 0.f); v1 = fmaxf(v1, 0.f);
                v2 = fmaxf(v2, 0.f); v3 = fmaxf(v3, 0.f);
            }
            if (EPI == EPI_QSCALE) {
                v0 *= scale; v1 *= scale; v2 *= scale; v3 *= scale;
            }
            if (EPI == EPI_KEYMASK) {
                if (!mask[cc])     { v0 = -1e9f; v2 = -1e9f; }
                if (!mask[cc + 1]) { v1 = -1e9f; v3 = -1e9f; }
            }
            if (EPI == EPI_ROWMASK) {
                if (!keep0) { v0 = 0.f; v1 = 0.f; }
                if (!keep1) { v2 = 0.f; v3 = 0.f; }
            }
            float2 o0 = {v0, v1}, o1 = {v2, v3};
            *(float2*)&C[(long)r0 * ldc + cc] = o0;
            *(float2*)&C[(long)r1 * ldc + cc] = o1;
        }
    }
}

// ---------------- transpose: out[C][R] = in[R][C]^T --------------------------
__global__ void transpose_k(const float* __restrict__ in, float* __restrict__ out,
                            int R, int C)
{
    __shared__ float t[32][33];
    const int bx = blockIdx.x * 32, by = blockIdx.y * 32;
#pragma unroll
    for (int j = 0; j < 32; j += 8)
        t[threadIdx.y + j][threadIdx.x] =
            in[(long)(by + threadIdx.y + j) * C + bx + threadIdx.x];
    __syncthreads();
#pragma unroll
    for (int j = 0; j < 32; j += 8)
        out[(long)(bx + threadIdx.y + j) * R + by + threadIdx.x] =
            t[threadIdx.x][threadIdx.y + j];
}

// ---------------- mask: sigmoid(h @ w2 + b2) > 0.15 --------------------------
__global__ void score_k(const float* __restrict__ h, const float* __restrict__ w2,
                        const float* __restrict__ b2, int* __restrict__ mask)
{
    const int warp = (blockIdx.x * blockDim.x + threadIdx.x) >> 5;
    const int lane = threadIdx.x & 31;
    if (warp >= NTOK) return;
    const float* hr = h + warp * DHID;
    float s = 0.f;
#pragma unroll
    for (int i = 0; i < DHID / 32; i++)
        s += hr[lane + i * 32] * w2[lane + i * 32];
#pragma unroll
    for (int o = 16; o; o >>= 1) s += __shfl_xor_sync(0xffffffffu, s, o);
    if (lane == 0) {
        float sig = 1.0f / (1.0f + expf(-(s + b2[0])));
        mask[warp] = (sig > 0.15f) ? 1 : 0;
    }
}

// ---------------- row softmax: S fp32 -> P fp16 ------------------------------
__global__ __launch_bounds__(256) void softmax_k(const float* __restrict__ S,
                                                 __half* __restrict__ P)
{
    __shared__ float cache[NTOK];
    __shared__ float red[256];
    const size_t row = (size_t)blockIdx.y * NTOK + blockIdx.x;
    const float* Sr = S + row * NTOK;
    const int tid = threadIdx.x;

    float m = -3.4e38f;
#pragma unroll
    for (int i = 0; i < 4; i++) {
        float4 v = *(const float4*)&Sr[(tid + i * 256) * 4];
        m = fmaxf(m, fmaxf(fmaxf(v.x, v.y), fmaxf(v.z, v.w)));
    }
    red[tid] = m;
    __syncthreads();
    for (int s = 128; s; s >>= 1) {
        if (tid < s) red[tid] = fmaxf(red[tid], red[tid + s]);
        __syncthreads();
    }
    m = red[0];
    __syncthreads();

    float sum = 0.f;
#pragma unroll
    for (int i = 0; i < 4; i++) {
        int f4 = tid + i * 256;
        float4 v = *(const float4*)&Sr[f4 * 4];
        float4 p;
        p.x = __expf(v.x - m); p.y = __expf(v.y - m);
        p.z = __expf(v.z - m); p.w = __expf(v.w - m);
        *(float4*)&cache[f4 * 4] = p;
        sum += p.x + p.y + p.z + p.w;
    }
    red[tid] = sum;
    __syncthreads();
    for (int s = 128; s; s >>= 1) {
        if (tid < s) red[tid] += red[tid + s];
        __syncthreads();
    }
    const float inv = 1.0f / red[0];
    uint2* Pr = (uint2*)(P + row * NTOK);
#pragma unroll
    for (int i = 0; i < 4; i++) {
        int f4 = tid + i * 256;
        float4 p = *(const float4*)&cache[f4 * 4];
        uint2 o;
        o.x = pack2h(p.x * inv, p.y * inv);
        o.y = pack2h(p.z * inv, p.w * inv);
        Pr[f4] = o;
    }
}

// ---------------------------------------------------------------------------
extern "C" void kernel_launch(void* const* d_in, const int* in_sizes, int n_in,
                              void* d_out, int out_size)
{
    const float* q  = (const float*)d_in[0];
    const float* k  = (const float*)d_in[1];
    const float* v  = (const float*)d_in[2];
    const float* w1 = (const float*)d_in[3];
    const float* b1 = (const float*)d_in[4];
    const float* w2 = (const float*)d_in[5];
    const float* b2 = (const float*)d_in[6];
    const float* wq = (const float*)d_in[7];
    const float* bq = (const float*)d_in[8];
    const float* wk = (const float*)d_in[9];
    const float* bk = (const float*)d_in[10];
    const float* wv = (const float*)d_in[11];
    const float* bv = (const float*)d_in[12];
    const float* wo = (const float*)d_in[13];
    const float* bo = (const float*)d_in[14];
    float* out = (float*)d_out;

    float *hh, *qp, *kp, *vp, *ctx, *w1t, *wqt, *wkt, *wvt, *wot, *vpt, *S;
    __half* P;
    int* msk;
    cudaGetSymbolAddress((void**)&hh,  g_h);
    cudaGetSymbolAddress((void**)&msk, g_mask);
    cudaGetSymbolAddress((void**)&qp,  g_qp);
    cudaGetSymbolAddress((void**)&kp,  g_kp);
    cudaGetSymbolAddress((void**)&vp,  g_vp);
    cudaGetSymbolAddress((void**)&ctx, g_ctx);
    cudaGetSymbolAddress((void**)&w1t, g_w1t);
    cudaGetSymbolAddress((void**)&wqt, g_wqt);
    cudaGetSymbolAddress((void**)&wkt, g_wkt);
    cudaGetSymbolAddress((void**)&wvt, g_wvt);
    cudaGetSymbolAddress((void**)&wot, g_wot);
    cudaGetSymbolAddress((void**)&vpt, g_vpt);
    cudaGetSymbolAddress((void**)&S,   g_S);
    cudaGetSymbolAddress((void**)&P,   g_P);

    cudaFuncSetAttribute(gemm_bf<EPI_RAW, 1>,
        cudaFuncAttributeMaxDynamicSharedMemorySize, SMEM_BYTES);
    cudaFuncSetAttribute(gemm_bf<EPI_BIAS, 0>,
        cudaFuncAttributeMaxDynamicSharedMemorySize, SMEM_BYTES);
    cudaFuncSetAttribute(gemm_bf<EPI_RELU, 0>,
        cudaFuncAttributeMaxDynamicSharedMemorySize, SMEM_BYTES);
    cudaFuncSetAttribute(gemm_bf<EPI_QSCALE, 0>,
        cudaFuncAttributeMaxDynamicSharedMemorySize, SMEM_BYTES);
    cudaFuncSetAttribute(gemm_bf<EPI_KEYMASK, 0>,
        cudaFuncAttributeMaxDynamicSharedMemorySize, SMEM_BYTES);
    cudaFuncSetAttribute(gemm_bf<EPI_ROWMASK, 0>,
        cudaFuncAttributeMaxDynamicSharedMemorySize, SMEM_BYTES);

    dim3 tb(32, 8);
    transpose_k<<<dim3(DHID / 32, DMODEL / 32), tb>>>(w1, w1t, DMODEL, DHID);
    transpose_k<<<dim3(32, 32), tb>>>(wq, wqt, DMODEL, DMODEL);
    transpose_k<<<dim3(32, 32), tb>>>(wk, wkt, DMODEL, DMODEL);
    transpose_k<<<dim3(32, 32), tb>>>(wv, wvt, DMODEL, DMODEL);
    transpose_k<<<dim3(32, 32), tb>>>(wo, wot, DMODEL, DMODEL);

    // 1) predictor hidden: h = relu(q @ w1 + b1)
    gemm_bf<EPI_RELU, 0><<<dim3(DHID / 128, NTOK / 128), 256, SMEM_BYTES>>>(
        q, DMODEL, 0, w1t, DMODEL, 0, hh, DHID, 0, DMODEL, b1, nullptr, 0.f);
    // 2) token mask
    score_k<<<NTOK / 8, 256>>>(hh, w2, b2, msk);
    // 3) projections (softmax scale folded into qp)
    gemm_bf<EPI_QSCALE, 0><<<dim3(8, 32), 256, SMEM_BYTES>>>(
        q, DMODEL, 0, wqt, DMODEL, 0, qp, DMODEL, 0, DMODEL, bq, nullptr,
        0.0625f);
    gemm_bf<EPI_BIAS, 0><<<dim3(8, 32), 256, SMEM_BYTES>>>(
        k, DMODEL, 0, wkt, DMODEL, 0, kp, DMODEL, 0, DMODEL, bk, nullptr, 0.f);
    gemm_bf<EPI_BIAS, 0><<<dim3(8, 32), 256, SMEM_BYTES>>>(
        v, DMODEL, 0, wvt, DMODEL, 0, vp, DMODEL, 0, DMODEL, bv, nullptr, 0.f);
    // 4) transpose V projection -> [1024][4096]
    transpose_k<<<dim3(DMODEL / 32, NTOK / 32), tb>>>(vp, vpt, NTOK, DMODEL);
    // 5) S[h] = qp @ kp^T, masked keys -> -1e9
    gemm_bf<EPI_KEYMASK, 0><<<dim3(32, 32, NHEADS), 256, SMEM_BYTES>>>(
        qp, DMODEL, HDIM, kp, DMODEL, HDIM, S, NTOK, (long)NTOK * NTOK,
        HDIM, nullptr, msk, 0.f);
    // 6) softmax rows -> fp16 P
    softmax_k<<<dim3(NTOK, NHEADS), 256>>>(S, P);
    // 7) ctx[h] = P @ V  (plain fp16 A, hi-only B)
    gemm_bf<EPI_RAW, 1><<<dim3(HDIM / 128, 32, NHEADS), 256, SMEM_BYTES>>>(
        P, NTOK, (long)NTOK * NTOK, vpt, NTOK, (long)HDIM * NTOK,
        ctx, DMODEL, HDIM, NTOK, nullptr, nullptr, 0.f);
    // 8) out = rowmask(ctx @ wo + bo)
    gemm_bf<EPI_ROWMASK, 0><<<dim3(8, 32), 256, SMEM_BYTES>>>(
        ctx, DMODEL, 0, wot, DMODEL, 0, out, DMODEL, 0, DMODEL, bo, msk, 0.f);
}

// round 13
// speedup vs baseline: 1.3998x; 1.1273x over previous
#include <cuda_runtime.h>
#include <cuda_fp16.h>
#include <cstdint>
#include <math.h>

#define NTOK   4096
#define DMODEL 1024
#define DHID   256
#define NHEADS 4
#define HDIM   256

// ---------------- scratch (__device__ globals; no allocation allowed) -------
__device__ float  g_h  [NTOK * DHID];
__device__ int    g_mask[NTOK];
__device__ __half g_qp [NTOK * DMODEL];
__device__ __half g_kp [NTOK * DMODEL];
__device__ __half g_vp [NTOK * DMODEL];
__device__ __half g_vpt[DMODEL * NTOK];
__device__ float  g_ctx[NTOK * DMODEL];
__device__ float  g_w1t[DHID * DMODEL];
__device__ float  g_wqt[DMODEL * DMODEL];
__device__ float  g_wkt[DMODEL * DMODEL];
__device__ float  g_wvt[DMODEL * DMODEL];
__device__ float  g_wot[DMODEL * DMODEL];
__device__ float  g_S  [(size_t)NHEADS * NTOK * NTOK];    // 268MB
__device__ __half g_P  [(size_t)NHEADS * NTOK * NTOK];    // 134MB

// ---------------- fp16 helpers ----------------------------------------------
__device__ __forceinline__ void split2h(float x0, float x1,
                                        uint32_t& h, uint32_t& l) {
    __half2 hv = __floats2half2_rn(x0, x1);
    float f0 = __low2float(hv), f1 = __high2float(hv);
    __half2 lv = __floats2half2_rn(x0 - f0, x1 - f1);
    h = *(uint32_t*)&hv;
    l = *(uint32_t*)&lv;
}
__device__ __forceinline__ uint32_t pack2h(float x0, float x1) {
    __half2 hv = __floats2half2_rn(x0, x1);
    return *(uint32_t*)&hv;
}
__device__ __forceinline__ void mma16816(float* c, const uint32_t* a,
                                         const uint32_t* b) {
    asm volatile(
        "mma.sync.aligned.m16n8k16.row.col.f32.f16.f16.f32 "
        "{%0,%1,%2,%3}, {%4,%5,%6,%7}, {%8,%9}, {%0,%1,%2,%3};"
        : "+f"(c[0]), "+f"(c[1]), "+f"(c[2]), "+f"(c[3])
        : "r"(a[0]), "r"(a[1]), "r"(a[2]), "r"(a[3]), "r"(b[0]), "r"(b[1]));
}
__device__ __forceinline__ uint32_t smem_u32(const void* p) {
    uint32_t a;
    asm("{ .reg .u64 t; cvta.to.shared.u64 t, %1; cvt.u32.u64 %0, t; }"
        : "=r"(a) : "l"(p));
    return a;
}
__device__ __forceinline__ void ldsm4(uint32_t& r0, uint32_t& r1,
                                      uint32_t& r2, uint32_t& r3,
                                      uint32_t addr) {
    asm volatile("ldmatrix.sync.aligned.m8n8.x4.shared.b16 {%0,%1,%2,%3}, [%4];"
                 : "=r"(r0), "=r"(r1), "=r"(r2), "=r"(r3) : "r"(addr));
}

// ---------------- unified tensor-core GEMM ----------------------------------
// D[M,N] = A[M,K] @ B[N,K]^T (+ epilogue). CTA 128x128, K-chunk 32,
// 256 threads, 8 warps (4x2), warp tile 32x64, 2 CTAs/SM.
// AH: A is fp16 in gmem (1 MMA/frag) vs fp32 2-term split (2 MMAs/frag).
// BH: B is fp16 in gmem vs fp32 -> fp16 hi conversion.
// WH: epilogue writes fp16 (Ch) vs fp32 (C).
enum { EPI_RAW = 0, EPI_BIAS, EPI_RELU, EPI_QSCALE, EPI_KEYMASK, EPI_ROWMASK };

#define SROW   20                      // u32 per smem row (16 data + 4 pad)
#define STG_U  (128 * SROW)
#define SMEM_BYTES (2 * 3 * STG_U * 4) // max: Ah|Al|Bh double-buffered

template <int AH, int BH>
__device__ __forceinline__ void ldg_chunk(const void* __restrict__ Arow,
                                          int lda,
                                          const void* __restrict__ Brow,
                                          int ldb, int k0, int tid,
                                          float4* av, uint2* av2,
                                          float4* bv, uint2* bv2) {
#pragma unroll
    for (int i = 0; i < 4; i++) {
        int idx = tid + i * 256;
        int r = idx >> 3, c4 = idx & 7;
        if (AH)
            av2[i] = *(const uint2*)((const __half*)Arow +
                                     (long)r * lda + k0 + c4 * 4);
        else
            av[i] = *(const float4*)((const float*)Arow +
                                     (long)r * lda + k0 + c4 * 4);
        if (BH)
            bv2[i] = *(const uint2*)((const __half*)Brow +
                                     (long)r * ldb + k0 + c4 * 4);
        else
            bv[i] = *(const float4*)((const float*)Brow +
                                     (long)r * ldb + k0 + c4 * 4);
    }
}
template <int AH, int BH>
__device__ __forceinline__ void sts_chunk(uint32_t* st, int tid,
                                          const float4* av, const uint2* av2,
                                          const float4* bv, const uint2* bv2) {
    uint32_t* Ah = st;
    uint32_t* Al = st + STG_U;                   // unused when AH
    uint32_t* Bh = st + (AH ? 1 : 2) * STG_U;
#pragma unroll
    for (int i = 0; i < 4; i++) {
        int idx = tid + i * 256;
        int r = idx >> 3, c4 = idx & 7;
        int o = r * SROW + c4 * 2;
        if (AH) {
            Ah[o] = av2[i].x; Ah[o + 1] = av2[i].y;
        } else {
            uint32_t h01, l01, h23, l23;
            split2h(av[i].x, av[i].y, h01, l01);
            split2h(av[i].z, av[i].w, h23, l23);
            Ah[o] = h01; Ah[o + 1] = h23;
            Al[o] = l01; Al[o + 1] = l23;
        }
        if (BH) {
            Bh[o] = bv2[i].x; Bh[o + 1] = bv2[i].y;
        } else {
            Bh[o] = pack2h(bv[i].x, bv[i].y);
            Bh[o + 1] = pack2h(bv[i].z, bv[i].w);
        }
    }
}

template <int EPI, int AH, int BH, int WH>
__global__ __launch_bounds__(256, 2) void gemm_bf(
    const void* __restrict__ A, int lda, long aZ,
    const void* __restrict__ B, int ldb, long bZ,
    float* __restrict__ C, __half* __restrict__ Ch, int ldc, long cZ,
    int K, const float* __restrict__ bias,
    const int* __restrict__ mask, float scale)
{
    extern __shared__ __align__(16) char smem[];
    const int tid = threadIdx.x;
    const int wid = tid >> 5, lane = tid & 31;
    const int wm = wid & 3, wn = wid >> 2;      // 4x2 warp grid
    const int qr = lane >> 2, qc = lane & 3;
    const int bm = blockIdx.y * 128, bn = blockIdx.x * 128;
    const int stgb = (AH ? 2 : 3) * STG_U * 4;

    const void* Arow = AH
        ? (const void*)((const __half*)A + blockIdx.z * aZ + (long)bm * lda)
        : (const void*)((const float*)A + blockIdx.z * aZ + (long)bm * lda);
    const void* Brow = BH
        ? (const void*)((const __half*)B + blockIdx.z * bZ + (long)bn * ldb)
        : (const void*)((const float*)B + blockIdx.z * bZ + (long)bn * ldb);
    if (WH) Ch += blockIdx.z * cZ;
    else    C  += blockIdx.z * cZ;

    const int a_off = (wm * 32 + ((lane >> 3) & 1) * 8 + (lane & 7)) * SROW +
                      (lane >> 4) * 4;
    const int b_off = (wn * 64 + (lane >> 4) * 8 + (lane & 7)) * SROW +
                      ((lane >> 3) & 1) * 4;

    float acc[2][8][4];
#pragma unroll
    for (int mf = 0; mf < 2; mf++)
#pragma unroll
        for (int nf = 0; nf < 8; nf++)
#pragma unroll
            for (int j = 0; j < 4; j++) acc[mf][nf][j] = 0.f;

    const int nc = K / 32;
    float4 av[4], bv[4];
    uint2 av2[4], bv2[4];
    ldg_chunk<AH, BH>(Arow, lda, Brow, ldb, 0, tid, av, av2, bv, bv2);
    sts_chunk<AH, BH>((uint32_t*)smem, tid, av, av2, bv, bv2);
    __syncthreads();

    for (int c = 0; c < nc; c++) {
        if (c + 1 < nc)
            ldg_chunk<AH, BH>(Arow, lda, Brow, ldb, (c + 1) * 32, tid,
                              av, av2, bv, bv2);
        const uint32_t sb = smem_u32(smem + (c & 1) * stgb);
#pragma unroll
        for (int kk = 0; kk < 2; kk++) {
            uint32_t ah[2][4], al[2][4], bh[8][2];
#pragma unroll
            for (int mf = 0; mf < 2; mf++) {
                uint32_t ao = sb + (uint32_t)(a_off + mf * 16 * SROW + kk * 8) * 4;
                ldsm4(ah[mf][0], ah[mf][1], ah[mf][2], ah[mf][3], ao);
                if (!AH)
                    ldsm4(al[mf][0], al[mf][1], al[mf][2], al[mf][3],
                          ao + STG_U * 4);
            }
#pragma unroll
            for (int p = 0; p < 4; p++) {
                uint32_t bo = sb + (AH ? 1 : 2) * STG_U * 4 +
                              (uint32_t)(b_off + p * 16 * SROW + kk * 8) * 4;
                ldsm4(bh[2 * p][0], bh[2 * p][1],
                      bh[2 * p + 1][0], bh[2 * p + 1][1], bo);
            }
#pragma unroll
            for (int mf = 0; mf < 2; mf++)
#pragma unroll
                for (int nf = 0; nf < 8; nf++) {
                    mma16816(acc[mf][nf], ah[mf], bh[nf]);
                    if (!AH) mma16816(acc[mf][nf], al[mf], bh[nf]);
                }
        }
        __syncthreads();
        if (c + 1 < nc) {
            sts_chunk<AH, BH>((uint32_t*)(smem + ((c + 1) & 1) * stgb), tid,
                              av, av2, bv, bv2);
            __syncthreads();
        }
    }

#pragma unroll
    for (int mf = 0; mf < 2; mf++) {
        const int r0 = bm + wm * 32 + mf * 16 + qr;
        const int r1 = r0 + 8;
        int keep0 = 1, keep1 = 1;
        if (EPI == EPI_ROWMASK) { keep0 = mask[r0]; keep1 = mask[r1]; }
#pragma unroll
        for (int nf = 0; nf < 8; nf++) {
            const int cc = bn + wn * 64 + nf * 8 + qc * 2;
            float v0 = acc[mf][nf][0], v1 = acc[mf][nf][1];
            float v2 = acc[mf][nf][2], v3 = acc[mf][nf][3];
            if (EPI == EPI_BIAS || EPI == EPI_RELU || EPI == EPI_QSCALE ||
                EPI == EPI_ROWMASK) {
                float b0 = bias[cc], b1 = bias[cc + 1];
                v0 += b0; v1 += b1; v2 += b0; v3 += b1;
            }
            if (EPI == EPI_RELU) {
                v0 = fmaxf(v0, 0.f); v1 = fmaxf(v1, 0.f);
                v2 = fmaxf(v2, 0.f); v3 = fmaxf(v3, 0.f);
            }
            if (EPI == EPI_QSCALE) {
                v0 *= scale; v1 *= scale; v2 *= scale; v3 *= scale;
            }
            if (EPI == EPI_KEYMASK) {
                if (!mask[cc])     { v0 = -1e9f; v2 = -1e9f; }
                if (!mask[cc + 1]) { v1 = -1e9f; v3 = -1e9f; }
            }
            if (EPI == EPI_ROWMASK) {
                if (!keep0) { v0 = 0.f; v1 = 0.f; }
                if (!keep1) { v2 = 0.f; v3 = 0.f; }
            }
            if (WH) {
                *(uint32_t*)&Ch[(long)r0 * ldc + cc] = pack2h(v0, v1);
                *(uint32_t*)&Ch[(long)r1 * ldc + cc] = pack2h(v2, v3);
            } else {
                float2 o0 = {v0, v1}, o1 = {v2, v3};
                *(float2*)&C[(long)r0 * ldc + cc] = o0;
                *(float2*)&C[(long)r1 * ldc + cc] = o1;
            }
        }
    }
}

// ---------------- transposes -------------------------------------------------
__global__ void transpose_k(const float* __restrict__ in, float* __restrict__ out,
                            int R, int C)
{
    __shared__ float t[32][33];
    const int bx = blockIdx.x * 32, by = blockIdx.y * 32;
#pragma unroll
    for (int j = 0; j < 32; j += 8)
        t[threadIdx.y + j][threadIdx.x] =
            in[(long)(by + threadIdx.y + j) * C + bx + threadIdx.x];
    __syncthreads();
#pragma unroll
    for (int j = 0; j < 32; j += 8)
        out[(long)(bx + threadIdx.y + j) * R + by + threadIdx.x] =
            t[threadIdx.x][threadIdx.y + j];
}

__global__ void transpose_h(const __half* __restrict__ in,
                            __half* __restrict__ out, int R, int C)
{
    __shared__ __half t[32][34];
    const int bx = blockIdx.x * 32, by = blockIdx.y * 32;
#pragma unroll
    for (int j = 0; j < 32; j += 8)
        t[threadIdx.y + j][threadIdx.x] =
            in[(long)(by + threadIdx.y + j) * C + bx + threadIdx.x];
    __syncthreads();
#pragma unroll
    for (int j = 0; j < 32; j += 8)
        out[(long)(bx + threadIdx.y + j) * R + by + threadIdx.x] =
            t[threadIdx.x][threadIdx.y + j];
}

// ---------------- mask: sigmoid(h @ w2 + b2) > 0.15 --------------------------
__global__ void score_k(const float* __restrict__ h, const float* __restrict__ w2,
                        const float* __restrict__ b2, int* __restrict__ mask)
{
    const int warp = (blockIdx.x * blockDim.x + threadIdx.x) >> 5;
    const int lane = threadIdx.x & 31;
    if (warp >= NTOK) return;
    const float* hr = h + warp * DHID;
    float s = 0.f;
#pragma unroll
    for (int i = 0; i < DHID / 32; i++)
        s += hr[lane + i * 32] * w2[lane + i * 32];
#pragma unroll
    for (int o = 16; o; o >>= 1) s += __shfl_xor_sync(0xffffffffu, s, o);
    if (lane == 0) {
        float sig = 1.0f / (1.0f + expf(-(s + b2[0])));
        mask[warp] = (sig > 0.15f) ? 1 : 0;
    }
}

// ---------------- row softmax: S fp32 -> P fp16 ------------------------------
__global__ __launch_bounds__(256) void softmax_k(const float* __restrict__ S,
                                                 __half* __restrict__ P)
{
    __shared__ float cache[NTOK];
    __shared__ float red[256];
    const size_t row = (size_t)blockIdx.y * NTOK + blockIdx.x;
    const float* Sr = S + row * NTOK;
    const int tid = threadIdx.x;

    float m = -3.4e38f;
#pragma unroll
    for (int i = 0; i < 4; i++) {
        float4 v = *(const float4*)&Sr[(tid + i * 256) * 4];
        m = fmaxf(m, fmaxf(fmaxf(v.x, v.y), fmaxf(v.z, v.w)));
    }
    red[tid] = m;
    __syncthreads();
    for (int s = 128; s; s >>= 1) {
        if (tid < s) red[tid] = fmaxf(red[tid], red[tid + s]);
        __syncthreads();
    }
    m = red[0];
    __syncthreads();

    float sum = 0.f;
#pragma unroll
    for (int i = 0; i < 4; i++) {
        int f4 = tid + i * 256;
        float4 v = *(const float4*)&Sr[f4 * 4];
        float4 p;
        p.x = __expf(v.x - m); p.y = __expf(v.y - m);
        p.z = __expf(v.z - m); p.w = __expf(v.w - m);
        *(float4*)&cache[f4 * 4] = p;
        sum += p.x + p.y + p.z + p.w;
    }
    red[tid] = sum;
    __syncthreads();
    for (int s = 128; s; s >>= 1) {
        if (tid < s) red[tid] += red[tid + s];
        __syncthreads();
    }
    const float inv = 1.0f / red[0];
    uint2* Pr = (uint2*)(P + row * NTOK);
#pragma unroll
    for (int i = 0; i < 4; i++) {
        int f4 = tid + i * 256;
        float4 p = *(const float4*)&cache[f4 * 4];
        uint2 o;
        o.x = pack2h(p.x * inv, p.y * inv);
        o.y = pack2h(p.z * inv, p.w * inv);
        Pr[f4] = o;
    }
}

// ---------------------------------------------------------------------------
extern "C" void kernel_launch(void* const* d_in, const int* in_sizes, int n_in,
                              void* d_out, int out_size)
{
    const float* q  = (const float*)d_in[0];
    const float* k  = (const float*)d_in[1];
    const float* v  = (const float*)d_in[2];
    const float* w1 = (const float*)d_in[3];
    const float* b1 = (const float*)d_in[4];
    const float* w2 = (const float*)d_in[5];
    const float* b2 = (const float*)d_in[6];
    const float* wq = (const float*)d_in[7];
    const float* bq = (const float*)d_in[8];
    const float* wk = (const float*)d_in[9];
    const float* bk = (const float*)d_in[10];
    const float* wv = (const float*)d_in[11];
    const float* bv = (const float*)d_in[12];
    const float* wo = (const float*)d_in[13];
    const float* bo = (const float*)d_in[14];
    float* out = (float*)d_out;

    float *hh, *ctx, *w1t, *wqt, *wkt, *wvt, *wot, *S;
    __half *qp, *kp, *vp, *vpt, *P;
    int* msk;
    cudaGetSymbolAddress((void**)&hh,  g_h);
    cudaGetSymbolAddress((void**)&msk, g_mask);
    cudaGetSymbolAddress((void**)&qp,  g_qp);
    cudaGetSymbolAddress((void**)&kp,  g_kp);
    cudaGetSymbolAddress((void**)&vp,  g_vp);
    cudaGetSymbolAddress((void**)&vpt, g_vpt);
    cudaGetSymbolAddress((void**)&ctx, g_ctx);
    cudaGetSymbolAddress((void**)&w1t, g_w1t);
    cudaGetSymbolAddress((void**)&wqt, g_wqt);
    cudaGetSymbolAddress((void**)&wkt, g_wkt);
    cudaGetSymbolAddress((void**)&wvt, g_wvt);
    cudaGetSymbolAddress((void**)&wot, g_wot);
    cudaGetSymbolAddress((void**)&S,   g_S);
    cudaGetSymbolAddress((void**)&P,   g_P);

    cudaFuncSetAttribute(gemm_bf<EPI_RELU, 0, 0, 0>,
        cudaFuncAttributeMaxDynamicSharedMemorySize, SMEM_BYTES);
    cudaFuncSetAttribute(gemm_bf<EPI_QSCALE, 0, 0, 1>,
        cudaFuncAttributeMaxDynamicSharedMemorySize, SMEM_BYTES);
    cudaFuncSetAttribute(gemm_bf<EPI_BIAS, 0, 0, 1>,
        cudaFuncAttributeMaxDynamicSharedMemorySize, SMEM_BYTES);
    cudaFuncSetAttribute(gemm_bf<EPI_KEYMASK, 1, 1, 0>,
        cudaFuncAttributeMaxDynamicSharedMemorySize, SMEM_BYTES);
    cudaFuncSetAttribute(gemm_bf<EPI_RAW, 1, 1, 0>,
        cudaFuncAttributeMaxDynamicSharedMemorySize, SMEM_BYTES);
    cudaFuncSetAttribute(gemm_bf<EPI_ROWMASK, 0, 0, 0>,
        cudaFuncAttributeMaxDynamicSharedMemorySize, SMEM_BYTES);

    dim3 tb(32, 8);
    transpose_k<<<dim3(DHID / 32, DMODEL / 32), tb>>>(w1, w1t, DMODEL, DHID);
    transpose_k<<<dim3(32, 32), tb>>>(wq, wqt, DMODEL, DMODEL);
    transpose_k<<<dim3(32, 32), tb>>>(wk, wkt, DMODEL, DMODEL);
    transpose_k<<<dim3(32, 32), tb>>>(wv, wvt, DMODEL, DMODEL);
    transpose_k<<<dim3(32, 32), tb>>>(wo, wot, DMODEL, DMODEL);

    // 1) predictor hidden: h = relu(q @ w1 + b1)
    gemm_bf<EPI_RELU, 0, 0, 0>
        <<<dim3(DHID / 128, NTOK / 128), 256, SMEM_BYTES>>>(
        q, DMODEL, 0, w1t, DMODEL, 0, hh, nullptr, DHID, 0, DMODEL,
        b1, nullptr, 0.f);
    // 2) token mask
    score_k<<<NTOK / 8, 256>>>(hh, w2, b2, msk);
    // 3) projections -> fp16 outputs (softmax scale folded into qp)
    gemm_bf<EPI_QSCALE, 0, 0, 1><<<dim3(8, 32), 256, SMEM_BYTES>>>(
        q, DMODEL, 0, wqt, DMODEL, 0, nullptr, qp, DMODEL, 0, DMODEL,
        bq, nullptr, 0.0625f);
    gemm_bf<EPI_BIAS, 0, 0, 1><<<dim3(8, 32), 256, SMEM_BYTES>>>(
        k, DMODEL, 0, wkt, DMODEL, 0, nullptr, kp, DMODEL, 0, DMODEL,
        bk, nullptr, 0.f);
    gemm_bf<EPI_BIAS, 0, 0, 1><<<dim3(8, 32), 256, SMEM_BYTES>>>(
        v, DMODEL, 0, wvt, DMODEL, 0, nullptr, vp, DMODEL, 0, DMODEL,
        bv, nullptr, 0.f);
    // 4) transpose V projection (fp16) -> [1024][4096]
    transpose_h<<<dim3(DMODEL / 32, NTOK / 32), tb>>>(vp, vpt, NTOK, DMODEL);
    // 5) S[h] = qp @ kp^T (both fp16), masked keys -> -1e9
    gemm_bf<EPI_KEYMASK, 1, 1, 0><<<dim3(32, 32, NHEADS), 256, SMEM_BYTES>>>(
        qp, DMODEL, HDIM, kp, DMODEL, HDIM, S, nullptr, NTOK,
        (long)NTOK * NTOK, HDIM, nullptr, msk, 0.f);
    // 6) softmax rows -> fp16 P
    softmax_k<<<dim3(NTOK, NHEADS), 256>>>(S, P);
    // 7) ctx[h] = P @ V (both fp16)
    gemm_bf<EPI_RAW, 1, 1, 0><<<dim3(HDIM / 128, 32, NHEADS), 256, SMEM_BYTES>>>(
        P, NTOK, (long)NTOK * NTOK, vpt, NTOK, (long)HDIM * NTOK,
        ctx, nullptr, DMODEL, HDIM, NTOK, nullptr, nullptr, 0.f);
    // 8) out = rowmask(ctx @ wo + bo)
    gemm_bf<EPI_ROWMASK, 0, 0, 0><<<dim3(8, 32), 256, SMEM_BYTES>>>(
        ctx, DMODEL, 0, wot, DMODEL, 0, out, nullptr, DMODEL, 0, DMODEL,
        bo, msk, 0.f);
}

// round 14
// speedup vs baseline: 1.4110x; 1.0080x over previous
#include <cuda_runtime.h>
#include <cuda_fp16.h>
#include <cstdint>
#include <math.h>

#define NTOK   4096
#define DMODEL 1024
#define DHID   256
#define NHEADS 4
#define HDIM   256

// ---------------- scratch (__device__ globals; no allocation allowed) -------
__device__ float  g_h  [NTOK * DHID];
__device__ int    g_mask[NTOK];
__device__ __half g_qp [NTOK * DMODEL];
__device__ __half g_kp [NTOK * DMODEL];
__device__ __half g_vp [NTOK * DMODEL];
__device__ __half g_vpt[DMODEL * NTOK];
__device__ float  g_ctx[NTOK * DMODEL];
__device__ float  g_w1t[DHID * DMODEL];
__device__ float  g_wqt[DMODEL * DMODEL];
__device__ float  g_wkt[DMODEL * DMODEL];
__device__ float  g_wvt[DMODEL * DMODEL];
__device__ float  g_wot[DMODEL * DMODEL];
__device__ __half g_S  [(size_t)NHEADS * NTOK * NTOK];    // 134MB
__device__ __half g_P  [(size_t)NHEADS * NTOK * NTOK];    // 134MB

#define MASK_NEG (-60000.0f)   // finite in fp16; exp() == 0 after row-max shift

// ---------------- fp16 helpers ----------------------------------------------
__device__ __forceinline__ void split2h(float x0, float x1,
                                        uint32_t& h, uint32_t& l) {
    __half2 hv = __floats2half2_rn(x0, x1);
    float f0 = __low2float(hv), f1 = __high2float(hv);
    __half2 lv = __floats2half2_rn(x0 - f0, x1 - f1);
    h = *(uint32_t*)&hv;
    l = *(uint32_t*)&lv;
}
__device__ __forceinline__ uint32_t pack2h(float x0, float x1) {
    __half2 hv = __floats2half2_rn(x0, x1);
    return *(uint32_t*)&hv;
}
__device__ __forceinline__ void mma16816(float* c, const uint32_t* a,
                                         const uint32_t* b) {
    asm volatile(
        "mma.sync.aligned.m16n8k16.row.col.f32.f16.f16.f32 "
        "{%0,%1,%2,%3}, {%4,%5,%6,%7}, {%8,%9}, {%0,%1,%2,%3};"
        : "+f"(c[0]), "+f"(c[1]), "+f"(c[2]), "+f"(c[3])
        : "r"(a[0]), "r"(a[1]), "r"(a[2]), "r"(a[3]), "r"(b[0]), "r"(b[1]));
}
__device__ __forceinline__ uint32_t smem_u32(const void* p) {
    uint32_t a;
    asm("{ .reg .u64 t; cvta.to.shared.u64 t, %1; cvt.u32.u64 %0, t; }"
        : "=r"(a) : "l"(p));
    return a;
}
__device__ __forceinline__ void ldsm4(uint32_t& r0, uint32_t& r1,
                                      uint32_t& r2, uint32_t& r3,
                                      uint32_t addr) {
    asm volatile("ldmatrix.sync.aligned.m8n8.x4.shared.b16 {%0,%1,%2,%3}, [%4];"
                 : "=r"(r0), "=r"(r1), "=r"(r2), "=r"(r3) : "r"(addr));
}

// ---------------- unified tensor-core GEMM ----------------------------------
// D[M,N] = A[M,K] @ B[N,K]^T (+ epilogue). CTA 128x128, K-chunk 32,
// 256 threads, 8 warps (4x2), warp tile 32x64, 2 CTAs/SM.
// AH/BH: operand is fp16 in gmem. WH: epilogue writes fp16.
enum { EPI_RAW = 0, EPI_BIAS, EPI_RELU, EPI_QSCALE, EPI_KEYMASK, EPI_ROWMASK };

#define SROW   20                      // u32 per smem row (16 data + 4 pad)
#define STG_U  (128 * SROW)
#define SMEM_BYTES (2 * 3 * STG_U * 4) // max: Ah|Al|Bh double-buffered

template <int AH, int BH>
__device__ __forceinline__ void ldg_chunk(const void* __restrict__ Arow,
                                          int lda,
                                          const void* __restrict__ Brow,
                                          int ldb, int k0, int tid,
                                          float4* av, uint2* av2,
                                          float4* bv, uint2* bv2) {
#pragma unroll
    for (int i = 0; i < 4; i++) {
        int idx = tid + i * 256;
        int r = idx >> 3, c4 = idx & 7;
        if (AH)
            av2[i] = *(const uint2*)((const __half*)Arow +
                                     (long)r * lda + k0 + c4 * 4);
        else
            av[i] = *(const float4*)((const float*)Arow +
                                     (long)r * lda + k0 + c4 * 4);
        if (BH)
            bv2[i] = *(const uint2*)((const __half*)Brow +
                                     (long)r * ldb + k0 + c4 * 4);
        else
            bv[i] = *(const float4*)((const float*)Brow +
                                     (long)r * ldb + k0 + c4 * 4);
    }
}
template <int AH, int BH>
__device__ __forceinline__ void sts_chunk(uint32_t* st, int tid,
                                          const float4* av, const uint2* av2,
                                          const float4* bv, const uint2* bv2) {
    uint32_t* Ah = st;
    uint32_t* Al = st + STG_U;                   // unused when AH
    uint32_t* Bh = st + (AH ? 1 : 2) * STG_U;
#pragma unroll
    for (int i = 0; i < 4; i++) {
        int idx = tid + i * 256;
        int r = idx >> 3, c4 = idx & 7;
        int o = r * SROW + c4 * 2;
        if (AH) {
            Ah[o] = av2[i].x; Ah[o + 1] = av2[i].y;
        } else {
            uint32_t h01, l01, h23, l23;
            split2h(av[i].x, av[i].y, h01, l01);
            split2h(av[i].z, av[i].w, h23, l23);
            Ah[o] = h01; Ah[o + 1] = h23;
            Al[o] = l01; Al[o + 1] = l23;
        }
        if (BH) {
            Bh[o] = bv2[i].x; Bh[o + 1] = bv2[i].y;
        } else {
            Bh[o] = pack2h(bv[i].x, bv[i].y);
            Bh[o + 1] = pack2h(bv[i].z, bv[i].w);
        }
    }
}

template <int EPI, int AH, int BH, int WH>
__global__ __launch_bounds__(256, 2) void gemm_bf(
    const void* __restrict__ A, int lda, long aZ,
    const void* __restrict__ B, int ldb, long bZ,
    float* __restrict__ C, __half* __restrict__ Ch, int ldc, long cZ,
    int K, const float* __restrict__ bias,
    const int* __restrict__ mask, float scale)
{
    extern __shared__ __align__(16) char smem[];
    const int tid = threadIdx.x;
    const int wid = tid >> 5, lane = tid & 31;
    const int wm = wid & 3, wn = wid >> 2;      // 4x2 warp grid
    const int qr = lane >> 2, qc = lane & 3;
    const int bm = blockIdx.y * 128, bn = blockIdx.x * 128;
    const int stgb = (AH ? 2 : 3) * STG_U * 4;

    const void* Arow = AH
        ? (const void*)((const __half*)A + blockIdx.z * aZ + (long)bm * lda)
        : (const void*)((const float*)A + blockIdx.z * aZ + (long)bm * lda);
    const void* Brow = BH
        ? (const void*)((const __half*)B + blockIdx.z * bZ + (long)bn * ldb)
        : (const void*)((const float*)B + blockIdx.z * bZ + (long)bn * ldb);
    if (WH) Ch += blockIdx.z * cZ;
    else    C  += blockIdx.z * cZ;

    const int a_off = (wm * 32 + ((lane >> 3) & 1) * 8 + (lane & 7)) * SROW +
                      (lane >> 4) * 4;
    const int b_off = (wn * 64 + (lane >> 4) * 8 + (lane & 7)) * SROW +
                      ((lane >> 3) & 1) * 4;

    float acc[2][8][4];
#pragma unroll
    for (int mf = 0; mf < 2; mf++)
#pragma unroll
        for (int nf = 0; nf < 8; nf++)
#pragma unroll
            for (int j = 0; j < 4; j++) acc[mf][nf][j] = 0.f;

    const int nc = K / 32;
    float4 av[4], bv[4];
    uint2 av2[4], bv2[4];
    ldg_chunk<AH, BH>(Arow, lda, Brow, ldb, 0, tid, av, av2, bv, bv2);
    sts_chunk<AH, BH>((uint32_t*)smem, tid, av, av2, bv, bv2);
    __syncthreads();

    for (int c = 0; c < nc; c++) {
        if (c + 1 < nc)
            ldg_chunk<AH, BH>(Arow, lda, Brow, ldb, (c + 1) * 32, tid,
                              av, av2, bv, bv2);
        const uint32_t sb = smem_u32(smem + (c & 1) * stgb);
#pragma unroll
        for (int kk = 0; kk < 2; kk++) {
            uint32_t ah[2][4], al[2][4], bh[8][2];
#pragma unroll
            for (int mf = 0; mf < 2; mf++) {
                uint32_t ao = sb + (uint32_t)(a_off + mf * 16 * SROW + kk * 8) * 4;
                ldsm4(ah[mf][0], ah[mf][1], ah[mf][2], ah[mf][3], ao);
                if (!AH)
                    ldsm4(al[mf][0], al[mf][1], al[mf][2], al[mf][3],
                          ao + STG_U * 4);
            }
#pragma unroll
            for (int p = 0; p < 4; p++) {
                uint32_t bo = sb + (AH ? 1 : 2) * STG_U * 4 +
                              (uint32_t)(b_off + p * 16 * SROW + kk * 8) * 4;
                ldsm4(bh[2 * p][0], bh[2 * p][1],
                      bh[2 * p + 1][0], bh[2 * p + 1][1], bo);
            }
#pragma unroll
            for (int mf = 0; mf < 2; mf++)
#pragma unroll
                for (int nf = 0; nf < 8; nf++) {
                    mma16816(acc[mf][nf], ah[mf], bh[nf]);
                    if (!AH) mma16816(acc[mf][nf], al[mf], bh[nf]);
                }
        }
        __syncthreads();
        if (c + 1 < nc) {
            sts_chunk<AH, BH>((uint32_t*)(smem + ((c + 1) & 1) * stgb), tid,
                              av, av2, bv, bv2);
            __syncthreads();
        }
    }

#pragma unroll
    for (int mf = 0; mf < 2; mf++) {
        const int r0 = bm + wm * 32 + mf * 16 + qr;
        const int r1 = r0 + 8;
        int keep0 = 1, keep1 = 1;
        if (EPI == EPI_ROWMASK) { keep0 = mask[r0]; keep1 = mask[r1]; }
#pragma unroll
        for (int nf = 0; nf < 8; nf++) {
            const int cc = bn + wn * 64 + nf * 8 + qc * 2;
            float v0 = acc[mf][nf][0], v1 = acc[mf][nf][1];
            float v2 = acc[mf][nf][2], v3 = acc[mf][nf][3];
            if (EPI == EPI_BIAS || EPI == EPI_RELU || EPI == EPI_QSCALE ||
                EPI == EPI_ROWMASK) {
                float b0 = bias[cc], b1 = bias[cc + 1];
                v0 += b0; v1 += b1; v2 += b0; v3 += b1;
            }
            if (EPI == EPI_RELU) {
                v0 = fmaxf(v0, 0.f); v1 = fmaxf(v1, 0.f);
                v2 = fmaxf(v2, 0.f); v3 = fmaxf(v3, 0.f);
            }
            if (EPI == EPI_QSCALE) {
                v0 *= scale; v1 *= scale; v2 *= scale; v3 *= scale;
            }
            if (EPI == EPI_KEYMASK) {
                if (!mask[cc])     { v0 = MASK_NEG; v2 = MASK_NEG; }
                if (!mask[cc + 1]) { v1 = MASK_NEG; v3 = MASK_NEG; }
            }
            if (EPI == EPI_ROWMASK) {
                if (!keep0) { v0 = 0.f; v1 = 0.f; }
                if (!keep1) { v2 = 0.f; v3 = 0.f; }
            }
            if (WH) {
                *(uint32_t*)&Ch[(long)r0 * ldc + cc] = pack2h(v0, v1);
                *(uint32_t*)&Ch[(long)r1 * ldc + cc] = pack2h(v2, v3);
            } else {
                float2 o0 = {v0, v1}, o1 = {v2, v3};
                *(float2*)&C[(long)r0 * ldc + cc] = o0;
                *(float2*)&C[(long)r1 * ldc + cc] = o1;
            }
        }
    }
}

// ---------------- transposes -------------------------------------------------
__global__ void transpose_k(const float* __restrict__ in, float* __restrict__ out,
                            int R, int C)
{
    __shared__ float t[32][33];
    const int bx = blockIdx.x * 32, by = blockIdx.y * 32;
#pragma unroll
    for (int j = 0; j < 32; j += 8)
        t[threadIdx.y + j][threadIdx.x] =
            in[(long)(by + threadIdx.y + j) * C + bx + threadIdx.x];
    __syncthreads();
#pragma unroll
    for (int j = 0; j < 32; j += 8)
        out[(long)(bx + threadIdx.y + j) * R + by + threadIdx.x] =
            t[threadIdx.x][threadIdx.y + j];
}

__global__ void transpose_h(const __half* __restrict__ in,
                            __half* __restrict__ out, int R, int C)
{
    __shared__ __half t[32][34];
    const int bx = blockIdx.x * 32, by = blockIdx.y * 32;
#pragma unroll
    for (int j = 0; j < 32; j += 8)
        t[threadIdx.y + j][threadIdx.x] =
            in[(long)(by + threadIdx.y + j) * C + bx + threadIdx.x];
    __syncthreads();
#pragma unroll
    for (int j = 0; j < 32; j += 8)
        out[(long)(bx + threadIdx.y + j) * R + by + threadIdx.x] =
            t[threadIdx.x][threadIdx.y + j];
}

// ---------------- mask: sigmoid(h @ w2 + b2) > 0.15 --------------------------
__global__ void score_k(const float* __restrict__ h, const float* __restrict__ w2,
                        const float* __restrict__ b2, int* __restrict__ mask)
{
    const int warp = (blockIdx.x * blockDim.x + threadIdx.x) >> 5;
    const int lane = threadIdx.x & 31;
    if (warp >= NTOK) return;
    const float* hr = h + warp * DHID;
    float s = 0.f;
#pragma unroll
    for (int i = 0; i < DHID / 32; i++)
        s += hr[lane + i * 32] * w2[lane + i * 32];
#pragma unroll
    for (int o = 16; o; o >>= 1) s += __shfl_xor_sync(0xffffffffu, s, o);
    if (lane == 0) {
        float sig = 1.0f / (1.0f + expf(-(s + b2[0])));
        mask[warp] = (sig > 0.15f) ? 1 : 0;
    }
}

// ---------------- row softmax: S fp16 -> P fp16 ------------------------------
__global__ __launch_bounds__(256) void softmax_k(const __half* __restrict__ S,
                                                 __half* __restrict__ P)
{
    __shared__ float cache[NTOK];
    __shared__ float red[256];
    const size_t row = (size_t)blockIdx.y * NTOK + blockIdx.x;
    const uint2* Sr = (const uint2*)(S + row * NTOK);
    const int tid = threadIdx.x;

    // pass 1: load fp16 row, stage floats in smem, row max
    float m = -3.4e38f;
#pragma unroll
    for (int i = 0; i < 4; i++) {
        int u2i = tid + i * 256;              // 1024 uint2 = 4096 halves
        uint2 u = Sr[u2i];
        __half2 h0 = *(__half2*)&u.x, h1 = *(__half2*)&u.y;
        float f0 = __low2float(h0), f1 = __high2float(h0);
        float f2 = __low2float(h1), f3 = __high2float(h1);
        float4 fv = {f0, f1, f2, f3};
        *(float4*)&cache[u2i * 4] = fv;
        m = fmaxf(m, fmaxf(fmaxf(f0, f1), fmaxf(f2, f3)));
    }
    red[tid] = m;
    __syncthreads();
    for (int s = 128; s; s >>= 1) {
        if (tid < s) red[tid] = fmaxf(red[tid], red[tid + s]);
        __syncthreads();
    }
    m = red[0];
    __syncthreads();

    // pass 2: exp from smem, sum
    float sum = 0.f;
#pragma unroll
    for (int i = 0; i < 4; i++) {
        int f4 = tid + i * 256;
        float4 v = *(const float4*)&cache[f4 * 4];
        float4 p;
        p.x = __expf(v.x - m); p.y = __expf(v.y - m);
        p.z = __expf(v.z - m); p.w = __expf(v.w - m);
        *(float4*)&cache[f4 * 4] = p;
        sum += p.x + p.y + p.z + p.w;
    }
    red[tid] = sum;
    __syncthreads();
    for (int s = 128; s; s >>= 1) {
        if (tid < s) red[tid] += red[tid + s];
        __syncthreads();
    }
    const float inv = 1.0f / red[0];
    uint2* Pr = (uint2*)(P + row * NTOK);
#pragma unroll
    for (int i = 0; i < 4; i++) {
        int f4 = tid + i * 256;
        float4 p = *(const float4*)&cache[f4 * 4];
        uint2 o;
        o.x = pack2h(p.x * inv, p.y * inv);
        o.y = pack2h(p.z * inv, p.w * inv);
        Pr[f4] = o;
    }
}

// ---------------------------------------------------------------------------
extern "C" void kernel_launch(void* const* d_in, const int* in_sizes, int n_in,
                              void* d_out, int out_size)
{
    const float* q  = (const float*)d_in[0];
    const float* k  = (const float*)d_in[1];
    const float* v  = (const float*)d_in[2];
    const float* w1 = (const float*)d_in[3];
    const float* b1 = (const float*)d_in[4];
    const float* w2 = (const float*)d_in[5];
    const float* b2 = (const float*)d_in[6];
    const float* wq = (const float*)d_in[7];
    const float* bq = (const float*)d_in[8];
    const float* wk = (const float*)d_in[9];
    const float* bk = (const float*)d_in[10];
    const float* wv = (const float*)d_in[11];
    const float* bv = (const float*)d_in[12];
    const float* wo = (const float*)d_in[13];
    const float* bo = (const float*)d_in[14];
    float* out = (float*)d_out;

    float *hh, *ctx, *w1t, *wqt, *wkt, *wvt, *wot;
    __half *qp, *kp, *vp, *vpt, *S, *P;
    int* msk;
    cudaGetSymbolAddress((void**)&hh,  g_h);
    cudaGetSymbolAddress((void**)&msk, g_mask);
    cudaGetSymbolAddress((void**)&qp,  g_qp);
    cudaGetSymbolAddress((void**)&kp,  g_kp);
    cudaGetSymbolAddress((void**)&vp,  g_vp);
    cudaGetSymbolAddress((void**)&vpt, g_vpt);
    cudaGetSymbolAddress((void**)&ctx, g_ctx);
    cudaGetSymbolAddress((void**)&w1t, g_w1t);
    cudaGetSymbolAddress((void**)&wqt, g_wqt);
    cudaGetSymbolAddress((void**)&wkt, g_wkt);
    cudaGetSymbolAddress((void**)&wvt, g_wvt);
    cudaGetSymbolAddress((void**)&wot, g_wot);
    cudaGetSymbolAddress((void**)&S,   g_S);
    cudaGetSymbolAddress((void**)&P,   g_P);

    cudaFuncSetAttribute(gemm_bf<EPI_RELU, 0, 0, 0>,
        cudaFuncAttributeMaxDynamicSharedMemorySize, SMEM_BYTES);
    cudaFuncSetAttribute(gemm_bf<EPI_QSCALE, 0, 0, 1>,
        cudaFuncAttributeMaxDynamicSharedMemorySize, SMEM_BYTES);
    cudaFuncSetAttribute(gemm_bf<EPI_BIAS, 0, 0, 1>,
        cudaFuncAttributeMaxDynamicSharedMemorySize, SMEM_BYTES);
    cudaFuncSetAttribute(gemm_bf<EPI_KEYMASK, 1, 1, 1>,
        cudaFuncAttributeMaxDynamicSharedMemorySize, SMEM_BYTES);
    cudaFuncSetAttribute(gemm_bf<EPI_RAW, 1, 1, 0>,
        cudaFuncAttributeMaxDynamicSharedMemorySize, SMEM_BYTES);
    cudaFuncSetAttribute(gemm_bf<EPI_ROWMASK, 0, 0, 0>,
        cudaFuncAttributeMaxDynamicSharedMemorySize, SMEM_BYTES);

    dim3 tb(32, 8);
    transpose_k<<<dim3(DHID / 32, DMODEL / 32), tb>>>(w1, w1t, DMODEL, DHID);
    transpose_k<<<dim3(32, 32), tb>>>(wq, wqt, DMODEL, DMODEL);
    transpose_k<<<dim3(32, 32), tb>>>(wk, wkt, DMODEL, DMODEL);
    transpose_k<<<dim3(32, 32), tb>>>(wv, wvt, DMODEL, DMODEL);
    transpose_k<<<dim3(32, 32), tb>>>(wo, wot, DMODEL, DMODEL);

    // 1) predictor hidden: h = relu(q @ w1 + b1)
    gemm_bf<EPI_RELU, 0, 0, 0>
        <<<dim3(DHID / 128, NTOK / 128), 256, SMEM_BYTES>>>(
        q, DMODEL, 0, w1t, DMODEL, 0, hh, nullptr, DHID, 0, DMODEL,
        b1, nullptr, 0.f);
    // 2) token mask
    score_k<<<NTOK / 8, 256>>>(hh, w2, b2, msk);
    // 3) projections -> fp16 outputs (softmax scale folded into qp)
    gemm_bf<EPI_QSCALE, 0, 0, 1><<<dim3(8, 32), 256, SMEM_BYTES>>>(
        q, DMODEL, 0, wqt, DMODEL, 0, nullptr, qp, DMODEL, 0, DMODEL,
        bq, nullptr, 0.0625f);
    gemm_bf<EPI_BIAS, 0, 0, 1><<<dim3(8, 32), 256, SMEM_BYTES>>>(
        k, DMODEL, 0, wkt, DMODEL, 0, nullptr, kp, DMODEL, 0, DMODEL,
        bk, nullptr, 0.f);
    gemm_bf<EPI_BIAS, 0, 0, 1><<<dim3(8, 32), 256, SMEM_BYTES>>>(
        v, DMODEL, 0, wvt, DMODEL, 0, nullptr, vp, DMODEL, 0, DMODEL,
        bv, nullptr, 0.f);
    // 4) transpose V projection (fp16) -> [1024][4096]
    transpose_h<<<dim3(DMODEL / 32, NTOK / 32), tb>>>(vp, vpt, NTOK, DMODEL);
    // 5) S[h] = qp @ kp^T (both fp16) -> fp16 S, masked keys -> -60000
    gemm_bf<EPI_KEYMASK, 1, 1, 1><<<dim3(32, 32, NHEADS), 256, SMEM_BYTES>>>(
        qp, DMODEL, HDIM, kp, DMODEL, HDIM, nullptr, S, NTOK,
        (long)NTOK * NTOK, HDIM, nullptr, msk, 0.f);
    // 6) softmax rows (fp16 in) -> fp16 P
    softmax_k<<<dim3(NTOK, NHEADS), 256>>>(S, P);
    // 7) ctx[h] = P @ V (both fp16)
    gemm_bf<EPI_RAW, 1, 1, 0><<<dim3(HDIM / 128, 32, NHEADS), 256, SMEM_BYTES>>>(
        P, NTOK, (long)NTOK * NTOK, vpt, NTOK, (long)HDIM * NTOK,
        ctx, nullptr, DMODEL, HDIM, NTOK, nullptr, nullptr, 0.f);
    // 8) out = rowmask(ctx @ wo + bo)
    gemm_bf<EPI_ROWMASK, 0, 0, 0><<<dim3(8, 32), 256, SMEM_BYTES>>>(
        ctx, DMODEL, 0, wot, DMODEL, 0, out, nullptr, DMODEL, 0, DMODEL,
        bo, msk, 0.f);
}

// round 15
// speedup vs baseline: 1.4960x; 1.0602x over previous
#include <cuda_runtime.h>
#include <cuda_fp16.h>
#include <cstdint>
#include <math.h>

#define NTOK   4096
#define DMODEL 1024
#define DHID   256
#define NHEADS 4
#define HDIM   256

// ---------------- scratch (__device__ globals; no allocation allowed) -------
__device__ float  g_h  [NTOK * DHID];
__device__ int    g_mask[NTOK];
__device__ __half g_qp [NTOK * DMODEL];
__device__ __half g_kp [NTOK * DMODEL];
__device__ __half g_vp [NTOK * DMODEL];
__device__ __half g_vpt[DMODEL * NTOK];
__device__ float  g_ctx[NTOK * DMODEL];
__device__ float  g_w1t[DHID * DMODEL];
__device__ float  g_wqt[DMODEL * DMODEL];
__device__ float  g_wkt[DMODEL * DMODEL];
__device__ float  g_wvt[DMODEL * DMODEL];
__device__ float  g_wot[DMODEL * DMODEL];
__device__ __half g_S  [(size_t)NHEADS * NTOK * NTOK];    // 134MB
__device__ __half g_P  [(size_t)NHEADS * NTOK * NTOK];    // 134MB

#define MASK_NEG (-60000.0f)   // finite in fp16; exp() == 0 after row-max shift

// ---------------- fp16 helpers ----------------------------------------------
__device__ __forceinline__ void split2h(float x0, float x1,
                                        uint32_t& h, uint32_t& l) {
    __half2 hv = __floats2half2_rn(x0, x1);
    float f0 = __low2float(hv), f1 = __high2float(hv);
    __half2 lv = __floats2half2_rn(x0 - f0, x1 - f1);
    h = *(uint32_t*)&hv;
    l = *(uint32_t*)&lv;
}
__device__ __forceinline__ uint32_t pack2h(float x0, float x1) {
    __half2 hv = __floats2half2_rn(x0, x1);
    return *(uint32_t*)&hv;
}
__device__ __forceinline__ void mma16816(float* c, const uint32_t* a,
                                         const uint32_t* b) {
    asm volatile(
        "mma.sync.aligned.m16n8k16.row.col.f32.f16.f16.f32 "
        "{%0,%1,%2,%3}, {%4,%5,%6,%7}, {%8,%9}, {%0,%1,%2,%3};"
        : "+f"(c[0]), "+f"(c[1]), "+f"(c[2]), "+f"(c[3])
        : "r"(a[0]), "r"(a[1]), "r"(a[2]), "r"(a[3]), "r"(b[0]), "r"(b[1]));
}
__device__ __forceinline__ uint32_t smem_u32(const void* p) {
    uint32_t a;
    asm("{ .reg .u64 t; cvta.to.shared.u64 t, %1; cvt.u32.u64 %0, t; }"
        : "=r"(a) : "l"(p));
    return a;
}
__device__ __forceinline__ void ldsm4(uint32_t& r0, uint32_t& r1,
                                      uint32_t& r2, uint32_t& r3,
                                      uint32_t addr) {
    asm volatile("ldmatrix.sync.aligned.m8n8.x4.shared.b16 {%0,%1,%2,%3}, [%4];"
                 : "=r"(r0), "=r"(r1), "=r"(r2), "=r"(r3) : "r"(addr));
}

// ---------------- unified tensor-core GEMM core ------------------------------
// D[M,N] = A[M,K] @ B[N,K]^T (+ epilogue). CTA 128x128, K-chunk 32,
// 256 threads, 8 warps (4x2), warp tile 32x64.
// AH/BH: operand fp16 in gmem. WH: epilogue writes fp16.
enum { EPI_RAW = 0, EPI_BIAS, EPI_RELU, EPI_QSCALE, EPI_KEYMASK, EPI_ROWMASK };

#define SROW   20                      // u32 per smem row (16 data + 4 pad)
#define STG_U  (128 * SROW)
#define SMEM_BYTES (2 * 3 * STG_U * 4) // 61440

template <int AH, int BH>
__device__ __forceinline__ void ldg_chunk(const void* __restrict__ Arow,
                                          int lda,
                                          const void* __restrict__ Brow,
                                          int ldb, int k0, int tid,
                                          float4* av, uint2* av2,
                                          float4* bv, uint2* bv2) {
#pragma unroll
    for (int i = 0; i < 4; i++) {
        int idx = tid + i * 256;
        int r = idx >> 3, c4 = idx & 7;
        if (AH)
            av2[i] = *(const uint2*)((const __half*)Arow +
                                     (long)r * lda + k0 + c4 * 4);
        else
            av[i] = *(const float4*)((const float*)Arow +
                                     (long)r * lda + k0 + c4 * 4);
        if (BH)
            bv2[i] = *(const uint2*)((const __half*)Brow +
                                     (long)r * ldb + k0 + c4 * 4);
        else
            bv[i] = *(const float4*)((const float*)Brow +
                                     (long)r * ldb + k0 + c4 * 4);
    }
}
template <int AH, int BH>
__device__ __forceinline__ void sts_chunk(uint32_t* st, int tid,
                                          const float4* av, const uint2* av2,
                                          const float4* bv, const uint2* bv2) {
    uint32_t* Ah = st;
    uint32_t* Al = st + STG_U;
    uint32_t* Bh = st + (AH ? 1 : 2) * STG_U;
#pragma unroll
    for (int i = 0; i < 4; i++) {
        int idx = tid + i * 256;
        int r = idx >> 3, c4 = idx & 7;
        int o = r * SROW + c4 * 2;
        if (AH) {
            Ah[o] = av2[i].x; Ah[o + 1] = av2[i].y;
        } else {
            uint32_t h01, l01, h23, l23;
            split2h(av[i].x, av[i].y, h01, l01);
            split2h(av[i].z, av[i].w, h23, l23);
            Ah[o] = h01; Ah[o + 1] = h23;
            Al[o] = l01; Al[o + 1] = l23;
        }
        if (BH) {
            Bh[o] = bv2[i].x; Bh[o + 1] = bv2[i].y;
        } else {
            Bh[o] = pack2h(bv[i].x, bv[i].y);
            Bh[o + 1] = pack2h(bv[i].z, bv[i].w);
        }
    }
}

template <int EPI, int AH, int BH, int WH>
__device__ __forceinline__ void gemm_core(
    const void* __restrict__ A, int lda,
    const void* __restrict__ B, int ldb,
    float* __restrict__ C, __half* __restrict__ Ch, int ldc,
    int K, const float* __restrict__ bias,
    const int* __restrict__ mask, float scale)
{
    extern __shared__ __align__(16) char smem[];
    const int tid = threadIdx.x;
    const int wid = tid >> 5, lane = tid & 31;
    const int wm = wid & 3, wn = wid >> 2;
    const int qr = lane >> 2, qc = lane & 3;
    const int bm = blockIdx.y * 128, bn = blockIdx.x * 128;
    const int stgb = (AH ? 2 : 3) * STG_U * 4;

    const void* Arow = AH
        ? (const void*)((const __half*)A + (long)bm * lda)
        : (const void*)((const float*)A + (long)bm * lda);
    const void* Brow = BH
        ? (const void*)((const __half*)B + (long)bn * ldb)
        : (const void*)((const float*)B + (long)bn * ldb);

    const int a_off = (wm * 32 + ((lane >> 3) & 1) * 8 + (lane & 7)) * SROW +
                      (lane >> 4) * 4;
    const int b_off = (wn * 64 + (lane >> 4) * 8 + (lane & 7)) * SROW +
                      ((lane >> 3) & 1) * 4;

    float acc[2][8][4];
#pragma unroll
    for (int mf = 0; mf < 2; mf++)
#pragma unroll
        for (int nf = 0; nf < 8; nf++)
#pragma unroll
            for (int j = 0; j < 4; j++) acc[mf][nf][j] = 0.f;

    const int nc = K / 32;
    float4 av[4], bv[4];
    uint2 av2[4], bv2[4];
    ldg_chunk<AH, BH>(Arow, lda, Brow, ldb, 0, tid, av, av2, bv, bv2);
    sts_chunk<AH, BH>((uint32_t*)smem, tid, av, av2, bv, bv2);
    __syncthreads();

    for (int c = 0; c < nc; c++) {
        if (c + 1 < nc)
            ldg_chunk<AH, BH>(Arow, lda, Brow, ldb, (c + 1) * 32, tid,
                              av, av2, bv, bv2);
        const uint32_t sb = smem_u32(smem + (c & 1) * stgb);
#pragma unroll
        for (int kk = 0; kk < 2; kk++) {
            uint32_t ah[2][4], al[2][4], bh[8][2];
#pragma unroll
            for (int mf = 0; mf < 2; mf++) {
                uint32_t ao = sb + (uint32_t)(a_off + mf * 16 * SROW + kk * 8) * 4;
                ldsm4(ah[mf][0], ah[mf][1], ah[mf][2], ah[mf][3], ao);
                if (!AH)
                    ldsm4(al[mf][0], al[mf][1], al[mf][2], al[mf][3],
                          ao + STG_U * 4);
            }
#pragma unroll
            for (int p = 0; p < 4; p++) {
                uint32_t bo = sb + (AH ? 1 : 2) * STG_U * 4 +
                              (uint32_t)(b_off + p * 16 * SROW + kk * 8) * 4;
                ldsm4(bh[2 * p][0], bh[2 * p][1],
                      bh[2 * p + 1][0], bh[2 * p + 1][1], bo);
            }
#pragma unroll
            for (int mf = 0; mf < 2; mf++)
#pragma unroll
                for (int nf = 0; nf < 8; nf++) {
                    mma16816(acc[mf][nf], ah[mf], bh[nf]);
                    if (!AH) mma16816(acc[mf][nf], al[mf], bh[nf]);
                }
        }
        __syncthreads();
        if (c + 1 < nc) {
            sts_chunk<AH, BH>((uint32_t*)(smem + ((c + 1) & 1) * stgb), tid,
                              av, av2, bv, bv2);
            __syncthreads();
        }
    }

#pragma unroll
    for (int mf = 0; mf < 2; mf++) {
        const int r0 = bm + wm * 32 + mf * 16 + qr;
        const int r1 = r0 + 8;
        int keep0 = 1, keep1 = 1;
        if (EPI == EPI_ROWMASK) { keep0 = mask[r0]; keep1 = mask[r1]; }
#pragma unroll
        for (int nf = 0; nf < 8; nf++) {
            const int cc = bn + wn * 64 + nf * 8 + qc * 2;
            float v0 = acc[mf][nf][0], v1 = acc[mf][nf][1];
            float v2 = acc[mf][nf][2], v3 = acc[mf][nf][3];
            if (EPI == EPI_BIAS || EPI == EPI_RELU || EPI == EPI_QSCALE ||
                EPI == EPI_ROWMASK) {
                float b0 = bias[cc], b1 = bias[cc + 1];
                v0 += b0; v1 += b1; v2 += b0; v3 += b1;
            }
            if (EPI == EPI_RELU) {
                v0 = fmaxf(v0, 0.f); v1 = fmaxf(v1, 0.f);
                v2 = fmaxf(v2, 0.f); v3 = fmaxf(v3, 0.f);
            }
            if (EPI == EPI_QSCALE) {
                v0 *= scale; v1 *= scale; v2 *= scale; v3 *= scale;
            }
            if (EPI == EPI_KEYMASK) {
                if (!mask[cc])     { v0 = MASK_NEG; v2 = MASK_NEG; }
                if (!mask[cc + 1]) { v1 = MASK_NEG; v3 = MASK_NEG; }
            }
            if (EPI == EPI_ROWMASK) {
                if (!keep0) { v0 = 0.f; v1 = 0.f; }
                if (!keep1) { v2 = 0.f; v3 = 0.f; }
            }
            if (WH) {
                *(uint32_t*)&Ch[(long)r0 * ldc + cc] = pack2h(v0, v1);
                *(uint32_t*)&Ch[(long)r1 * ldc + cc] = pack2h(v2, v3);
            } else {
                float2 o0 = {v0, v1}, o1 = {v2, v3};
                *(float2*)&C[(long)r0 * ldc + cc] = o0;
                *(float2*)&C[(long)r1 * ldc + cc] = o1;
            }
        }
    }
}

template <int EPI, int AH, int BH, int WH>
__global__ __launch_bounds__(256, 2) void gemm_bf(
    const void* __restrict__ A, int lda, long aZ,
    const void* __restrict__ B, int ldb, long bZ,
    float* __restrict__ C, __half* __restrict__ Ch, int ldc, long cZ,
    int K, const float* __restrict__ bias,
    const int* __restrict__ mask, float scale)
{
    const void* Az = AH ? (const void*)((const __half*)A + blockIdx.z * aZ)
                        : (const void*)((const float*)A + blockIdx.z * aZ);
    const void* Bz = BH ? (const void*)((const __half*)B + blockIdx.z * bZ)
                        : (const void*)((const float*)B + blockIdx.z * bZ);
    gemm_core<EPI, AH, BH, WH>(Az, lda, Bz, ldb,
                               WH ? nullptr : C + blockIdx.z * cZ,
                               WH ? Ch + blockIdx.z * cZ : nullptr,
                               ldc, K, bias, mask, scale);
}

// fused Q/K/V projections: z selects operand set; scale=1 for K/V
__global__ __launch_bounds__(256, 2) void proj3_k(
    const float* __restrict__ q, const float* __restrict__ k,
    const float* __restrict__ v,
    const float* __restrict__ wqt, const float* __restrict__ wkt,
    const float* __restrict__ wvt,
    __half* __restrict__ qp, __half* __restrict__ kp, __half* __restrict__ vp,
    const float* __restrict__ bq, const float* __restrict__ bk,
    const float* __restrict__ bv)
{
    const int z = blockIdx.z;
    const float* A = (z == 0) ? q : (z == 1) ? k : v;
    const float* B = (z == 0) ? wqt : (z == 1) ? wkt : wvt;
    __half* Ch = (z == 0) ? qp : (z == 1) ? kp : vp;
    const float* bias = (z == 0) ? bq : (z == 1) ? bk : bv;
    const float scale = (z == 0) ? 0.0625f : 1.0f;
    gemm_core<EPI_QSCALE, 0, 0, 1>(A, DMODEL, B, DMODEL, nullptr, Ch,
                                   DMODEL, DMODEL, bias, nullptr, scale);
}

// ---------------- PV kernel: N-tile = 256 (whole head), single P pass --------
// 8 warps (4x2), warp tile 32x128. acc 128 regs -> 1 CTA/SM.
#define PV_STG ((128 + 256) * SROW * 4)   // A | B per stage = 30720

__global__ __launch_bounds__(256, 1) void pv_k(
    const __half* __restrict__ P, const __half* __restrict__ Vt,
    float* __restrict__ ctx)
{
    extern __shared__ __align__(16) char smem[];
    const int tid = threadIdx.x, wid = tid >> 5, lane = tid & 31;
    const int wm = wid & 3, wn = wid >> 2;
    const int qr = lane >> 2, qc = lane & 3;
    const int bm = blockIdx.y * 128, h = blockIdx.z;

    const __half* Arow = P + (size_t)h * NTOK * NTOK + (long)bm * NTOK;
    const __half* Brow = Vt + (size_t)h * HDIM * NTOK;
    float* Cc = ctx + h * HDIM;

    const int a_off = (wm * 32 + ((lane >> 3) & 1) * 8 + (lane & 7)) * SROW +
                      (lane >> 4) * 4;
    const int b_off = (wn * 128 + (lane >> 4) * 8 + (lane & 7)) * SROW +
                      ((lane >> 3) & 1) * 4;

    float acc[2][16][4];
#pragma unroll
    for (int mf = 0; mf < 2; mf++)
#pragma unroll
        for (int nf = 0; nf < 16; nf++)
#pragma unroll
            for (int j = 0; j < 4; j++) acc[mf][nf][j] = 0.f;

    uint2 av2[4], bv2[8];
    auto ldg = [&](int k0) {
#pragma unroll
        for (int i = 0; i < 4; i++) {
            int idx = tid + i * 256;
            int r = idx >> 3, c4 = idx & 7;
            av2[i] = *(const uint2*)(Arow + (long)r * NTOK + k0 + c4 * 4);
        }
#pragma unroll
        for (int i = 0; i < 8; i++) {
            int idx = tid + i * 256;
            int r = idx >> 3, c4 = idx & 7;
            bv2[i] = *(const uint2*)(Brow + (long)r * NTOK + k0 + c4 * 4);
        }
    };
    auto sts = [&](uint32_t* st) {
        uint32_t* Bh = st + 128 * SROW;
#pragma unroll
        for (int i = 0; i < 4; i++) {
            int idx = tid + i * 256;
            int o = (idx >> 3) * SROW + (idx & 7) * 2;
            st[o] = av2[i].x; st[o + 1] = av2[i].y;
        }
#pragma unroll
        for (int i = 0; i < 8; i++) {
            int idx = tid + i * 256;
            int o = (idx >> 3) * SROW + (idx & 7) * 2;
            Bh[o] = bv2[i].x; Bh[o + 1] = bv2[i].y;
        }
    };

    const int nc = NTOK / 32;
    ldg(0);
    sts((uint32_t*)smem);
    __syncthreads();

    for (int c = 0; c < nc; c++) {
        if (c + 1 < nc) ldg((c + 1) * 32);
        const uint32_t sb = smem_u32(smem + (c & 1) * PV_STG);
#pragma unroll
        for (int kk = 0; kk < 2; kk++) {
            uint32_t ah[2][4], bh[16][2];
#pragma unroll
            for (int mf = 0; mf < 2; mf++) {
                uint32_t ao = sb + (uint32_t)(a_off + mf * 16 * SROW + kk * 8) * 4;
                ldsm4(ah[mf][0], ah[mf][1], ah[mf][2], ah[mf][3], ao);
            }
#pragma unroll
            for (int p = 0; p < 8; p++) {
                uint32_t bo = sb + 128 * SROW * 4 +
                              (uint32_t)(b_off + p * 16 * SROW + kk * 8) * 4;
                ldsm4(bh[2 * p][0], bh[2 * p][1],
                      bh[2 * p + 1][0], bh[2 * p + 1][1], bo);
            }
#pragma unroll
            for (int mf = 0; mf < 2; mf++)
#pragma unroll
                for (int nf = 0; nf < 16; nf++)
                    mma16816(acc[mf][nf], ah[mf], bh[nf]);
        }
        __syncthreads();
        if (c + 1 < nc) {
            sts((uint32_t*)(smem + ((c + 1) & 1) * PV_STG));
            __syncthreads();
        }
    }

#pragma unroll
    for (int mf = 0; mf < 2; mf++) {
        const int r0 = bm + wm * 32 + mf * 16 + qr;
        const int r1 = r0 + 8;
#pragma unroll
        for (int nf = 0; nf < 16; nf++) {
            const int cc = wn * 128 + nf * 8 + qc * 2;
            float2 o0 = {acc[mf][nf][0], acc[mf][nf][1]};
            float2 o1 = {acc[mf][nf][2], acc[mf][nf][3]};
            *(float2*)&Cc[(long)r0 * DMODEL + cc] = o0;
            *(float2*)&Cc[(long)r1 * DMODEL + cc] = o1;
        }
    }
}

// ---------------- transposes -------------------------------------------------
__global__ void transpose_k(const float* __restrict__ in, float* __restrict__ out,
                            int R, int C)
{
    __shared__ float t[32][33];
    const int bx = blockIdx.x * 32, by = blockIdx.y * 32;
#pragma unroll
    for (int j = 0; j < 32; j += 8)
        t[threadIdx.y + j][threadIdx.x] =
            in[(long)(by + threadIdx.y + j) * C + bx + threadIdx.x];
    __syncthreads();
#pragma unroll
    for (int j = 0; j < 32; j += 8)
        out[(long)(bx + threadIdx.y + j) * R + by + threadIdx.x] =
            t[threadIdx.x][threadIdx.y + j];
}

// 4 square weight transposes in one launch (z selects)
__global__ void transpose4_k(const float* __restrict__ i0,
                             const float* __restrict__ i1,
                             const float* __restrict__ i2,
                             const float* __restrict__ i3,
                             float* __restrict__ o0, float* __restrict__ o1,
                             float* __restrict__ o2, float* __restrict__ o3)
{
    __shared__ float t[32][33];
    const int z = blockIdx.z;
    const float* in = (z == 0) ? i0 : (z == 1) ? i1 : (z == 2) ? i2 : i3;
    float* out = (z == 0) ? o0 : (z == 1) ? o1 : (z == 2) ? o2 : o3;
    const int bx = blockIdx.x * 32, by = blockIdx.y * 32;
#pragma unroll
    for (int j = 0; j < 32; j += 8)
        t[threadIdx.y + j][threadIdx.x] =
            in[(long)(by + threadIdx.y + j) * DMODEL + bx + threadIdx.x];
    __syncthreads();
#pragma unroll
    for (int j = 0; j < 32; j += 8)
        out[(long)(bx + threadIdx.y + j) * DMODEL + by + threadIdx.x] =
            t[threadIdx.x][threadIdx.y + j];
}

__global__ void transpose_h(const __half* __restrict__ in,
                            __half* __restrict__ out, int R, int C)
{
    __shared__ __half t[32][34];
    const int bx = blockIdx.x * 32, by = blockIdx.y * 32;
#pragma unroll
    for (int j = 0; j < 32; j += 8)
        t[threadIdx.y + j][threadIdx.x] =
            in[(long)(by + threadIdx.y + j) * C + bx + threadIdx.x];
    __syncthreads();
#pragma unroll
    for (int j = 0; j < 32; j += 8)
        out[(long)(bx + threadIdx.y + j) * R + by + threadIdx.x] =
            t[threadIdx.x][threadIdx.y + j];
}

// ---------------- mask: sigmoid(h @ w2 + b2) > 0.15 --------------------------
__global__ void score_k(const float* __restrict__ h, const float* __restrict__ w2,
                        const float* __restrict__ b2, int* __restrict__ mask)
{
    const int warp = (blockIdx.x * blockDim.x + threadIdx.x) >> 5;
    const int lane = threadIdx.x & 31;
    if (warp >= NTOK) return;
    const float* hr = h + warp * DHID;
    float s = 0.f;
#pragma unroll
    for (int i = 0; i < DHID / 32; i++)
        s += hr[lane + i * 32] * w2[lane + i * 32];
#pragma unroll
    for (int o = 16; o; o >>= 1) s += __shfl_xor_sync(0xffffffffu, s, o);
    if (lane == 0) {
        float sig = 1.0f / (1.0f + expf(-(s + b2[0])));
        mask[warp] = (sig > 0.15f) ? 1 : 0;
    }
}

// ---------------- row softmax: S fp16 -> P fp16 ------------------------------
__global__ __launch_bounds__(256) void softmax_k(const __half* __restrict__ S,
                                                 __half* __restrict__ P)
{
    __shared__ float cache[NTOK];
    __shared__ float red[256];
    const size_t row = (size_t)blockIdx.y * NTOK + blockIdx.x;
    const uint2* Sr = (const uint2*)(S + row * NTOK);
    const int tid = threadIdx.x;

    float m = -3.4e38f;
#pragma unroll
    for (int i = 0; i < 4; i++) {
        int u2i = tid + i * 256;
        uint2 u = Sr[u2i];
        __half2 h0 = *(__half2*)&u.x, h1 = *(__half2*)&u.y;
        float f0 = __low2float(h0), f1 = __high2float(h0);
        float f2 = __low2float(h1), f3 = __high2float(h1);
        float4 fv = {f0, f1, f2, f3};
        *(float4*)&cache[u2i * 4] = fv;
        m = fmaxf(m, fmaxf(fmaxf(f0, f1), fmaxf(f2, f3)));
    }
    red[tid] = m;
    __syncthreads();
    for (int s = 128; s; s >>= 1) {
        if (tid < s) red[tid] = fmaxf(red[tid], red[tid + s]);
        __syncthreads();
    }
    m = red[0];
    __syncthreads();

    float sum = 0.f;
#pragma unroll
    for (int i = 0; i < 4; i++) {
        int f4 = tid + i * 256;
        float4 v = *(const float4*)&cache[f4 * 4];
        float4 p;
        p.x = __expf(v.x - m); p.y = __expf(v.y - m);
        p.z = __expf(v.z - m); p.w = __expf(v.w - m);
        *(float4*)&cache[f4 * 4] = p;
        sum += p.x + p.y + p.z + p.w;
    }
    red[tid] = sum;
    __syncthreads();
    for (int s = 128; s; s >>= 1) {
        if (tid < s) red[tid] += red[tid + s];
        __syncthreads();
    }
    const float inv = 1.0f / red[0];
    uint2* Pr = (uint2*)(P + row * NTOK);
#pragma unroll
    for (int i = 0; i < 4; i++) {
        int f4 = tid + i * 256;
        float4 p = *(const float4*)&cache[f4 * 4];
        uint2 o;
        o.x = pack2h(p.x * inv, p.y * inv);
        o.y = pack2h(p.z * inv, p.w * inv);
        Pr[f4] = o;
    }
}

// ---------------------------------------------------------------------------
extern "C" void kernel_launch(void* const* d_in, const int* in_sizes, int n_in,
                              void* d_out, int out_size)
{
    const float* q  = (const float*)d_in[0];
    const float* k  = (const float*)d_in[1];
    const float* v  = (const float*)d_in[2];
    const float* w1 = (const float*)d_in[3];
    const float* b1 = (const float*)d_in[4];
    const float* w2 = (const float*)d_in[5];
    const float* b2 = (const float*)d_in[6];
    const float* wq = (const float*)d_in[7];
    const float* bq = (const float*)d_in[8];
    const float* wk = (const float*)d_in[9];
    const float* bk = (const float*)d_in[10];
    const float* wv = (const float*)d_in[11];
    const float* bv = (const float*)d_in[12];
    const float* wo = (const float*)d_in[13];
    const float* bo = (const float*)d_in[14];
    float* out = (float*)d_out;

    float *hh, *ctx, *w1t, *wqt, *wkt, *wvt, *wot;
    __half *qp, *kp, *vp, *vpt, *S, *P;
    int* msk;
    cudaGetSymbolAddress((void**)&hh,  g_h);
    cudaGetSymbolAddress((void**)&msk, g_mask);
    cudaGetSymbolAddress((void**)&qp,  g_qp);
    cudaGetSymbolAddress((void**)&kp,  g_kp);
    cudaGetSymbolAddress((void**)&vp,  g_vp);
    cudaGetSymbolAddress((void**)&vpt, g_vpt);
    cudaGetSymbolAddress((void**)&ctx, g_ctx);
    cudaGetSymbolAddress((void**)&w1t, g_w1t);
    cudaGetSymbolAddress((void**)&wqt, g_wqt);
    cudaGetSymbolAddress((void**)&wkt, g_wkt);
    cudaGetSymbolAddress((void**)&wvt, g_wvt);
    cudaGetSymbolAddress((void**)&wot, g_wot);
    cudaGetSymbolAddress((void**)&S,   g_S);
    cudaGetSymbolAddress((void**)&P,   g_P);

    cudaFuncSetAttribute(gemm_bf<EPI_RELU, 0, 0, 0>,
        cudaFuncAttributeMaxDynamicSharedMemorySize, SMEM_BYTES);
    cudaFuncSetAttribute(proj3_k,
        cudaFuncAttributeMaxDynamicSharedMemorySize, SMEM_BYTES);
    cudaFuncSetAttribute(gemm_bf<EPI_KEYMASK, 1, 1, 1>,
        cudaFuncAttributeMaxDynamicSharedMemorySize, SMEM_BYTES);
    cudaFuncSetAttribute(pv_k,
        cudaFuncAttributeMaxDynamicSharedMemorySize, SMEM_BYTES);
    cudaFuncSetAttribute(gemm_bf<EPI_ROWMASK, 0, 0, 0>,
        cudaFuncAttributeMaxDynamicSharedMemorySize, SMEM_BYTES);

    dim3 tb(32, 8);
    transpose_k<<<dim3(DHID / 32, DMODEL / 32), tb>>>(w1, w1t, DMODEL, DHID);
    transpose4_k<<<dim3(32, 32, 4), tb>>>(wq, wk, wv, wo, wqt, wkt, wvt, wot);

    // 1) predictor hidden: h = relu(q @ w1 + b1)
    gemm_bf<EPI_RELU, 0, 0, 0>
        <<<dim3(DHID / 128, NTOK / 128), 256, SMEM_BYTES>>>(
        q, DMODEL, 0, w1t, DMODEL, 0, hh, nullptr, DHID, 0, DMODEL,
        b1, nullptr, 0.f);
    // 2) token mask
    score_k<<<NTOK / 8, 256>>>(hh, w2, b2, msk);
    // 3) fused Q/K/V projections -> fp16 (softmax scale folded into Q)
    proj3_k<<<dim3(8, 32, 3), 256, SMEM_BYTES>>>(
        q, k, v, wqt, wkt, wvt, qp, kp, vp, bq, bk, bv);
    // 4) transpose V projection (fp16) -> [1024][4096]
    transpose_h<<<dim3(DMODEL / 32, NTOK / 32), tb>>>(vp, vpt, NTOK, DMODEL);
    // 5) S[h] = qp @ kp^T (both fp16) -> fp16 S, masked keys -> -60000
    gemm_bf<EPI_KEYMASK, 1, 1, 1><<<dim3(32, 32, NHEADS), 256, SMEM_BYTES>>>(
        qp, DMODEL, HDIM, kp, DMODEL, HDIM, nullptr, S, NTOK,
        (long)NTOK * NTOK, HDIM, nullptr, msk, 0.f);
    // 6) softmax rows (fp16 in) -> fp16 P
    softmax_k<<<dim3(NTOK, NHEADS), 256>>>(S, P);
    // 7) ctx[h] = P @ V, whole head per CTA (single P pass)
    pv_k<<<dim3(1, NTOK / 128, NHEADS), 256, SMEM_BYTES>>>(P, vpt, ctx);
    // 8) out = rowmask(ctx @ wo + bo)
    gemm_bf<EPI_ROWMASK, 0, 0, 0><<<dim3(8, 32), 256, SMEM_BYTES>>>(
        ctx, DMODEL, 0, wot, DMODEL, 0, out, nullptr, DMODEL, 0, DMODEL,
        bo, msk, 0.f);
}

// round 16
// speedup vs baseline: 1.7543x; 1.1727x over previous
#include <cuda_runtime.h>
#include <cuda_fp16.h>
#include <cstdint>
#include <math.h>

#define NTOK   4096
#define DMODEL 1024
#define DHID   256
#define NHEADS 4
#define HDIM   256

// ---------------- scratch (__device__ globals; no allocation allowed) -------
__device__ float  g_h  [NTOK * DHID];
__device__ int    g_mask[NTOK];
__device__ __half g_q16[NTOK * DMODEL];
__device__ __half g_k16[NTOK * DMODEL];
__device__ __half g_v16[NTOK * DMODEL];
__device__ __half g_qp [NTOK * DMODEL];
__device__ __half g_kp [NTOK * DMODEL];
__device__ __half g_vp [NTOK * DMODEL];
__device__ __half g_vpt[DMODEL * NTOK];
__device__ __half g_ctx[NTOK * DMODEL];
__device__ float  g_w1t[DHID * DMODEL];
__device__ float  g_wqt[DMODEL * DMODEL];
__device__ float  g_wkt[DMODEL * DMODEL];
__device__ float  g_wvt[DMODEL * DMODEL];
__device__ float  g_wot[DMODEL * DMODEL];
__device__ __half g_S  [(size_t)NHEADS * NTOK * NTOK];    // 134MB
__device__ __half g_P  [(size_t)NHEADS * NTOK * NTOK];    // 134MB

#define MASK_NEG (-60000.0f)   // finite in fp16; exp() == 0 after row-max shift

// ---------------- fp16 helpers ----------------------------------------------
__device__ __forceinline__ void split2h(float x0, float x1,
                                        uint32_t& h, uint32_t& l) {
    __half2 hv = __floats2half2_rn(x0, x1);
    float f0 = __low2float(hv), f1 = __high2float(hv);
    __half2 lv = __floats2half2_rn(x0 - f0, x1 - f1);
    h = *(uint32_t*)&hv;
    l = *(uint32_t*)&lv;
}
__device__ __forceinline__ uint32_t pack2h(float x0, float x1) {
    __half2 hv = __floats2half2_rn(x0, x1);
    return *(uint32_t*)&hv;
}
__device__ __forceinline__ void mma16816(float* c, const uint32_t* a,
                                         const uint32_t* b) {
    asm volatile(
        "mma.sync.aligned.m16n8k16.row.col.f32.f16.f16.f32 "
        "{%0,%1,%2,%3}, {%4,%5,%6,%7}, {%8,%9}, {%0,%1,%2,%3};"
        : "+f"(c[0]), "+f"(c[1]), "+f"(c[2]), "+f"(c[3])
        : "r"(a[0]), "r"(a[1]), "r"(a[2]), "r"(a[3]), "r"(b[0]), "r"(b[1]));
}
__device__ __forceinline__ uint32_t smem_u32(const void* p) {
    uint32_t a;
    asm("{ .reg .u64 t; cvta.to.shared.u64 t, %1; cvt.u32.u64 %0, t; }"
        : "=r"(a) : "l"(p));
    return a;
}
__device__ __forceinline__ void ldsm4(uint32_t& r0, uint32_t& r1,
                                      uint32_t& r2, uint32_t& r3,
                                      uint32_t addr) {
    asm volatile("ldmatrix.sync.aligned.m8n8.x4.shared.b16 {%0,%1,%2,%3}, [%4];"
                 : "=r"(r0), "=r"(r1), "=r"(r2), "=r"(r3) : "r"(addr));
}

// ---------------- unified tensor-core GEMM core ------------------------------
// D[M,N] = A[M,K] @ B[N,K]^T (+ epilogue). CTA 128x128, K-chunk 32,
// 256 threads, 8 warps (4x2), warp tile 32x64.
// AH/BH: operand fp16 in gmem. WH: epilogue writes fp16.
enum { EPI_RAW = 0, EPI_BIAS, EPI_RELU, EPI_QSCALE, EPI_KEYMASK, EPI_ROWMASK };

#define SROW   20                      // u32 per smem row (16 data + 4 pad)
#define STG_U  (128 * SROW)
#define SMEM_BYTES (2 * 3 * STG_U * 4) // 61440

template <int AH, int BH>
__device__ __forceinline__ void ldg_chunk(const void* __restrict__ Arow,
                                          int lda,
                                          const void* __restrict__ Brow,
                                          int ldb, int k0, int tid,
                                          float4* av, uint2* av2,
                                          float4* bv, uint2* bv2) {
#pragma unroll
    for (int i = 0; i < 4; i++) {
        int idx = tid + i * 256;
        int r = idx >> 3, c4 = idx & 7;
        if (AH)
            av2[i] = *(const uint2*)((const __half*)Arow +
                                     (long)r * lda + k0 + c4 * 4);
        else
            av[i] = *(const float4*)((const float*)Arow +
                                     (long)r * lda + k0 + c4 * 4);
        if (BH)
            bv2[i] = *(const uint2*)((const __half*)Brow +
                                     (long)r * ldb + k0 + c4 * 4);
        else
            bv[i] = *(const float4*)((const float*)Brow +
                                     (long)r * ldb + k0 + c4 * 4);
    }
}
template <int AH, int BH>
__device__ __forceinline__ void sts_chunk(uint32_t* st, int tid,
                                          const float4* av, const uint2* av2,
                                          const float4* bv, const uint2* bv2) {
    uint32_t* Ah = st;
    uint32_t* Al = st + STG_U;
    uint32_t* Bh = st + (AH ? 1 : 2) * STG_U;
#pragma unroll
    for (int i = 0; i < 4; i++) {
        int idx = tid + i * 256;
        int r = idx >> 3, c4 = idx & 7;
        int o = r * SROW + c4 * 2;
        if (AH) {
            Ah[o] = av2[i].x; Ah[o + 1] = av2[i].y;
        } else {
            uint32_t h01, l01, h23, l23;
            split2h(av[i].x, av[i].y, h01, l01);
            split2h(av[i].z, av[i].w, h23, l23);
            Ah[o] = h01; Ah[o + 1] = h23;
            Al[o] = l01; Al[o + 1] = l23;
        }
        if (BH) {
            Bh[o] = bv2[i].x; Bh[o + 1] = bv2[i].y;
        } else {
            Bh[o] = pack2h(bv[i].x, bv[i].y);
            Bh[o + 1] = pack2h(bv[i].z, bv[i].w);
        }
    }
}

template <int EPI, int AH, int BH, int WH>
__device__ __forceinline__ void gemm_core(
    const void* __restrict__ A, int lda,
    const void* __restrict__ B, int ldb,
    float* __restrict__ C, __half* __restrict__ Ch, int ldc,
    int K, const float* __restrict__ bias,
    const int* __restrict__ mask, float scale)
{
    extern __shared__ __align__(16) char smem[];
    const int tid = threadIdx.x;
    const int wid = tid >> 5, lane = tid & 31;
    const int wm = wid & 3, wn = wid >> 2;
    const int qr = lane >> 2, qc = lane & 3;
    const int bm = blockIdx.y * 128, bn = blockIdx.x * 128;
    const int stgb = (AH ? 2 : 3) * STG_U * 4;

    const void* Arow = AH
        ? (const void*)((const __half*)A + (long)bm * lda)
        : (const void*)((const float*)A + (long)bm * lda);
    const void* Brow = BH
        ? (const void*)((const __half*)B + (long)bn * ldb)
        : (const void*)((const float*)B + (long)bn * ldb);

    const int a_off = (wm * 32 + ((lane >> 3) & 1) * 8 + (lane & 7)) * SROW +
                      (lane >> 4) * 4;
    const int b_off = (wn * 64 + (lane >> 4) * 8 + (lane & 7)) * SROW +
                      ((lane >> 3) & 1) * 4;

    float acc[2][8][4];
#pragma unroll
    for (int mf = 0; mf < 2; mf++)
#pragma unroll
        for (int nf = 0; nf < 8; nf++)
#pragma unroll
            for (int j = 0; j < 4; j++) acc[mf][nf][j] = 0.f;

    const int nc = K / 32;
    float4 av[4], bv[4];
    uint2 av2[4], bv2[4];
    ldg_chunk<AH, BH>(Arow, lda, Brow, ldb, 0, tid, av, av2, bv, bv2);
    sts_chunk<AH, BH>((uint32_t*)smem, tid, av, av2, bv, bv2);
    __syncthreads();

    for (int c = 0; c < nc; c++) {
        if (c + 1 < nc)
            ldg_chunk<AH, BH>(Arow, lda, Brow, ldb, (c + 1) * 32, tid,
                              av, av2, bv, bv2);
        const uint32_t sb = smem_u32(smem + (c & 1) * stgb);
#pragma unroll
        for (int kk = 0; kk < 2; kk++) {
            uint32_t ah[2][4], al[2][4], bh[8][2];
#pragma unroll
            for (int mf = 0; mf < 2; mf++) {
                uint32_t ao = sb + (uint32_t)(a_off + mf * 16 * SROW + kk * 8) * 4;
                ldsm4(ah[mf][0], ah[mf][1], ah[mf][2], ah[mf][3], ao);
                if (!AH)
                    ldsm4(al[mf][0], al[mf][1], al[mf][2], al[mf][3],
                          ao + STG_U * 4);
            }
#pragma unroll
            for (int p = 0; p < 4; p++) {
                uint32_t bo = sb + (AH ? 1 : 2) * STG_U * 4 +
                              (uint32_t)(b_off + p * 16 * SROW + kk * 8) * 4;
                ldsm4(bh[2 * p][0], bh[2 * p][1],
                      bh[2 * p + 1][0], bh[2 * p + 1][1], bo);
            }
#pragma unroll
            for (int mf = 0; mf < 2; mf++)
#pragma unroll
                for (int nf = 0; nf < 8; nf++) {
                    mma16816(acc[mf][nf], ah[mf], bh[nf]);
                    if (!AH) mma16816(acc[mf][nf], al[mf], bh[nf]);
                }
        }
        __syncthreads();
        if (c + 1 < nc) {
            sts_chunk<AH, BH>((uint32_t*)(smem + ((c + 1) & 1) * stgb), tid,
                              av, av2, bv, bv2);
            __syncthreads();
        }
    }

#pragma unroll
    for (int mf = 0; mf < 2; mf++) {
        const int r0 = bm + wm * 32 + mf * 16 + qr;
        const int r1 = r0 + 8;
        int keep0 = 1, keep1 = 1;
        if (EPI == EPI_ROWMASK) { keep0 = mask[r0]; keep1 = mask[r1]; }
#pragma unroll
        for (int nf = 0; nf < 8; nf++) {
            const int cc = bn + wn * 64 + nf * 8 + qc * 2;
            float v0 = acc[mf][nf][0], v1 = acc[mf][nf][1];
            float v2 = acc[mf][nf][2], v3 = acc[mf][nf][3];
            if (EPI == EPI_BIAS || EPI == EPI_RELU || EPI == EPI_QSCALE ||
                EPI == EPI_ROWMASK) {
                float b0 = bias[cc], b1 = bias[cc + 1];
                v0 += b0; v1 += b1; v2 += b0; v3 += b1;
            }
            if (EPI == EPI_RELU) {
                v0 = fmaxf(v0, 0.f); v1 = fmaxf(v1, 0.f);
                v2 = fmaxf(v2, 0.f); v3 = fmaxf(v3, 0.f);
            }
            if (EPI == EPI_QSCALE) {
                v0 *= scale; v1 *= scale; v2 *= scale; v3 *= scale;
            }
            if (EPI == EPI_KEYMASK) {
                if (!mask[cc])     { v0 = MASK_NEG; v2 = MASK_NEG; }
                if (!mask[cc + 1]) { v1 = MASK_NEG; v3 = MASK_NEG; }
            }
            if (EPI == EPI_ROWMASK) {
                if (!keep0) { v0 = 0.f; v1 = 0.f; }
                if (!keep1) { v2 = 0.f; v3 = 0.f; }
            }
            if (WH) {
                *(uint32_t*)&Ch[(long)r0 * ldc + cc] = pack2h(v0, v1);
                *(uint32_t*)&Ch[(long)r1 * ldc + cc] = pack2h(v2, v3);
            } else {
                float2 o0 = {v0, v1}, o1 = {v2, v3};
                *(float2*)&C[(long)r0 * ldc + cc] = o0;
                *(float2*)&C[(long)r1 * ldc + cc] = o1;
            }
        }
    }
}

template <int EPI, int AH, int BH, int WH>
__global__ __launch_bounds__(256, 2) void gemm_bf(
    const void* __restrict__ A, int lda, long aZ,
    const void* __restrict__ B, int ldb, long bZ,
    float* __restrict__ C, __half* __restrict__ Ch, int ldc, long cZ,
    int K, const float* __restrict__ bias,
    const int* __restrict__ mask, float scale)
{
    const void* Az = AH ? (const void*)((const __half*)A + blockIdx.z * aZ)
                        : (const void*)((const float*)A + blockIdx.z * aZ);
    const void* Bz = BH ? (const void*)((const __half*)B + blockIdx.z * bZ)
                        : (const void*)((const float*)B + blockIdx.z * bZ);
    gemm_core<EPI, AH, BH, WH>(Az, lda, Bz, ldb,
                               WH ? nullptr : C + blockIdx.z * cZ,
                               WH ? Ch + blockIdx.z * cZ : nullptr,
                               ldc, K, bias, mask, scale);
}

// fused Q/K/V projections (fp16 inputs, 1 MMA/frag): z selects operand set
__global__ __launch_bounds__(256, 2) void proj3_k(
    const __half* __restrict__ q16, const __half* __restrict__ k16,
    const __half* __restrict__ v16,
    const float* __restrict__ wqt, const float* __restrict__ wkt,
    const float* __restrict__ wvt,
    __half* __restrict__ qp, __half* __restrict__ kp, __half* __restrict__ vp,
    const float* __restrict__ bq, const float* __restrict__ bk,
    const float* __restrict__ bv)
{
    const int z = blockIdx.z;
    const __half* A = (z == 0) ? q16 : (z == 1) ? k16 : v16;
    const float* B = (z == 0) ? wqt : (z == 1) ? wkt : wvt;
    __half* Ch = (z == 0) ? qp : (z == 1) ? kp : vp;
    const float* bias = (z == 0) ? bq : (z == 1) ? bk : bv;
    const float scale = (z == 0) ? 0.0625f : 1.0f;
    gemm_core<EPI_QSCALE, 1, 0, 1>(A, DMODEL, B, DMODEL, nullptr, Ch,
                                   DMODEL, DMODEL, bias, nullptr, scale);
}

// ---------------- PV kernel: N-tile = 256 (whole head), fp16 ctx out ---------
#define PV_STG ((128 + 256) * SROW * 4)

__global__ __launch_bounds__(256, 1) void pv_k(
    const __half* __restrict__ P, const __half* __restrict__ Vt,
    __half* __restrict__ ctx)
{
    extern __shared__ __align__(16) char smem[];
    const int tid = threadIdx.x, wid = tid >> 5, lane = tid & 31;
    const int wm = wid & 3, wn = wid >> 2;
    const int qr = lane >> 2, qc = lane & 3;
    const int bm = blockIdx.y * 128, h = blockIdx.z;

    const __half* Arow = P + (size_t)h * NTOK * NTOK + (long)bm * NTOK;
    const __half* Brow = Vt + (size_t)h * HDIM * NTOK;
    __half* Cc = ctx + h * HDIM;

    const int a_off = (wm * 32 + ((lane >> 3) & 1) * 8 + (lane & 7)) * SROW +
                      (lane >> 4) * 4;
    const int b_off = (wn * 128 + (lane >> 4) * 8 + (lane & 7)) * SROW +
                      ((lane >> 3) & 1) * 4;

    float acc[2][16][4];
#pragma unroll
    for (int mf = 0; mf < 2; mf++)
#pragma unroll
        for (int nf = 0; nf < 16; nf++)
#pragma unroll
            for (int j = 0; j < 4; j++) acc[mf][nf][j] = 0.f;

    uint2 av2[4], bv2[8];
    auto ldg = [&](int k0) {
#pragma unroll
        for (int i = 0; i < 4; i++) {
            int idx = tid + i * 256;
            int r = idx >> 3, c4 = idx & 7;
            av2[i] = *(const uint2*)(Arow + (long)r * NTOK + k0 + c4 * 4);
        }
#pragma unroll
        for (int i = 0; i < 8; i++) {
            int idx = tid + i * 256;
            int r = idx >> 3, c4 = idx & 7;
            bv2[i] = *(const uint2*)(Brow + (long)r * NTOK + k0 + c4 * 4);
        }
    };
    auto sts = [&](uint32_t* st) {
        uint32_t* Bh = st + 128 * SROW;
#pragma unroll
        for (int i = 0; i < 4; i++) {
            int idx = tid + i * 256;
            int o = (idx >> 3) * SROW + (idx & 7) * 2;
            st[o] = av2[i].x; st[o + 1] = av2[i].y;
        }
#pragma unroll
        for (int i = 0; i < 8; i++) {
            int idx = tid + i * 256;
            int o = (idx >> 3) * SROW + (idx & 7) * 2;
            Bh[o] = bv2[i].x; Bh[o + 1] = bv2[i].y;
        }
    };

    const int nc = NTOK / 32;
    ldg(0);
    sts((uint32_t*)smem);
    __syncthreads();

    for (int c = 0; c < nc; c++) {
        if (c + 1 < nc) ldg((c + 1) * 32);
        const uint32_t sb = smem_u32(smem + (c & 1) * PV_STG);
#pragma unroll
        for (int kk = 0; kk < 2; kk++) {
            uint32_t ah[2][4], bh[16][2];
#pragma unroll
            for (int mf = 0; mf < 2; mf++) {
                uint32_t ao = sb + (uint32_t)(a_off + mf * 16 * SROW + kk * 8) * 4;
                ldsm4(ah[mf][0], ah[mf][1], ah[mf][2], ah[mf][3], ao);
            }
#pragma unroll
            for (int p = 0; p < 8; p++) {
                uint32_t bo = sb + 128 * SROW * 4 +
                              (uint32_t)(b_off + p * 16 * SROW + kk * 8) * 4;
                ldsm4(bh[2 * p][0], bh[2 * p][1],
                      bh[2 * p + 1][0], bh[2 * p + 1][1], bo);
            }
#pragma unroll
            for (int mf = 0; mf < 2; mf++)
#pragma unroll
                for (int nf = 0; nf < 16; nf++)
                    mma16816(acc[mf][nf], ah[mf], bh[nf]);
        }
        __syncthreads();
        if (c + 1 < nc) {
            sts((uint32_t*)(smem + ((c + 1) & 1) * PV_STG));
            __syncthreads();
        }
    }

#pragma unroll
    for (int mf = 0; mf < 2; mf++) {
        const int r0 = bm + wm * 32 + mf * 16 + qr;
        const int r1 = r0 + 8;
#pragma unroll
        for (int nf = 0; nf < 16; nf++) {
            const int cc = wn * 128 + nf * 8 + qc * 2;
            *(uint32_t*)&Cc[(long)r0 * DMODEL + cc] =
                pack2h(acc[mf][nf][0], acc[mf][nf][1]);
            *(uint32_t*)&Cc[(long)r1 * DMODEL + cc] =
                pack2h(acc[mf][nf][2], acc[mf][nf][3]);
        }
    }
}

// ---------------- conversions / transposes -----------------------------------
__global__ void to_half3(const float4* __restrict__ q, const float4* __restrict__ k,
                         const float4* __restrict__ v,
                         uint2* __restrict__ q16, uint2* __restrict__ k16,
                         uint2* __restrict__ v16)
{
    const int z = blockIdx.y;
    const float4* in = (z == 0) ? q : (z == 1) ? k : v;
    uint2* out = (z == 0) ? q16 : (z == 1) ? k16 : v16;
    long i = (long)blockIdx.x * 256 + threadIdx.x;
    float4 f = in[i];
    uint2 o;
    o.x = pack2h(f.x, f.y);
    o.y = pack2h(f.z, f.w);
    out[i] = o;
}

__global__ void transpose_k(const float* __restrict__ in, float* __restrict__ out,
                            int R, int C)
{
    __shared__ float t[32][33];
    const int bx = blockIdx.x * 32, by = blockIdx.y * 32;
#pragma unroll
    for (int j = 0; j < 32; j += 8)
        t[threadIdx.y + j][threadIdx.x] =
            in[(long)(by + threadIdx.y + j) * C + bx + threadIdx.x];
    __syncthreads();
#pragma unroll
    for (int j = 0; j < 32; j += 8)
        out[(long)(bx + threadIdx.y + j) * R + by + threadIdx.x] =
            t[threadIdx.x][threadIdx.y + j];
}

__global__ void transpose4_k(const float* __restrict__ i0,
                             const float* __restrict__ i1,
                             const float* __restrict__ i2,
                             const float* __restrict__ i3,
                             float* __restrict__ o0, float* __restrict__ o1,
                             float* __restrict__ o2, float* __restrict__ o3)
{
    __shared__ float t[32][33];
    const int z = blockIdx.z;
    const float* in = (z == 0) ? i0 : (z == 1) ? i1 : (z == 2) ? i2 : i3;
    float* out = (z == 0) ? o0 : (z == 1) ? o1 : (z == 2) ? o2 : o3;
    const int bx = blockIdx.x * 32, by = blockIdx.y * 32;
#pragma unroll
    for (int j = 0; j < 32; j += 8)
        t[threadIdx.y + j][threadIdx.x] =
            in[(long)(by + threadIdx.y + j) * DMODEL + bx + threadIdx.x];
    __syncthreads();
#pragma unroll
    for (int j = 0; j < 32; j += 8)
        out[(long)(bx + threadIdx.y + j) * DMODEL + by + threadIdx.x] =
            t[threadIdx.x][threadIdx.y + j];
}

__global__ void transpose_h(const __half* __restrict__ in,
                            __half* __restrict__ out, int R, int C)
{
    __shared__ __half t[32][34];
    const int bx = blockIdx.x * 32, by = blockIdx.y * 32;
#pragma unroll
    for (int j = 0; j < 32; j += 8)
        t[threadIdx.y + j][threadIdx.x] =
            in[(long)(by + threadIdx.y + j) * C + bx + threadIdx.x];
    __syncthreads();
#pragma unroll
    for (int j = 0; j < 32; j += 8)
        out[(long)(bx + threadIdx.y + j) * R + by + threadIdx.x] =
            t[threadIdx.x][threadIdx.y + j];
}

// ---------------- mask: sigmoid(h @ w2 + b2) > 0.15 --------------------------
__global__ void score_k(const float* __restrict__ h, const float* __restrict__ w2,
                        const float* __restrict__ b2, int* __restrict__ mask)
{
    const int warp = (blockIdx.x * blockDim.x + threadIdx.x) >> 5;
    const int lane = threadIdx.x & 31;
    if (warp >= NTOK) return;
    const float* hr = h + warp * DHID;
    float s = 0.f;
#pragma unroll
    for (int i = 0; i < DHID / 32; i++)
        s += hr[lane + i * 32] * w2[lane + i * 32];
#pragma unroll
    for (int o = 16; o; o >>= 1) s += __shfl_xor_sync(0xffffffffu, s, o);
    if (lane == 0) {
        float sig = 1.0f / (1.0f + expf(-(s + b2[0])));
        mask[warp] = (sig > 0.15f) ? 1 : 0;
    }
}

// ---------------- row softmax: S fp16 -> P fp16 ------------------------------
__global__ __launch_bounds__(256) void softmax_k(const __half* __restrict__ S,
                                                 __half* __restrict__ P)
{
    __shared__ float cache[NTOK];
    __shared__ float red[256];
    const size_t row = (size_t)blockIdx.y * NTOK + blockIdx.x;
    const uint2* Sr = (const uint2*)(S + row * NTOK);
    const int tid = threadIdx.x;

    float m = -3.4e38f;
#pragma unroll
    for (int i = 0; i < 4; i++) {
        int u2i = tid + i * 256;
        uint2 u = Sr[u2i];
        __half2 h0 = *(__half2*)&u.x, h1 = *(__half2*)&u.y;
        float f0 = __low2float(h0), f1 = __high2float(h0);
        float f2 = __low2float(h1), f3 = __high2float(h1);
        float4 fv = {f0, f1, f2, f3};
        *(float4*)&cache[u2i * 4] = fv;
        m = fmaxf(m, fmaxf(fmaxf(f0, f1), fmaxf(f2, f3)));
    }
    red[tid] = m;
    __syncthreads();
    for (int s = 128; s; s >>= 1) {
        if (tid < s) red[tid] = fmaxf(red[tid], red[tid + s]);
        __syncthreads();
    }
    m = red[0];
    __syncthreads();

    float sum = 0.f;
#pragma unroll
    for (int i = 0; i < 4; i++) {
        int f4 = tid + i * 256;
        float4 v = *(const float4*)&cache[f4 * 4];
        float4 p;
        p.x = __expf(v.x - m); p.y = __expf(v.y - m);
        p.z = __expf(v.z - m); p.w = __expf(v.w - m);
        *(float4*)&cache[f4 * 4] = p;
        sum += p.x + p.y + p.z + p.w;
    }
    red[tid] = sum;
    __syncthreads();
    for (int s = 128; s; s >>= 1) {
        if (tid < s) red[tid] += red[tid + s];
        __syncthreads();
    }
    const float inv = 1.0f / red[0];
    uint2* Pr = (uint2*)(P + row * NTOK);
#pragma unroll
    for (int i = 0; i < 4; i++) {
        int f4 = tid + i * 256;
        float4 p = *(const float4*)&cache[f4 * 4];
        uint2 o;
        o.x = pack2h(p.x * inv, p.y * inv);
        o.y = pack2h(p.z * inv, p.w * inv);
        Pr[f4] = o;
    }
}

// ---------------------------------------------------------------------------
extern "C" void kernel_launch(void* const* d_in, const int* in_sizes, int n_in,
                              void* d_out, int out_size)
{
    const float* q  = (const float*)d_in[0];
    const float* k  = (const float*)d_in[1];
    const float* v  = (const float*)d_in[2];
    const float* w1 = (const float*)d_in[3];
    const float* b1 = (const float*)d_in[4];
    const float* w2 = (const float*)d_in[5];
    const float* b2 = (const float*)d_in[6];
    const float* wq = (const float*)d_in[7];
    const float* bq = (const float*)d_in[8];
    const float* wk = (const float*)d_in[9];
    const float* bk = (const float*)d_in[10];
    const float* wv = (const float*)d_in[11];
    const float* bv = (const float*)d_in[12];
    const float* wo = (const float*)d_in[13];
    const float* bo = (const float*)d_in[14];
    float* out = (float*)d_out;

    float *hh, *w1t, *wqt, *wkt, *wvt, *wot;
    __half *q16, *k16, *v16, *qp, *kp, *vp, *vpt, *ctx, *S, *P;
    int* msk;
    cudaGetSymbolAddress((void**)&hh,  g_h);
    cudaGetSymbolAddress((void**)&msk, g_mask);
    cudaGetSymbolAddress((void**)&q16, g_q16);
    cudaGetSymbolAddress((void**)&k16, g_k16);
    cudaGetSymbolAddress((void**)&v16, g_v16);
    cudaGetSymbolAddress((void**)&qp,  g_qp);
    cudaGetSymbolAddress((void**)&kp,  g_kp);
    cudaGetSymbolAddress((void**)&vp,  g_vp);
    cudaGetSymbolAddress((void**)&vpt, g_vpt);
    cudaGetSymbolAddress((void**)&ctx, g_ctx);
    cudaGetSymbolAddress((void**)&w1t, g_w1t);
    cudaGetSymbolAddress((void**)&wqt, g_wqt);
    cudaGetSymbolAddress((void**)&wkt, g_wkt);
    cudaGetSymbolAddress((void**)&wvt, g_wvt);
    cudaGetSymbolAddress((void**)&wot, g_wot);
    cudaGetSymbolAddress((void**)&S,   g_S);
    cudaGetSymbolAddress((void**)&P,   g_P);

    cudaFuncSetAttribute(gemm_bf<EPI_RELU, 0, 0, 0>,
        cudaFuncAttributeMaxDynamicSharedMemorySize, SMEM_BYTES);
    cudaFuncSetAttribute(proj3_k,
        cudaFuncAttributeMaxDynamicSharedMemorySize, SMEM_BYTES);
    cudaFuncSetAttribute(gemm_bf<EPI_KEYMASK, 1, 1, 1>,
        cudaFuncAttributeMaxDynamicSharedMemorySize, SMEM_BYTES);
    cudaFuncSetAttribute(pv_k,
        cudaFuncAttributeMaxDynamicSharedMemorySize, SMEM_BYTES);
    cudaFuncSetAttribute(gemm_bf<EPI_ROWMASK, 1, 0, 0>,
        cudaFuncAttributeMaxDynamicSharedMemorySize, SMEM_BYTES);

    dim3 tb(32, 8);
    transpose_k<<<dim3(DHID / 32, DMODEL / 32), tb>>>(w1, w1t, DMODEL, DHID);
    transpose4_k<<<dim3(32, 32, 4), tb>>>(wq, wk, wv, wo, wqt, wkt, wvt, wot);
    // q/k/v -> fp16 (for projections; predictor keeps fp32 q)
    to_half3<<<dim3(NTOK * DMODEL / 1024, 3), 256>>>(
        (const float4*)q, (const float4*)k, (const float4*)v,
        (uint2*)q16, (uint2*)k16, (uint2*)v16);

    // 1) predictor hidden: h = relu(q @ w1 + b1)  (full precision: feeds mask)
    gemm_bf<EPI_RELU, 0, 0, 0>
        <<<dim3(DHID / 128, NTOK / 128), 256, SMEM_BYTES>>>(
        q, DMODEL, 0, w1t, DMODEL, 0, hh, nullptr, DHID, 0, DMODEL,
        b1, nullptr, 0.f);
    // 2) token mask
    score_k<<<NTOK / 8, 256>>>(hh, w2, b2, msk);
    // 3) fused Q/K/V projections from fp16 inputs (scale folded into Q)
    proj3_k<<<dim3(8, 32, 3), 256, SMEM_BYTES>>>(
        q16, k16, v16, wqt, wkt, wvt, qp, kp, vp, bq, bk, bv);
    // 4) transpose V projection (fp16) -> [1024][4096]
    transpose_h<<<dim3(DMODEL / 32, NTOK / 32), tb>>>(vp, vpt, NTOK, DMODEL);
    // 5) S[h] = qp @ kp^T (both fp16) -> fp16 S, masked keys -> -60000
    gemm_bf<EPI_KEYMASK, 1, 1, 1><<<dim3(32, 32, NHEADS), 256, SMEM_BYTES>>>(
        qp, DMODEL, HDIM, kp, DMODEL, HDIM, nullptr, S, NTOK,
        (long)NTOK * NTOK, HDIM, nullptr, msk, 0.f);
    // 6) softmax rows (fp16 in) -> fp16 P
    softmax_k<<<dim3(NTOK, NHEADS), 256>>>(S, P);
    // 7) ctx[h] = P @ V, whole head per CTA, fp16 ctx out
    pv_k<<<dim3(1, NTOK / 128, NHEADS), 256, SMEM_BYTES>>>(P, vpt, ctx);
    // 8) out = rowmask(ctx @ wo + bo)  (ctx fp16, 1 MMA/frag)
    gemm_bf<EPI_ROWMASK, 1, 0, 0><<<dim3(8, 32), 256, SMEM_BYTES>>>(
        ctx, DMODEL, 0, wot, DMODEL, 0, out, nullptr, DMODEL, 0, DMODEL,
        bo, msk, 0.f);
}

// round 17
// speedup vs baseline: 1.8202x; 1.0376x over previous
#include <cuda_runtime.h>
#include <cuda_fp16.h>
#include <cstdint>
#include <math.h>

#define NTOK   4096
#define DMODEL 1024
#define DHID   256
#define NHEADS 4
#define HDIM   256

// ---------------- scratch (__device__ globals; no allocation allowed) -------
__device__ float  g_h  [NTOK * DHID];
__device__ int    g_mask[NTOK];
__device__ __half g_q16[NTOK * DMODEL];
__device__ __half g_k16[NTOK * DMODEL];
__device__ __half g_v16[NTOK * DMODEL];
__device__ __half g_qp [NTOK * DMODEL];
__device__ __half g_kp [NTOK * DMODEL];
__device__ __half g_vp [NTOK * DMODEL];
__device__ __half g_vpt[DMODEL * NTOK];
__device__ __half g_ctx[NTOK * DMODEL];
__device__ float  g_w1t[DHID * DMODEL];
__device__ float  g_wqt[DMODEL * DMODEL];
__device__ float  g_wkt[DMODEL * DMODEL];
__device__ float  g_wvt[DMODEL * DMODEL];
__device__ float  g_wot[DMODEL * DMODEL];
__device__ __half g_S  [(size_t)NHEADS * NTOK * NTOK];    // 134MB
__device__ __half g_P  [(size_t)NHEADS * NTOK * NTOK];    // 134MB

#define MASK_NEG (-60000.0f)   // finite in fp16; exp() == 0 after row-max shift

// ---------------- fp16 helpers ----------------------------------------------
__device__ __forceinline__ void split2h(float x0, float x1,
                                        uint32_t& h, uint32_t& l) {
    __half2 hv = __floats2half2_rn(x0, x1);
    float f0 = __low2float(hv), f1 = __high2float(hv);
    __half2 lv = __floats2half2_rn(x0 - f0, x1 - f1);
    h = *(uint32_t*)&hv;
    l = *(uint32_t*)&lv;
}
__device__ __forceinline__ uint32_t pack2h(float x0, float x1) {
    __half2 hv = __floats2half2_rn(x0, x1);
    return *(uint32_t*)&hv;
}
__device__ __forceinline__ void mma16816(float* c, const uint32_t* a,
                                         const uint32_t* b) {
    asm volatile(
        "mma.sync.aligned.m16n8k16.row.col.f32.f16.f16.f32 "
        "{%0,%1,%2,%3}, {%4,%5,%6,%7}, {%8,%9}, {%0,%1,%2,%3};"
        : "+f"(c[0]), "+f"(c[1]), "+f"(c[2]), "+f"(c[3])
        : "r"(a[0]), "r"(a[1]), "r"(a[2]), "r"(a[3]), "r"(b[0]), "r"(b[1]));
}
__device__ __forceinline__ uint32_t smem_u32(const void* p) {
    uint32_t a;
    asm("{ .reg .u64 t; cvta.to.shared.u64 t, %1; cvt.u32.u64 %0, t; }"
        : "=r"(a) : "l"(p));
    return a;
}
__device__ __forceinline__ void ldsm4(uint32_t& r0, uint32_t& r1,
                                      uint32_t& r2, uint32_t& r3,
                                      uint32_t addr) {
    asm volatile("ldmatrix.sync.aligned.m8n8.x4.shared.b16 {%0,%1,%2,%3}, [%4];"
                 : "=r"(r0), "=r"(r1), "=r"(r2), "=r"(r3) : "r"(addr));
}

// ---------------- unified tensor-core GEMM core ------------------------------
// D[M,N] = A[M,K] @ B[N,K]^T (+ epilogue). CTA 128x128, K-chunk 32,
// 256 threads, 8 warps (4x2), warp tile 32x64.
// AH/BH: operand fp16 in gmem. WH: epilogue writes fp16.
enum { EPI_RAW = 0, EPI_BIAS, EPI_RELU, EPI_QSCALE, EPI_KEYMASK, EPI_ROWMASK };

#define SROW   20                      // u32 per smem row (16 data + 4 pad)
#define STG_U  (128 * SROW)
#define SMEM_BYTES (2 * 3 * STG_U * 4) // 61440

template <int AH, int BH>
__device__ __forceinline__ void ldg_chunk(const void* __restrict__ Arow,
                                          int lda,
                                          const void* __restrict__ Brow,
                                          int ldb, int k0, int tid,
                                          float4* av, uint2* av2,
                                          float4* bv, uint2* bv2) {
#pragma unroll
    for (int i = 0; i < 4; i++) {
        int idx = tid + i * 256;
        int r = idx >> 3, c4 = idx & 7;
        if (AH)
            av2[i] = *(const uint2*)((const __half*)Arow +
                                     (long)r * lda + k0 + c4 * 4);
        else
            av[i] = *(const float4*)((const float*)Arow +
                                     (long)r * lda + k0 + c4 * 4);
        if (BH)
            bv2[i] = *(const uint2*)((const __half*)Brow +
                                     (long)r * ldb + k0 + c4 * 4);
        else
            bv[i] = *(const float4*)((const float*)Brow +
                                     (long)r * ldb + k0 + c4 * 4);
    }
}
template <int AH, int BH>
__device__ __forceinline__ void sts_chunk(uint32_t* st, int tid,
                                          const float4* av, const uint2* av2,
                                          const float4* bv, const uint2* bv2) {
    uint32_t* Ah = st;
    uint32_t* Al = st + STG_U;
    uint32_t* Bh = st + (AH ? 1 : 2) * STG_U;
#pragma unroll
    for (int i = 0; i < 4; i++) {
        int idx = tid + i * 256;
        int r = idx >> 3, c4 = idx & 7;
        int o = r * SROW + c4 * 2;
        if (AH) {
            Ah[o] = av2[i].x; Ah[o + 1] = av2[i].y;
        } else {
            uint32_t h01, l01, h23, l23;
            split2h(av[i].x, av[i].y, h01, l01);
            split2h(av[i].z, av[i].w, h23, l23);
            Ah[o] = h01; Ah[o + 1] = h23;
            Al[o] = l01; Al[o + 1] = l23;
        }
        if (BH) {
            Bh[o] = bv2[i].x; Bh[o + 1] = bv2[i].y;
        } else {
            Bh[o] = pack2h(bv[i].x, bv[i].y);
            Bh[o + 1] = pack2h(bv[i].z, bv[i].w);
        }
    }
}

template <int EPI, int AH, int BH, int WH>
__device__ __forceinline__ void gemm_core(
    const void* __restrict__ A, int lda,
    const void* __restrict__ B, int ldb,
    float* __restrict__ C, __half* __restrict__ Ch, int ldc,
    int K, const float* __restrict__ bias,
    const int* __restrict__ mask, float scale)
{
    extern __shared__ __align__(16) char smem[];
    const int tid = threadIdx.x;
    const int wid = tid >> 5, lane = tid & 31;
    const int wm = wid & 3, wn = wid >> 2;
    const int qr = lane >> 2, qc = lane & 3;
    const int bm = blockIdx.y * 128, bn = blockIdx.x * 128;
    const int stgb = (AH ? 2 : 3) * STG_U * 4;

    const void* Arow = AH
        ? (const void*)((const __half*)A + (long)bm * lda)
        : (const void*)((const float*)A + (long)bm * lda);
    const void* Brow = BH
        ? (const void*)((const __half*)B + (long)bn * ldb)
        : (const void*)((const float*)B + (long)bn * ldb);

    const int a_off = (wm * 32 + ((lane >> 3) & 1) * 8 + (lane & 7)) * SROW +
                      (lane >> 4) * 4;
    const int b_off = (wn * 64 + (lane >> 4) * 8 + (lane & 7)) * SROW +
                      ((lane >> 3) & 1) * 4;

    float acc[2][8][4];
#pragma unroll
    for (int mf = 0; mf < 2; mf++)
#pragma unroll
        for (int nf = 0; nf < 8; nf++)
#pragma unroll
            for (int j = 0; j < 4; j++) acc[mf][nf][j] = 0.f;

    const int nc = K / 32;
    float4 av[4], bv[4];
    uint2 av2[4], bv2[4];
    ldg_chunk<AH, BH>(Arow, lda, Brow, ldb, 0, tid, av, av2, bv, bv2);
    sts_chunk<AH, BH>((uint32_t*)smem, tid, av, av2, bv, bv2);
    __syncthreads();

    for (int c = 0; c < nc; c++) {
        if (c + 1 < nc)
            ldg_chunk<AH, BH>(Arow, lda, Brow, ldb, (c + 1) * 32, tid,
                              av, av2, bv, bv2);
        const uint32_t sb = smem_u32(smem + (c & 1) * stgb);
#pragma unroll
        for (int kk = 0; kk < 2; kk++) {
            uint32_t ah[2][4], al[2][4], bh[8][2];
#pragma unroll
            for (int mf = 0; mf < 2; mf++) {
                uint32_t ao = sb + (uint32_t)(a_off + mf * 16 * SROW + kk * 8) * 4;
                ldsm4(ah[mf][0], ah[mf][1], ah[mf][2], ah[mf][3], ao);
                if (!AH)
                    ldsm4(al[mf][0], al[mf][1], al[mf][2], al[mf][3],
                          ao + STG_U * 4);
            }
#pragma unroll
            for (int p = 0; p < 4; p++) {
                uint32_t bo = sb + (AH ? 1 : 2) * STG_U * 4 +
                              (uint32_t)(b_off + p * 16 * SROW + kk * 8) * 4;
                ldsm4(bh[2 * p][0], bh[2 * p][1],
                      bh[2 * p + 1][0], bh[2 * p + 1][1], bo);
            }
#pragma unroll
            for (int mf = 0; mf < 2; mf++)
#pragma unroll
                for (int nf = 0; nf < 8; nf++) {
                    mma16816(acc[mf][nf], ah[mf], bh[nf]);
                    if (!AH) mma16816(acc[mf][nf], al[mf], bh[nf]);
                }
        }
        __syncthreads();
        if (c + 1 < nc) {
            sts_chunk<AH, BH>((uint32_t*)(smem + ((c + 1) & 1) * stgb), tid,
                              av, av2, bv, bv2);
            __syncthreads();
        }
    }

#pragma unroll
    for (int mf = 0; mf < 2; mf++) {
        const int r0 = bm + wm * 32 + mf * 16 + qr;
        const int r1 = r0 + 8;
        int keep0 = 1, keep1 = 1;
        if (EPI == EPI_ROWMASK) { keep0 = mask[r0]; keep1 = mask[r1]; }
#pragma unroll
        for (int nf = 0; nf < 8; nf++) {
            const int cc = bn + wn * 64 + nf * 8 + qc * 2;
            float v0 = acc[mf][nf][0], v1 = acc[mf][nf][1];
            float v2 = acc[mf][nf][2], v3 = acc[mf][nf][3];
            if (EPI == EPI_BIAS || EPI == EPI_RELU || EPI == EPI_QSCALE ||
                EPI == EPI_ROWMASK) {
                float b0 = bias[cc], b1 = bias[cc + 1];
                v0 += b0; v1 += b1; v2 += b0; v3 += b1;
            }
            if (EPI == EPI_RELU) {
                v0 = fmaxf(v0, 0.f); v1 = fmaxf(v1, 0.f);
                v2 = fmaxf(v2, 0.f); v3 = fmaxf(v3, 0.f);
            }
            if (EPI == EPI_QSCALE) {
                v0 *= scale; v1 *= scale; v2 *= scale; v3 *= scale;
            }
            if (EPI == EPI_KEYMASK) {
                if (!mask[cc])     { v0 = MASK_NEG; v2 = MASK_NEG; }
                if (!mask[cc + 1]) { v1 = MASK_NEG; v3 = MASK_NEG; }
            }
            if (EPI == EPI_ROWMASK) {
                if (!keep0) { v0 = 0.f; v1 = 0.f; }
                if (!keep1) { v2 = 0.f; v3 = 0.f; }
            }
            if (WH) {
                *(uint32_t*)&Ch[(long)r0 * ldc + cc] = pack2h(v0, v1);
                *(uint32_t*)&Ch[(long)r1 * ldc + cc] = pack2h(v2, v3);
            } else {
                float2 o0 = {v0, v1}, o1 = {v2, v3};
                *(float2*)&C[(long)r0 * ldc + cc] = o0;
                *(float2*)&C[(long)r1 * ldc + cc] = o1;
            }
        }
    }
}

template <int EPI, int AH, int BH, int WH>
__global__ __launch_bounds__(256, 2) void gemm_bf(
    const void* __restrict__ A, int lda, long aZ,
    const void* __restrict__ B, int ldb, long bZ,
    float* __restrict__ C, __half* __restrict__ Ch, int ldc, long cZ,
    int K, const float* __restrict__ bias,
    const int* __restrict__ mask, float scale)
{
    const void* Az = AH ? (const void*)((const __half*)A + blockIdx.z * aZ)
                        : (const void*)((const float*)A + blockIdx.z * aZ);
    const void* Bz = BH ? (const void*)((const __half*)B + blockIdx.z * bZ)
                        : (const void*)((const float*)B + blockIdx.z * bZ);
    gemm_core<EPI, AH, BH, WH>(Az, lda, Bz, ldb,
                               WH ? nullptr : C + blockIdx.z * cZ,
                               WH ? Ch + blockIdx.z * cZ : nullptr,
                               ldc, K, bias, mask, scale);
}

// fused Q/K/V projections (z 0..2, fp16 in) + predictor hidden (z==3, fp32 in)
__global__ __launch_bounds__(256, 2) void proj4_k(
    const __half* __restrict__ q16, const __half* __restrict__ k16,
    const __half* __restrict__ v16,
    const float* __restrict__ wqt, const float* __restrict__ wkt,
    const float* __restrict__ wvt,
    __half* __restrict__ qp, __half* __restrict__ kp, __half* __restrict__ vp,
    const float* __restrict__ bq, const float* __restrict__ bk,
    const float* __restrict__ bv,
    const float* __restrict__ q32, const float* __restrict__ w1t,
    const float* __restrict__ b1, float* __restrict__ hh)
{
    const int z = blockIdx.z;
    if (z == 3) {
        // predictor: h = relu(q @ w1 + b1), full 2-term precision (feeds mask)
        if (blockIdx.x >= DHID / 128) return;
        gemm_core<EPI_RELU, 0, 0, 0>(q32, DMODEL, w1t, DMODEL, hh, nullptr,
                                     DHID, DMODEL, b1, nullptr, 0.f);
        return;
    }
    const __half* A = (z == 0) ? q16 : (z == 1) ? k16 : v16;
    const float* B = (z == 0) ? wqt : (z == 1) ? wkt : wvt;
    __half* Ch = (z == 0) ? qp : (z == 1) ? kp : vp;
    const float* bias = (z == 0) ? bq : (z == 1) ? bk : bv;
    const float scale = (z == 0) ? 0.0625f : 1.0f;
    gemm_core<EPI_QSCALE, 1, 0, 1>(A, DMODEL, B, DMODEL, nullptr, Ch,
                                   DMODEL, DMODEL, bias, nullptr, scale);
}

// ---------------- PV kernel: N-tile = 256 (whole head), fp16 ctx out ---------
#define PV_STG ((128 + 256) * SROW * 4)

__global__ __launch_bounds__(256, 1) void pv_k(
    const __half* __restrict__ P, const __half* __restrict__ Vt,
    __half* __restrict__ ctx)
{
    extern __shared__ __align__(16) char smem[];
    const int tid = threadIdx.x, wid = tid >> 5, lane = tid & 31;
    const int wm = wid & 3, wn = wid >> 2;
    const int qr = lane >> 2, qc = lane & 3;
    const int bm = blockIdx.y * 128, h = blockIdx.z;

    const __half* Arow = P + (size_t)h * NTOK * NTOK + (long)bm * NTOK;
    const __half* Brow = Vt + (size_t)h * HDIM * NTOK;
    __half* Cc = ctx + h * HDIM;

    const int a_off = (wm * 32 + ((lane >> 3) & 1) * 8 + (lane & 7)) * SROW +
                      (lane >> 4) * 4;
    const int b_off = (wn * 128 + (lane >> 4) * 8 + (lane & 7)) * SROW +
                      ((lane >> 3) & 1) * 4;

    float acc[2][16][4];
#pragma unroll
    for (int mf = 0; mf < 2; mf++)
#pragma unroll
        for (int nf = 0; nf < 16; nf++)
#pragma unroll
            for (int j = 0; j < 4; j++) acc[mf][nf][j] = 0.f;

    uint2 av2[4], bv2[8];
    auto ldg = [&](int k0) {
#pragma unroll
        for (int i = 0; i < 4; i++) {
            int idx = tid + i * 256;
            int r = idx >> 3, c4 = idx & 7;
            av2[i] = *(const uint2*)(Arow + (long)r * NTOK + k0 + c4 * 4);
        }
#pragma unroll
        for (int i = 0; i < 8; i++) {
            int idx = tid + i * 256;
            int r = idx >> 3, c4 = idx & 7;
            bv2[i] = *(const uint2*)(Brow + (long)r * NTOK + k0 + c4 * 4);
        }
    };
    auto sts = [&](uint32_t* st) {
        uint32_t* Bh = st + 128 * SROW;
#pragma unroll
        for (int i = 0; i < 4; i++) {
            int idx = tid + i * 256;
            int o = (idx >> 3) * SROW + (idx & 7) * 2;
            st[o] = av2[i].x; st[o + 1] = av2[i].y;
        }
#pragma unroll
        for (int i = 0; i < 8; i++) {
            int idx = tid + i * 256;
            int o = (idx >> 3) * SROW + (idx & 7) * 2;
            Bh[o] = bv2[i].x; Bh[o + 1] = bv2[i].y;
        }
    };

    const int nc = NTOK / 32;
    ldg(0);
    sts((uint32_t*)smem);
    __syncthreads();

    for (int c = 0; c < nc; c++) {
        if (c + 1 < nc) ldg((c + 1) * 32);
        const uint32_t sb = smem_u32(smem + (c & 1) * PV_STG);
#pragma unroll
        for (int kk = 0; kk < 2; kk++) {
            uint32_t ah[2][4], bh[16][2];
#pragma unroll
            for (int mf = 0; mf < 2; mf++) {
                uint32_t ao = sb + (uint32_t)(a_off + mf * 16 * SROW + kk * 8) * 4;
                ldsm4(ah[mf][0], ah[mf][1], ah[mf][2], ah[mf][3], ao);
            }
#pragma unroll
            for (int p = 0; p < 8; p++) {
                uint32_t bo = sb + 128 * SROW * 4 +
                              (uint32_t)(b_off + p * 16 * SROW + kk * 8) * 4;
                ldsm4(bh[2 * p][0], bh[2 * p][1],
                      bh[2 * p + 1][0], bh[2 * p + 1][1], bo);
            }
#pragma unroll
            for (int mf = 0; mf < 2; mf++)
#pragma unroll
                for (int nf = 0; nf < 16; nf++)
                    mma16816(acc[mf][nf], ah[mf], bh[nf]);
        }
        __syncthreads();
        if (c + 1 < nc) {
            sts((uint32_t*)(smem + ((c + 1) & 1) * PV_STG));
            __syncthreads();
        }
    }

#pragma unroll
    for (int mf = 0; mf < 2; mf++) {
        const int r0 = bm + wm * 32 + mf * 16 + qr;
        const int r1 = r0 + 8;
#pragma unroll
        for (int nf = 0; nf < 16; nf++) {
            const int cc = wn * 128 + nf * 8 + qc * 2;
            *(uint32_t*)&Cc[(long)r0 * DMODEL + cc] =
                pack2h(acc[mf][nf][0], acc[mf][nf][1]);
            *(uint32_t*)&Cc[(long)r1 * DMODEL + cc] =
                pack2h(acc[mf][nf][2], acc[mf][nf][3]);
        }
    }
}

// ---------------- conversions / transposes -----------------------------------
__global__ void to_half3(const float4* __restrict__ q, const float4* __restrict__ k,
                         const float4* __restrict__ v,
                         uint2* __restrict__ q16, uint2* __restrict__ k16,
                         uint2* __restrict__ v16)
{
    const int z = blockIdx.y;
    const float4* in = (z == 0) ? q : (z == 1) ? k : v;
    uint2* out = (z == 0) ? q16 : (z == 1) ? k16 : v16;
    long i = (long)blockIdx.x * 256 + threadIdx.x;
    float4 f = in[i];
    uint2 o;
    o.x = pack2h(f.x, f.y);
    o.y = pack2h(f.z, f.w);
    out[i] = o;
}

// 5 weight transposes in one launch: z 0..3 square [1024x1024], z==4 w1 [1024x256]
__global__ void transpose5_k(const float* __restrict__ i0,
                             const float* __restrict__ i1,
                             const float* __restrict__ i2,
                             const float* __restrict__ i3,
                             const float* __restrict__ i4,
                             float* __restrict__ o0, float* __restrict__ o1,
                             float* __restrict__ o2, float* __restrict__ o3,
                             float* __restrict__ o4)
{
    __shared__ float t[32][33];
    const int z = blockIdx.z;
    const int Cdim = (z == 4) ? DHID : DMODEL;
    if (blockIdx.x * 32 >= Cdim) return;
    const float* in = (z == 0) ? i0 : (z == 1) ? i1 : (z == 2) ? i2
                    : (z == 3) ? i3 : i4;
    float* out = (z == 0) ? o0 : (z == 1) ? o1 : (z == 2) ? o2
               : (z == 3) ? o3 : o4;
    const int bx = blockIdx.x * 32, by = blockIdx.y * 32;
#pragma unroll
    for (int j = 0; j < 32; j += 8)
        t[threadIdx.y + j][threadIdx.x] =
            in[(long)(by + threadIdx.y + j) * Cdim + bx + threadIdx.x];
    __syncthreads();
#pragma unroll
    for (int j = 0; j < 32; j += 8)
        out[(long)(bx + threadIdx.y + j) * DMODEL + by + threadIdx.x] =
            t[threadIdx.x][threadIdx.y + j];
}

__global__ void transpose_h(const __half* __restrict__ in,
                            __half* __restrict__ out, int R, int C)
{
    __shared__ __half t[32][34];
    const int bx = blockIdx.x * 32, by = blockIdx.y * 32;
#pragma unroll
    for (int j = 0; j < 32; j += 8)
        t[threadIdx.y + j][threadIdx.x] =
            in[(long)(by + threadIdx.y + j) * C + bx + threadIdx.x];
    __syncthreads();
#pragma unroll
    for (int j = 0; j < 32; j += 8)
        out[(long)(bx + threadIdx.y + j) * R + by + threadIdx.x] =
            t[threadIdx.x][threadIdx.y + j];
}

// ---------------- mask: sigmoid(h @ w2 + b2) > 0.15 --------------------------
__global__ void score_k(const float* __restrict__ h, const float* __restrict__ w2,
                        const float* __restrict__ b2, int* __restrict__ mask)
{
    const int warp = (blockIdx.x * blockDim.x + threadIdx.x) >> 5;
    const int lane = threadIdx.x & 31;
    if (warp >= NTOK) return;
    const float* hr = h + warp * DHID;
    float s = 0.f;
#pragma unroll
    for (int i = 0; i < DHID / 32; i++)
        s += hr[lane + i * 32] * w2[lane + i * 32];
#pragma unroll
    for (int o = 16; o; o >>= 1) s += __shfl_xor_sync(0xffffffffu, s, o);
    if (lane == 0) {
        float sig = 1.0f / (1.0f + expf(-(s + b2[0])));
        mask[warp] = (sig > 0.15f) ? 1 : 0;
    }
}

// ---------------- row softmax: S fp16 -> P fp16 ------------------------------
__global__ __launch_bounds__(256) void softmax_k(const __half* __restrict__ S,
                                                 __half* __restrict__ P)
{
    __shared__ float cache[NTOK];
    __shared__ float red[256];
    const size_t row = (size_t)blockIdx.y * NTOK + blockIdx.x;
    const uint2* Sr = (const uint2*)(S + row * NTOK);
    const int tid = threadIdx.x;

    float m = -3.4e38f;
#pragma unroll
    for (int i = 0; i < 4; i++) {
        int u2i = tid + i * 256;
        uint2 u = Sr[u2i];
        __half2 h0 = *(__half2*)&u.x, h1 = *(__half2*)&u.y;
        float f0 = __low2float(h0), f1 = __high2float(h0);
        float f2 = __low2float(h1), f3 = __high2float(h1);
        float4 fv = {f0, f1, f2, f3};
        *(float4*)&cache[u2i * 4] = fv;
        m = fmaxf(m, fmaxf(fmaxf(f0, f1), fmaxf(f2, f3)));
    }
    red[tid] = m;
    __syncthreads();
    for (int s = 128; s; s >>= 1) {
        if (tid < s) red[tid] = fmaxf(red[tid], red[tid + s]);
        __syncthreads();
    }
    m = red[0];
    __syncthreads();

    float sum = 0.f;
#pragma unroll
    for (int i = 0; i < 4; i++) {
        int f4 = tid + i * 256;
        float4 v = *(const float4*)&cache[f4 * 4];
        float4 p;
        p.x = __expf(v.x - m); p.y = __expf(v.y - m);
        p.z = __expf(v.z - m); p.w = __expf(v.w - m);
        *(float4*)&cache[f4 * 4] = p;
        sum += p.x + p.y + p.z + p.w;
    }
    red[tid] = sum;
    __syncthreads();
    for (int s = 128; s; s >>= 1) {
        if (tid < s) red[tid] += red[tid + s];
        __syncthreads();
    }
    const float inv = 1.0f / red[0];
    uint2* Pr = (uint2*)(P + row * NTOK);
#pragma unroll
    for (int i = 0; i < 4; i++) {
        int f4 = tid + i * 256;
        float4 p = *(const float4*)&cache[f4 * 4];
        uint2 o;
        o.x = pack2h(p.x * inv, p.y * inv);
        o.y = pack2h(p.z * inv, p.w * inv);
        Pr[f4] = o;
    }
}

// ---------------------------------------------------------------------------
extern "C" void kernel_launch(void* const* d_in, const int* in_sizes, int n_in,
                              void* d_out, int out_size)
{
    const float* q  = (const float*)d_in[0];
    const float* k  = (const float*)d_in[1];
    const float* v  = (const float*)d_in[2];
    const float* w1 = (const float*)d_in[3];
    const float* b1 = (const float*)d_in[4];
    const float* w2 = (const float*)d_in[5];
    const float* b2 = (const float*)d_in[6];
    const float* wq = (const float*)d_in[7];
    const float* bq = (const float*)d_in[8];
    const float* wk = (const float*)d_in[9];
    const float* bk = (const float*)d_in[10];
    const float* wv = (const float*)d_in[11];
    const float* bv = (const float*)d_in[12];
    const float* wo = (const float*)d_in[13];
    const float* bo = (const float*)d_in[14];
    float* out = (float*)d_out;

    float *hh, *w1t, *wqt, *wkt, *wvt, *wot;
    __half *q16, *k16, *v16, *qp, *kp, *vp, *vpt, *ctx, *S, *P;
    int* msk;
    cudaGetSymbolAddress((void**)&hh,  g_h);
    cudaGetSymbolAddress((void**)&msk, g_mask);
    cudaGetSymbolAddress((void**)&q16, g_q16);
    cudaGetSymbolAddress((void**)&k16, g_k16);
    cudaGetSymbolAddress((void**)&v16, g_v16);
    cudaGetSymbolAddress((void**)&qp,  g_qp);
    cudaGetSymbolAddress((void**)&kp,  g_kp);
    cudaGetSymbolAddress((void**)&vp,  g_vp);
    cudaGetSymbolAddress((void**)&vpt, g_vpt);
    cudaGetSymbolAddress((void**)&ctx, g_ctx);
    cudaGetSymbolAddress((void**)&w1t, g_w1t);
    cudaGetSymbolAddress((void**)&wqt, g_wqt);
    cudaGetSymbolAddress((void**)&wkt, g_wkt);
    cudaGetSymbolAddress((void**)&wvt, g_wvt);
    cudaGetSymbolAddress((void**)&wot, g_wot);
    cudaGetSymbolAddress((void**)&S,   g_S);
    cudaGetSymbolAddress((void**)&P,   g_P);

    cudaFuncSetAttribute(proj4_k,
        cudaFuncAttributeMaxDynamicSharedMemorySize, SMEM_BYTES);
    cudaFuncSetAttribute(gemm_bf<EPI_KEYMASK, 1, 1, 1>,
        cudaFuncAttributeMaxDynamicSharedMemorySize, SMEM_BYTES);
    cudaFuncSetAttribute(pv_k,
        cudaFuncAttributeMaxDynamicSharedMemorySize, SMEM_BYTES);
    cudaFuncSetAttribute(gemm_bf<EPI_ROWMASK, 1, 0, 0>,
        cudaFuncAttributeMaxDynamicSharedMemorySize, SMEM_BYTES);

    dim3 tb(32, 8);
    // 0) weight transposes (5 in one launch) + q/k/v -> fp16
    transpose5_k<<<dim3(32, 32, 5), tb>>>(wq, wk, wv, wo, w1,
                                          wqt, wkt, wvt, wot, w1t);
    to_half3<<<dim3(NTOK * DMODEL / 1024, 3), 256>>>(
        (const float4*)q, (const float4*)k, (const float4*)v,
        (uint2*)q16, (uint2*)k16, (uint2*)v16);

    // 1+3) fused: Q/K/V projections (z 0..2) + predictor hidden (z==3)
    proj4_k<<<dim3(8, 32, 4), 256, SMEM_BYTES>>>(
        q16, k16, v16, wqt, wkt, wvt, qp, kp, vp, bq, bk, bv,
        q, w1t, b1, hh);
    // 2) token mask
    score_k<<<NTOK / 8, 256>>>(hh, w2, b2, msk);
    // 4) transpose V projection (fp16) -> [1024][4096]
    transpose_h<<<dim3(DMODEL / 32, NTOK / 32), tb>>>(vp, vpt, NTOK, DMODEL);
    // 5) S[h] = qp @ kp^T (both fp16) -> fp16 S, masked keys -> -60000
    gemm_bf<EPI_KEYMASK, 1, 1, 1><<<dim3(32, 32, NHEADS), 256, SMEM_BYTES>>>(
        qp, DMODEL, HDIM, kp, DMODEL, HDIM, nullptr, S, NTOK,
        (long)NTOK * NTOK, HDIM, nullptr, msk, 0.f);
    // 6) softmax rows (fp16 in) -> fp16 P
    softmax_k<<<dim3(NTOK, NHEADS), 256>>>(S, P);
    // 7) ctx[h] = P @ V, whole head per CTA, fp16 ctx out
    pv_k<<<dim3(1, NTOK / 128, NHEADS), 256, SMEM_BYTES>>>(P, vpt, ctx);
    // 8) out = rowmask(ctx @ wo + bo)  (ctx fp16, 1 MMA/frag)
    gemm_bf<EPI_ROWMASK, 1, 0, 0><<<dim3(8, 32), 256, SMEM_BYTES>>>(
        ctx, DMODEL, 0, wot, DMODEL, 0, out, nullptr, DMODEL, 0, DMODEL,
        bo, msk, 0.f);
}